// round 6
// baseline (speedup 1.0000x reference)
#include <cuda_runtime.h>
#include <cuda_bf16.h>
#include <cstdint>

// Problem constants
#define B_   2
#define S_   2048
#define D_   2048
#define H_   16
#define HD_  128
#define R_   32
#define M_TOK (B_ * S_)              // 4096 tokens
#define LORA_SCALE (1.0f / 32.0f)

// ---------------------------------------------------------------------------
// Scratch (allocation-free rule: __device__ globals)
// ---------------------------------------------------------------------------
static __device__ float g_attn[M_TOK * D_];      // fp32 attention output

static __device__ __align__(16) __nv_bfloat16 g_qkvh[M_TOK * 3 * D_];
static __device__ __align__(16) __nv_bfloat16 g_qkvl[M_TOK * 3 * D_];
static __device__ __align__(16) __nv_bfloat16 g_xh[M_TOK * D_];
static __device__ __align__(16) __nv_bfloat16 g_xl[M_TOK * D_];
static __device__ __align__(16) __nv_bfloat16 g_wqh[3 * D_ * D_];
static __device__ __align__(16) __nv_bfloat16 g_wql[3 * D_ * D_];
static __device__ __align__(16) __nv_bfloat16 g_woh[D_ * D_];
static __device__ __align__(16) __nv_bfloat16 g_wol[D_ * D_];
static __device__ __align__(16) __nv_bfloat16 g_ah[M_TOK * D_];
static __device__ __align__(16) __nv_bfloat16 g_al[M_TOK * D_];
static __device__ __align__(16) __nv_bfloat16 g_bqt[3 * D_ * R_];   // [6144][32]
static __device__ __align__(16) __nv_bfloat16 g_bot[D_ * R_];       // [2048][32]
static __device__ __align__(16) __nv_bfloat16 g_t1h[M_TOK * R_];
static __device__ __align__(16) __nv_bfloat16 g_t2h[M_TOK * R_];

// ---------------------------------------------------------------------------
// helpers
// ---------------------------------------------------------------------------
__device__ __forceinline__ uint32_t smem_u32(const void* p) {
    uint32_t a;
    asm("{ .reg .u64 t; cvta.to.shared.u64 t, %1; cvt.u32.u64 %0, t; }"
        : "=r"(a) : "l"(p));
    return a;
}
__device__ __forceinline__ void cp16(uint32_t dst, const void* src) {
    asm volatile("cp.async.cg.shared.global [%0], [%1], 16;"
                 :: "r"(dst), "l"(src) : "memory");
}
__device__ __forceinline__ void cp_commit() {
    asm volatile("cp.async.commit_group;" ::: "memory");
}
__device__ __forceinline__ void cp_wait1() {
    asm volatile("cp.async.wait_group 1;" ::: "memory");
}
__device__ __forceinline__ void ldm4(uint32_t& r0, uint32_t& r1,
                                     uint32_t& r2, uint32_t& r3, uint32_t addr) {
    asm volatile("ldmatrix.sync.aligned.m8n8.x4.shared.b16 {%0,%1,%2,%3}, [%4];"
                 : "=r"(r0), "=r"(r1), "=r"(r2), "=r"(r3) : "r"(addr));
}
__device__ __forceinline__ void ldm4t(uint32_t& r0, uint32_t& r1,
                                      uint32_t& r2, uint32_t& r3, uint32_t addr) {
    asm volatile("ldmatrix.sync.aligned.m8n8.x4.trans.shared.b16 {%0,%1,%2,%3}, [%4];"
                 : "=r"(r0), "=r"(r1), "=r"(r2), "=r"(r3) : "r"(addr));
}
__device__ __forceinline__ void mma16(float* c, const uint32_t* a, const uint32_t* b) {
    asm volatile(
        "mma.sync.aligned.m16n8k16.row.col.f32.bf16.bf16.f32 "
        "{%0,%1,%2,%3}, {%4,%5,%6,%7}, {%8,%9}, {%0,%1,%2,%3};"
        : "+f"(c[0]), "+f"(c[1]), "+f"(c[2]), "+f"(c[3])
        : "r"(a[0]), "r"(a[1]), "r"(a[2]), "r"(a[3]), "r"(b[0]), "r"(b[1]));
}
// pack two fp32 -> bf16x2: hi by truncation
__device__ __forceinline__ uint32_t pack_hi(float x, float y) {
    return (__float_as_uint(y) & 0xffff0000u) | (__float_as_uint(x) >> 16);
}
// residuals (x - trunc_bf16(x)) packed RN
__device__ __forceinline__ uint32_t pack_lo(float x, float y) {
    float lx = x - __uint_as_float(__float_as_uint(x) & 0xffff0000u);
    float ly = y - __uint_as_float(__float_as_uint(y) & 0xffff0000u);
    __nv_bfloat162 t = __floats2bfloat162_rn(lx, ly);
    return *(uint32_t*)&t;
}

// ---------------------------------------------------------------------------
// Pre-pass: split fp32 -> bf16 hi (truncation) + bf16 lo (RN residual)
// ---------------------------------------------------------------------------
__global__ void __launch_bounds__(256) split_kernel(
    const float4* __restrict__ src, uint2* __restrict__ hi,
    uint2* __restrict__ lo, int n4)
{
    int i = blockIdx.x * 256 + threadIdx.x;
    if (i >= n4) return;
    float4 v = src[i];
    uint2 h, l;
    h.x = pack_hi(v.x, v.y);
    h.y = pack_hi(v.z, v.w);
    l.x = pack_lo(v.x, v.y);
    l.y = pack_lo(v.z, v.w);
    hi[i] = h;
    lo[i] = l;
}

// Pre-pass: Bq[32,N] -> out[N][32] bf16(RN), scaled
__global__ void __launch_bounds__(256) transpose_scale_kernel(
    const float* __restrict__ Bq, __nv_bfloat16* __restrict__ out,
    int N, float scale)
{
    int idx = blockIdx.x * 256 + threadIdx.x;
    int k = idx & 31;
    int n = idx >> 5;
    if (n < N)
        out[(size_t)n * 32 + k] = __float2bfloat16(Bq[(size_t)k * N + n] * scale);
}

// ---------------------------------------------------------------------------
// Pure-bf16 fused GEMM (bf16x3 via pre-split operands):
//   C = (Ah+Al) @ (Bh+Bl)^T + T @ Bqt^T
// Output: fp32 Cf, or split bf16 (Chi, Clo) when Cf == nullptr.
// ---------------------------------------------------------------------------
#define OFF_AH 0
#define OFF_AL 6144
#define OFF_BH 12288
#define OFF_BL 18432
#define STAGE_B 24576
#define TCG_SMEM (3 * STAGE_B)      // 73728 bytes

__global__ void __launch_bounds__(256, 2) tc_gemm_bf16(
    const __nv_bfloat16* __restrict__ Ah, const __nv_bfloat16* __restrict__ Al,
    const __nv_bfloat16* __restrict__ Bh, const __nv_bfloat16* __restrict__ Bl,
    const __nv_bfloat16* __restrict__ Tm, const __nv_bfloat16* __restrict__ Bqt,
    float* __restrict__ Cf, __nv_bfloat16* __restrict__ Chi,
    __nv_bfloat16* __restrict__ Clo, int M, int N, int K)
{
    extern __shared__ __align__(128) char smem[];
    const uint32_t sbase = smem_u32(smem);

    const int tid  = threadIdx.x;
    const int wid  = tid >> 5;
    const int lane = tid & 31;
    const int g    = lane >> 2;
    const int q    = lane & 3;
    const int warpM = (wid & 1) * 64;
    const int warpN = (wid >> 1) * 32;

    const int n0 = blockIdx.x * 128;
    const int m0 = blockIdx.y * 128;

    const int kc    = K >> 4;
    const int total = kc + 2;

    float acc[4][4][4];
    #pragma unroll
    for (int i = 0; i < 4; i++)
        #pragma unroll
        for (int j = 0; j < 4; j++)
            #pragma unroll
            for (int e = 0; e < 4; e++) acc[i][j][e] = 0.f;

    const int pr = tid >> 1;
    const int ps = tid & 1;
    auto issue = [&](int c, int s) {
        const uint32_t st = sbase + (uint32_t)s * STAGE_B;
        const uint32_t doff = (uint32_t)pr * 48u + (uint32_t)ps * 16u;
        if (c < kc) {
            size_t ao = (size_t)(m0 + pr) * K + c * 16 + ps * 8;
            size_t bo = (size_t)(n0 + pr) * K + c * 16 + ps * 8;
            cp16(st + OFF_AH + doff, Ah + ao);
            cp16(st + OFF_AL + doff, Al + ao);
            cp16(st + OFF_BH + doff, Bh + bo);
            cp16(st + OFF_BL + doff, Bl + bo);
        } else {
            int kl = (c - kc) * 16 + ps * 8;
            cp16(st + OFF_AH + doff, Tm  + (size_t)(m0 + pr) * 32 + kl);
            cp16(st + OFF_BH + doff, Bqt + (size_t)(n0 + pr) * 32 + kl);
        }
        cp_commit();
    };

    issue(0, 0);
    issue(1, 1);

    const int mi = lane >> 3;
    const int l7 = lane & 7;

    for (int i = 0; i < total; i++) {
        cp_wait1();
        __syncthreads();
        if (i + 2 < total) issue(i + 2, (i + 2) % 3);
        else cp_commit();

        const uint32_t st = sbase + (uint32_t)(i % 3) * STAGE_B;
        const bool lora = (i >= kc);

        uint32_t bh[4][2], bl[4][2];
        #pragma unroll
        for (int bg = 0; bg < 2; bg++) {
            uint32_t rowB = warpN + bg * 16 + ((mi >> 1) << 3) + l7;
            uint32_t addr = st + OFF_BH + rowB * 48u + (uint32_t)(mi & 1) * 16u;
            ldm4(bh[2 * bg][0], bh[2 * bg][1], bh[2 * bg + 1][0], bh[2 * bg + 1][1], addr);
            if (!lora)
                ldm4(bl[2 * bg][0], bl[2 * bg][1], bl[2 * bg + 1][0], bl[2 * bg + 1][1],
                     addr + (OFF_BL - OFF_BH));
        }
        #pragma unroll
        for (int mt = 0; mt < 4; mt++) {
            uint32_t rowA = warpM + mt * 16 + ((mi & 1) << 3) + l7;
            uint32_t addrA = st + OFF_AH + rowA * 48u + (uint32_t)(mi >> 1) * 16u;
            uint32_t ah[4], al[4];
            ldm4(ah[0], ah[1], ah[2], ah[3], addrA);
            if (!lora)
                ldm4(al[0], al[1], al[2], al[3], addrA + (OFF_AL - OFF_AH));
            #pragma unroll
            for (int nt = 0; nt < 4; nt++) {
                mma16(acc[mt][nt], ah, bh[nt]);
                if (!lora) {
                    mma16(acc[mt][nt], al, bh[nt]);
                    mma16(acc[mt][nt], ah, bl[nt]);
                }
            }
        }
    }

    // epilogue
    #pragma unroll
    for (int mt = 0; mt < 4; mt++) {
        int row = m0 + warpM + mt * 16 + g;
        #pragma unroll
        for (int nt = 0; nt < 4; nt++) {
            int col = n0 + warpN + nt * 8 + 2 * q;
            if (Cf) {
                *(float2*)&Cf[(size_t)row * N + col] =
                    make_float2(acc[mt][nt][0], acc[mt][nt][1]);
                *(float2*)&Cf[(size_t)(row + 8) * N + col] =
                    make_float2(acc[mt][nt][2], acc[mt][nt][3]);
            } else {
                size_t i0 = (size_t)row * N + col;
                size_t i1 = (size_t)(row + 8) * N + col;
                *(uint32_t*)&Chi[i0] = pack_hi(acc[mt][nt][0], acc[mt][nt][1]);
                *(uint32_t*)&Clo[i0] = pack_lo(acc[mt][nt][0], acc[mt][nt][1]);
                *(uint32_t*)&Chi[i1] = pack_hi(acc[mt][nt][2], acc[mt][nt][3]);
                *(uint32_t*)&Clo[i1] = pack_lo(acc[mt][nt][2], acc[mt][nt][3]);
            }
        }
    }
}

// ---------------------------------------------------------------------------
// Small LoRA-down GEMM: T[M,32] = X[M,K] @ A[K,32]   (writes bf16 RN)
// ---------------------------------------------------------------------------
__global__ void __launch_bounds__(256) lora_down_kernel(
    const float* __restrict__ X, const float* __restrict__ Amat,
    __nv_bfloat16* __restrict__ Tout, int M, int K)
{
    __shared__ __align__(16) float Xs[32][68];
    __shared__ __align__(16) float As2[64][36];

    const int tid = threadIdx.x;
    const int m0  = blockIdx.x * 32;
    const int n   = tid & 31;
    const int mq  = (tid >> 5) * 4;

    float acc[4] = {0.f, 0.f, 0.f, 0.f};

    for (int k0 = 0; k0 < K; k0 += 64) {
        __syncthreads();
        #pragma unroll
        for (int l = 0; l < 2; l++) {
            int idx = tid + l * 256;
            int m   = idx >> 4;
            int k4  = (idx & 15) << 2;
            *(float4*)&Xs[m][k4] =
                *(const float4*)&X[(size_t)(m0 + m) * K + k0 + k4];
        }
        #pragma unroll
        for (int l = 0; l < 2; l++) {
            int idx = tid + l * 256;
            int kk  = idx >> 3;
            int n4  = (idx & 7) << 2;
            *(float4*)&As2[kk][n4] =
                *(const float4*)&Amat[(size_t)(k0 + kk) * 32 + n4];
        }
        __syncthreads();
        #pragma unroll 16
        for (int kk = 0; kk < 64; kk++) {
            float a = As2[kk][n];
            acc[0] = fmaf(Xs[mq + 0][kk], a, acc[0]);
            acc[1] = fmaf(Xs[mq + 1][kk], a, acc[1]);
            acc[2] = fmaf(Xs[mq + 2][kk], a, acc[2]);
            acc[3] = fmaf(Xs[mq + 3][kk], a, acc[3]);
        }
    }
    #pragma unroll
    for (int i = 0; i < 4; i++)
        Tout[(size_t)(m0 + mq + i) * 32 + n] = __float2bfloat16(acc[i]);
}

// ---------------------------------------------------------------------------
// Tensor-core flash attention (bf16x3 hi/lo, online softmax).
// CTA: 256 threads, 8 warps, 128 q-rows.  Grid: (S/128, H, B).
// smem: Qh/Ql [128][136]bf16; 2-stage KV: Kh/Kl/Vh/Vl [64][136]bf16.
// rows padded to 272B -> conflict-free ldmatrix.
// ---------------------------------------------------------------------------
#define AROWB 272
#define QH_OFF 0
#define QL_OFF (128 * AROWB)
#define KV_OFF (2 * 128 * AROWB)
#define KHO 0
#define KLO (64 * AROWB)
#define VHO (2 * 64 * AROWB)
#define VLO (3 * 64 * AROWB)
#define ST_B (4 * 64 * AROWB)
#define ATTN_SMEM (KV_OFF + 2 * ST_B)    // 208896

__global__ void __launch_bounds__(256, 1) attn_mma(
    const __nv_bfloat16* __restrict__ qkvh, const __nv_bfloat16* __restrict__ qkvl,
    const float* __restrict__ alibi, const float* __restrict__ pad,
    float* __restrict__ outf, __nv_bfloat16* __restrict__ outh,
    __nv_bfloat16* __restrict__ outl)
{
    extern __shared__ __align__(128) char smem[];
    const uint32_t sb = smem_u32(smem);
    const int tid = threadIdx.x, wid = tid >> 5, lane = tid & 31;
    const int g = lane >> 2, q = lane & 3, l7 = lane & 7;
    const int q0 = blockIdx.x * 128, h = blockIdx.y, b = blockIdx.z;

    const size_t tokbase = (size_t)(b * S_);

    // --- load Q (both hi/lo) + KV tile 0 as group 0 ---
    {
        const __nv_bfloat16* bH = qkvh + (tokbase + q0) * 6144 + h * 128;
        const __nv_bfloat16* bL = qkvl + (tokbase + q0) * 6144 + h * 128;
        #pragma unroll
        for (int j = 0; j < 8; j++) {
            int idx = tid + j * 256;
            int row = idx >> 4, seg = idx & 15;
            uint32_t off = (uint32_t)row * AROWB + seg * 16;
            cp16(sb + QH_OFF + off, bH + (size_t)row * 6144 + seg * 8);
            cp16(sb + QL_OFF + off, bL + (size_t)row * 6144 + seg * 8);
        }
    }
    auto loadKV = [&](int kt, int st) {
        const uint32_t base = sb + KV_OFF + (uint32_t)st * ST_B;
        const __nv_bfloat16* kH = qkvh + (tokbase + kt * 64) * 6144 + D_ + h * 128;
        const __nv_bfloat16* kL = qkvl + (tokbase + kt * 64) * 6144 + D_ + h * 128;
        const __nv_bfloat16* vH = kH + D_;
        const __nv_bfloat16* vL = kL + D_;
        #pragma unroll
        for (int j = 0; j < 4; j++) {
            int idx = tid + j * 256;
            int row = idx >> 4, seg = idx & 15;
            uint32_t off = (uint32_t)row * AROWB + seg * 16;
            size_t go = (size_t)row * 6144 + seg * 8;
            cp16(base + KHO + off, kH + go);
            cp16(base + KLO + off, kL + go);
            cp16(base + VHO + off, vH + go);
            cp16(base + VLO + off, vL + go);
        }
    };
    loadKV(0, 0); cp_commit();
    loadKV(1, 1); cp_commit();

    float o[16][4];
    #pragma unroll
    for (int i = 0; i < 16; i++)
        #pragma unroll
        for (int e = 0; e < 4; e++) o[i][e] = 0.f;
    float m0r = -1e30f, m1r = -1e30f, l0r = 0.f, l1r = 0.f;

    const float sscale = 0.08838834764831845f;   // 1/sqrt(128)

    // fragment address components
    const uint32_t qoff = (uint32_t)(wid * 16 + ((lane >> 3) & 1) * 8 + l7) * AROWB
                        + ((lane >> 4) & 1) * 16;
    const uint32_t koff = (uint32_t)(((lane >> 4) & 1) * 8 + l7) * AROWB
                        + ((lane >> 3) & 1) * 16;
    const uint32_t voff = (uint32_t)(((lane >> 3) & 1) * 8 + l7) * AROWB
                        + ((lane >> 4) & 1) * 16;

    const float* arow0 = alibi + ((size_t)h * S_ + (q0 + wid * 16 + g)) * S_;
    const float* arow1 = arow0 + 8 * S_;
    const float* prow  = pad + (size_t)b * S_;

    for (int kt = 0; kt < S_ / 64; kt++) {
        cp_wait1();
        __syncthreads();
        const uint32_t st = sb + KV_OFF + (uint32_t)(kt & 1) * ST_B;
        const int k0 = kt * 64;

        // ---- QK^T (bf16x3) ----
        float c[8][4];
        #pragma unroll
        for (int i = 0; i < 8; i++)
            #pragma unroll
            for (int e = 0; e < 4; e++) c[i][e] = 0.f;

        #pragma unroll
        for (int kc = 0; kc < 8; kc++) {
            uint32_t qh4[4], ql4[4];
            ldm4(qh4[0], qh4[1], qh4[2], qh4[3], sb + QH_OFF + qoff + kc * 32);
            ldm4(ql4[0], ql4[1], ql4[2], ql4[3], sb + QL_OFF + qoff + kc * 32);
            #pragma unroll
            for (int np = 0; np < 4; np++) {
                uint32_t kh[4], kl[4];
                uint32_t ka = st + KHO + koff + (uint32_t)np * (16 * AROWB) + kc * 32;
                ldm4(kh[0], kh[1], kh[2], kh[3], ka);
                ldm4(kl[0], kl[1], kl[2], kl[3], ka + (KLO - KHO));
                mma16(c[2 * np],     qh4, &kh[0]);
                mma16(c[2 * np + 1], qh4, &kh[2]);
                mma16(c[2 * np],     ql4, &kh[0]);
                mma16(c[2 * np + 1], ql4, &kh[2]);
                mma16(c[2 * np],     qh4, &kl[0]);
                mma16(c[2 * np + 1], qh4, &kl[2]);
            }
        }

        // ---- bias + online softmax ----
        #pragma unroll
        for (int nt = 0; nt < 8; nt++) {
            int col = k0 + nt * 8 + 2 * q;
            float2 a0 = *(const float2*)(arow0 + col);
            float2 a1 = *(const float2*)(arow1 + col);
            float2 pd = *(const float2*)(prow + col);
            c[nt][0] = fmaf(c[nt][0], sscale, a0.x + pd.x);
            c[nt][1] = fmaf(c[nt][1], sscale, a0.y + pd.y);
            c[nt][2] = fmaf(c[nt][2], sscale, a1.x + pd.x);
            c[nt][3] = fmaf(c[nt][3], sscale, a1.y + pd.y);
        }
        float mx0 = -1e30f, mx1 = -1e30f;
        #pragma unroll
        for (int nt = 0; nt < 8; nt++) {
            mx0 = fmaxf(mx0, fmaxf(c[nt][0], c[nt][1]));
            mx1 = fmaxf(mx1, fmaxf(c[nt][2], c[nt][3]));
        }
        mx0 = fmaxf(mx0, __shfl_xor_sync(0xffffffffu, mx0, 1));
        mx0 = fmaxf(mx0, __shfl_xor_sync(0xffffffffu, mx0, 2));
        mx1 = fmaxf(mx1, __shfl_xor_sync(0xffffffffu, mx1, 1));
        mx1 = fmaxf(mx1, __shfl_xor_sync(0xffffffffu, mx1, 2));
        float mn0 = fmaxf(m0r, mx0), mn1 = fmaxf(m1r, mx1);
        float cr0 = __expf(m0r - mn0), cr1 = __expf(m1r - mn1);
        m0r = mn0; m1r = mn1;
        float s0 = 0.f, s1 = 0.f;
        #pragma unroll
        for (int nt = 0; nt < 8; nt++) {
            c[nt][0] = __expf(c[nt][0] - mn0);
            c[nt][1] = __expf(c[nt][1] - mn0);
            c[nt][2] = __expf(c[nt][2] - mn1);
            c[nt][3] = __expf(c[nt][3] - mn1);
            s0 += c[nt][0] + c[nt][1];
            s1 += c[nt][2] + c[nt][3];
        }
        s0 += __shfl_xor_sync(0xffffffffu, s0, 1);
        s0 += __shfl_xor_sync(0xffffffffu, s0, 2);
        s1 += __shfl_xor_sync(0xffffffffu, s1, 1);
        s1 += __shfl_xor_sync(0xffffffffu, s1, 2);
        l0r = l0r * cr0 + s0;
        l1r = l1r * cr1 + s1;
        #pragma unroll
        for (int i = 0; i < 16; i++) {
            o[i][0] *= cr0; o[i][1] *= cr0;
            o[i][2] *= cr1; o[i][3] *= cr1;
        }

        // ---- PV (bf16x3; P split in registers) ----
        #pragma unroll
        for (int kc = 0; kc < 4; kc++) {
            uint32_t ph[4], pl[4];
            ph[0] = pack_hi(c[2 * kc][0],     c[2 * kc][1]);
            ph[1] = pack_hi(c[2 * kc][2],     c[2 * kc][3]);
            ph[2] = pack_hi(c[2 * kc + 1][0], c[2 * kc + 1][1]);
            ph[3] = pack_hi(c[2 * kc + 1][2], c[2 * kc + 1][3]);
            pl[0] = pack_lo(c[2 * kc][0],     c[2 * kc][1]);
            pl[1] = pack_lo(c[2 * kc][2],     c[2 * kc][3]);
            pl[2] = pack_lo(c[2 * kc + 1][0], c[2 * kc + 1][1]);
            pl[3] = pack_lo(c[2 * kc + 1][2], c[2 * kc + 1][3]);
            uint32_t vrow = st + VHO + voff + (uint32_t)kc * (16 * AROWB);
            #pragma unroll
            for (int dg = 0; dg < 8; dg++) {
                uint32_t vh[4], vl[4];
                ldm4t(vh[0], vh[1], vh[2], vh[3], vrow + dg * 32);
                ldm4t(vl[0], vl[1], vl[2], vl[3], vrow + dg * 32 + (VLO - VHO));
                mma16(o[2 * dg],     ph, &vh[0]);
                mma16(o[2 * dg + 1], ph, &vh[2]);
                mma16(o[2 * dg],     pl, &vh[0]);
                mma16(o[2 * dg + 1], pl, &vh[2]);
                mma16(o[2 * dg],     ph, &vl[0]);
                mma16(o[2 * dg + 1], ph, &vl[2]);
            }
        }

        __syncthreads();
        if (kt + 2 < S_ / 64) { loadKV(kt + 2, kt & 1); cp_commit(); }
        else cp_commit();
    }

    // ---- epilogue ----
    float inv0 = 1.0f / l0r, inv1 = 1.0f / l1r;
    size_t row0 = tokbase + q0 + wid * 16 + g;
    size_t row1 = row0 + 8;
    #pragma unroll
    for (int nt = 0; nt < 16; nt++) {
        int col = h * 128 + nt * 8 + 2 * q;
        float f0 = o[nt][0] * inv0, f1 = o[nt][1] * inv0;
        float f2 = o[nt][2] * inv1, f3 = o[nt][3] * inv1;
        *(float2*)&outf[row0 * D_ + col] = make_float2(f0, f1);
        *(float2*)&outf[row1 * D_ + col] = make_float2(f2, f3);
        *(uint32_t*)&outh[row0 * D_ + col] = pack_hi(f0, f1);
        *(uint32_t*)&outl[row0 * D_ + col] = pack_lo(f0, f1);
        *(uint32_t*)&outh[row1 * D_ + col] = pack_hi(f2, f3);
        *(uint32_t*)&outl[row1 * D_ + col] = pack_lo(f2, f3);
    }
}

// ---------------------------------------------------------------------------
// kernel_launch
// ---------------------------------------------------------------------------
extern "C" void kernel_launch(void* const* d_in, const int* in_sizes, int n_in,
                              void* d_out, int out_size)
{
    const float* x     = (const float*)d_in[0];
    const float* alibi = (const float*)d_in[1];
    const float* pad   = (const float*)d_in[2];
    const float* Wqkv  = (const float*)d_in[3];
    const float* Aqkv  = (const float*)d_in[4];
    const float* Bqkv  = (const float*)d_in[5];
    const float* Wout  = (const float*)d_in[6];
    const float* Aout  = (const float*)d_in[7];
    const float* Bout  = (const float*)d_in[8];
    float* out = (float*)d_out;

    float *attn_p;
    __nv_bfloat16 *qkvh, *qkvl, *xh, *xl, *wqh, *wql, *woh, *wol, *ah, *al;
    __nv_bfloat16 *bqt, *bot, *t1h, *t2h;
    cudaGetSymbolAddress((void**)&attn_p, g_attn);
    cudaGetSymbolAddress((void**)&qkvh, g_qkvh);
    cudaGetSymbolAddress((void**)&qkvl, g_qkvl);
    cudaGetSymbolAddress((void**)&xh,  g_xh);
    cudaGetSymbolAddress((void**)&xl,  g_xl);
    cudaGetSymbolAddress((void**)&wqh, g_wqh);
    cudaGetSymbolAddress((void**)&wql, g_wql);
    cudaGetSymbolAddress((void**)&woh, g_woh);
    cudaGetSymbolAddress((void**)&wol, g_wol);
    cudaGetSymbolAddress((void**)&ah,  g_ah);
    cudaGetSymbolAddress((void**)&al,  g_al);
    cudaGetSymbolAddress((void**)&bqt, g_bqt);
    cudaGetSymbolAddress((void**)&bot, g_bot);
    cudaGetSymbolAddress((void**)&t1h, g_t1h);
    cudaGetSymbolAddress((void**)&t2h, g_t2h);

    cudaFuncSetAttribute(tc_gemm_bf16,
                         cudaFuncAttributeMaxDynamicSharedMemorySize, TCG_SMEM);
    cudaFuncSetAttribute(attn_mma,
                         cudaFuncAttributeMaxDynamicSharedMemorySize, ATTN_SMEM);

    // pre-pass splits
    split_kernel<<<(M_TOK * D_ / 4 + 255) / 256, 256>>>(
        (const float4*)x, (uint2*)xh, (uint2*)xl, M_TOK * D_ / 4);
    split_kernel<<<(3 * D_ * D_ / 4 + 255) / 256, 256>>>(
        (const float4*)Wqkv, (uint2*)wqh, (uint2*)wql, 3 * D_ * D_ / 4);
    split_kernel<<<(D_ * D_ / 4 + 255) / 256, 256>>>(
        (const float4*)Wout, (uint2*)woh, (uint2*)wol, D_ * D_ / 4);
    transpose_scale_kernel<<<(3 * D_ * R_ + 255) / 256, 256>>>(
        Bqkv, bqt, 3 * D_, LORA_SCALE);
    transpose_scale_kernel<<<(D_ * R_ + 255) / 256, 256>>>(
        Bout, bot, D_, LORA_SCALE);

    // t1 = x @ Aqkv
    lora_down_kernel<<<M_TOK / 32, 256>>>(x, Aqkv, t1h, M_TOK, D_);

    // qkv = x @ Wqkv^T + lora  -> bf16 hi/lo directly
    {
        dim3 grid((3 * D_) / 128, M_TOK / 128);
        tc_gemm_bf16<<<grid, 256, TCG_SMEM>>>(xh, xl, wqh, wql, t1h, bqt,
                                              nullptr, qkvh, qkvl,
                                              M_TOK, 3 * D_, D_);
    }

    // attention (tensor-core, bf16x3)
    {
        dim3 grid(S_ / 128, H_, B_);
        attn_mma<<<grid, 256, ATTN_SMEM>>>(qkvh, qkvl, alibi, pad,
                                           attn_p, ah, al);
    }

    // t2 = attn @ Aout
    lora_down_kernel<<<M_TOK / 32, 256>>>(attn_p, Aout, t2h, M_TOK, D_);

    // out = attn @ Wout^T + lora  -> fp32
    {
        dim3 grid(D_ / 128, M_TOK / 128);
        tc_gemm_bf16<<<grid, 256, TCG_SMEM>>>(ah, al, woh, wol, t2h, bot,
                                              out, nullptr, nullptr,
                                              M_TOK, D_, D_);
    }
}

// round 7
// speedup vs baseline: 1.1103x; 1.1103x over previous
#include <cuda_runtime.h>
#include <cuda_bf16.h>
#include <cuda_fp16.h>
#include <cstdint>

// Problem constants
#define B_   2
#define S_   2048
#define D_   2048
#define H_   16
#define HD_  128
#define R_   32
#define M_TOK (B_ * S_)              // 4096 tokens
#define LORA_SCALE (1.0f / 32.0f)

// ---------------------------------------------------------------------------
// Scratch (allocation-free rule: __device__ globals)
// ---------------------------------------------------------------------------
static __device__ float g_attn[M_TOK * D_];      // fp32 attention output

static __device__ __align__(16) __half        g_qkvh[M_TOK * 3 * D_];
static __device__ __align__(16) __half        g_qkvl[M_TOK * 3 * D_];
static __device__ __align__(16) __nv_bfloat16 g_xh[M_TOK * D_];
static __device__ __align__(16) __nv_bfloat16 g_xl[M_TOK * D_];
static __device__ __align__(16) __nv_bfloat16 g_wqh[3 * D_ * D_];
static __device__ __align__(16) __nv_bfloat16 g_wql[3 * D_ * D_];
static __device__ __align__(16) __nv_bfloat16 g_woh[D_ * D_];
static __device__ __align__(16) __nv_bfloat16 g_wol[D_ * D_];
static __device__ __align__(16) __nv_bfloat16 g_ah[M_TOK * D_];
static __device__ __align__(16) __nv_bfloat16 g_al[M_TOK * D_];
static __device__ __align__(16) __nv_bfloat16 g_bqt[3 * D_ * R_];   // [6144][32]
static __device__ __align__(16) __nv_bfloat16 g_bot[D_ * R_];       // [2048][32]
static __device__ __align__(16) __nv_bfloat16 g_t1h[M_TOK * R_];
static __device__ __align__(16) __nv_bfloat16 g_t2h[M_TOK * R_];
static __device__ float g_tpart[8 * M_TOK * R_];                    // split-K partials

// ---------------------------------------------------------------------------
// helpers
// ---------------------------------------------------------------------------
__device__ __forceinline__ uint32_t smem_u32(const void* p) {
    uint32_t a;
    asm("{ .reg .u64 t; cvta.to.shared.u64 t, %1; cvt.u32.u64 %0, t; }"
        : "=r"(a) : "l"(p));
    return a;
}
__device__ __forceinline__ void cp16(uint32_t dst, const void* src) {
    asm volatile("cp.async.cg.shared.global [%0], [%1], 16;"
                 :: "r"(dst), "l"(src) : "memory");
}
__device__ __forceinline__ void cp_commit() {
    asm volatile("cp.async.commit_group;" ::: "memory");
}
__device__ __forceinline__ void cp_wait1() {
    asm volatile("cp.async.wait_group 1;" ::: "memory");
}
__device__ __forceinline__ void ldm4(uint32_t& r0, uint32_t& r1,
                                     uint32_t& r2, uint32_t& r3, uint32_t addr) {
    asm volatile("ldmatrix.sync.aligned.m8n8.x4.shared.b16 {%0,%1,%2,%3}, [%4];"
                 : "=r"(r0), "=r"(r1), "=r"(r2), "=r"(r3) : "r"(addr));
}
__device__ __forceinline__ void ldm4t(uint32_t& r0, uint32_t& r1,
                                      uint32_t& r2, uint32_t& r3, uint32_t addr) {
    asm volatile("ldmatrix.sync.aligned.m8n8.x4.trans.shared.b16 {%0,%1,%2,%3}, [%4];"
                 : "=r"(r0), "=r"(r1), "=r"(r2), "=r"(r3) : "r"(addr));
}
__device__ __forceinline__ void mma16(float* c, const uint32_t* a, const uint32_t* b) {
    asm volatile(
        "mma.sync.aligned.m16n8k16.row.col.f32.bf16.bf16.f32 "
        "{%0,%1,%2,%3}, {%4,%5,%6,%7}, {%8,%9}, {%0,%1,%2,%3};"
        : "+f"(c[0]), "+f"(c[1]), "+f"(c[2]), "+f"(c[3])
        : "r"(a[0]), "r"(a[1]), "r"(a[2]), "r"(a[3]), "r"(b[0]), "r"(b[1]));
}
__device__ __forceinline__ void mma16h(float* c, const uint32_t* a, const uint32_t* b) {
    asm volatile(
        "mma.sync.aligned.m16n8k16.row.col.f32.f16.f16.f32 "
        "{%0,%1,%2,%3}, {%4,%5,%6,%7}, {%8,%9}, {%0,%1,%2,%3};"
        : "+f"(c[0]), "+f"(c[1]), "+f"(c[2]), "+f"(c[3])
        : "r"(a[0]), "r"(a[1]), "r"(a[2]), "r"(a[3]), "r"(b[0]), "r"(b[1]));
}
// bf16 packs (truncation hi, RN residual lo)
__device__ __forceinline__ uint32_t pack_hi(float x, float y) {
    return (__float_as_uint(y) & 0xffff0000u) | (__float_as_uint(x) >> 16);
}
__device__ __forceinline__ uint32_t pack_lo(float x, float y) {
    float lx = x - __uint_as_float(__float_as_uint(x) & 0xffff0000u);
    float ly = y - __uint_as_float(__float_as_uint(y) & 0xffff0000u);
    __nv_bfloat162 t = __floats2bfloat162_rn(lx, ly);
    return *(uint32_t*)&t;
}
// fp16 packs (RN hi, RN residual lo)
__device__ __forceinline__ uint32_t packh_rn(float x, float y) {
    __half2 t = __floats2half2_rn(x, y);
    return *(uint32_t*)&t;
}
__device__ __forceinline__ uint32_t packh_lo(float x, float y, uint32_t hibits) {
    __half2 h = *(__half2*)&hibits;
    float rx = x - __half2float(__low2half(h));
    float ry = y - __half2float(__high2half(h));
    __half2 t = __floats2half2_rn(rx, ry);
    return *(uint32_t*)&t;
}

// ---------------------------------------------------------------------------
// Pre-pass: split fp32 -> bf16 hi (truncation) + bf16 lo (RN residual)
// ---------------------------------------------------------------------------
__global__ void __launch_bounds__(256) split_kernel(
    const float4* __restrict__ src, uint2* __restrict__ hi,
    uint2* __restrict__ lo, int n4)
{
    int i = blockIdx.x * 256 + threadIdx.x;
    if (i >= n4) return;
    float4 v = src[i];
    uint2 h, l;
    h.x = pack_hi(v.x, v.y);
    h.y = pack_hi(v.z, v.w);
    l.x = pack_lo(v.x, v.y);
    l.y = pack_lo(v.z, v.w);
    hi[i] = h;
    lo[i] = l;
}

// Pre-pass: Bq[32,N] -> out[N][32] bf16(RN), scaled
__global__ void __launch_bounds__(256) transpose_scale_kernel(
    const float* __restrict__ Bq, __nv_bfloat16* __restrict__ out,
    int N, float scale)
{
    int idx = blockIdx.x * 256 + threadIdx.x;
    int k = idx & 31;
    int n = idx >> 5;
    if (n < N)
        out[(size_t)n * 32 + k] = __float2bfloat16(Bq[(size_t)k * N + n] * scale);
}

// ---------------------------------------------------------------------------
// Pure-bf16 fused GEMM (bf16x3 via pre-split operands):
//   C = (Ah+Al) @ (Bh+Bl)^T + T @ Bqt^T
// outMode: 0 = fp32 Cf, 1 = bf16 hi/lo, 2 = fp16 hi/lo (RN + residual)
// ---------------------------------------------------------------------------
#define OFF_AH 0
#define OFF_AL 6144
#define OFF_BH 12288
#define OFF_BL 18432
#define STAGE_B 24576
#define TCG_SMEM (3 * STAGE_B)      // 73728 bytes

__global__ void __launch_bounds__(256, 2) tc_gemm_bf16(
    const __nv_bfloat16* __restrict__ Ah, const __nv_bfloat16* __restrict__ Al,
    const __nv_bfloat16* __restrict__ Bh, const __nv_bfloat16* __restrict__ Bl,
    const __nv_bfloat16* __restrict__ Tm, const __nv_bfloat16* __restrict__ Bqt,
    float* __restrict__ Cf, uint16_t* __restrict__ Chi,
    uint16_t* __restrict__ Clo, int M, int N, int K, int outMode)
{
    extern __shared__ __align__(128) char smem[];
    const uint32_t sbase = smem_u32(smem);

    const int tid  = threadIdx.x;
    const int wid  = tid >> 5;
    const int lane = tid & 31;
    const int g    = lane >> 2;
    const int q    = lane & 3;
    const int warpM = (wid & 1) * 64;
    const int warpN = (wid >> 1) * 32;

    const int n0 = blockIdx.x * 128;
    const int m0 = blockIdx.y * 128;

    const int kc    = K >> 4;
    const int total = kc + 2;

    float acc[4][4][4];
    #pragma unroll
    for (int i = 0; i < 4; i++)
        #pragma unroll
        for (int j = 0; j < 4; j++)
            #pragma unroll
            for (int e = 0; e < 4; e++) acc[i][j][e] = 0.f;

    const int pr = tid >> 1;
    const int ps = tid & 1;
    auto issue = [&](int c, int s) {
        const uint32_t st = sbase + (uint32_t)s * STAGE_B;
        const uint32_t doff = (uint32_t)pr * 48u + (uint32_t)ps * 16u;
        if (c < kc) {
            size_t ao = (size_t)(m0 + pr) * K + c * 16 + ps * 8;
            size_t bo = (size_t)(n0 + pr) * K + c * 16 + ps * 8;
            cp16(st + OFF_AH + doff, Ah + ao);
            cp16(st + OFF_AL + doff, Al + ao);
            cp16(st + OFF_BH + doff, Bh + bo);
            cp16(st + OFF_BL + doff, Bl + bo);
        } else {
            int kl = (c - kc) * 16 + ps * 8;
            cp16(st + OFF_AH + doff, Tm  + (size_t)(m0 + pr) * 32 + kl);
            cp16(st + OFF_BH + doff, Bqt + (size_t)(n0 + pr) * 32 + kl);
        }
        cp_commit();
    };

    issue(0, 0);
    issue(1, 1);

    const int mi = lane >> 3;
    const int l7 = lane & 7;

    for (int i = 0; i < total; i++) {
        cp_wait1();
        __syncthreads();
        if (i + 2 < total) issue(i + 2, (i + 2) % 3);
        else cp_commit();

        const uint32_t st = sbase + (uint32_t)(i % 3) * STAGE_B;
        const bool lora = (i >= kc);

        uint32_t bh[4][2], bl[4][2];
        #pragma unroll
        for (int bg = 0; bg < 2; bg++) {
            uint32_t rowB = warpN + bg * 16 + ((mi >> 1) << 3) + l7;
            uint32_t addr = st + OFF_BH + rowB * 48u + (uint32_t)(mi & 1) * 16u;
            ldm4(bh[2 * bg][0], bh[2 * bg][1], bh[2 * bg + 1][0], bh[2 * bg + 1][1], addr);
            if (!lora)
                ldm4(bl[2 * bg][0], bl[2 * bg][1], bl[2 * bg + 1][0], bl[2 * bg + 1][1],
                     addr + (OFF_BL - OFF_BH));
        }
        #pragma unroll
        for (int mt = 0; mt < 4; mt++) {
            uint32_t rowA = warpM + mt * 16 + ((mi & 1) << 3) + l7;
            uint32_t addrA = st + OFF_AH + rowA * 48u + (uint32_t)(mi >> 1) * 16u;
            uint32_t ah[4], al[4];
            ldm4(ah[0], ah[1], ah[2], ah[3], addrA);
            if (!lora)
                ldm4(al[0], al[1], al[2], al[3], addrA + (OFF_AL - OFF_AH));
            #pragma unroll
            for (int nt = 0; nt < 4; nt++) {
                mma16(acc[mt][nt], ah, bh[nt]);
                if (!lora) {
                    mma16(acc[mt][nt], al, bh[nt]);
                    mma16(acc[mt][nt], ah, bl[nt]);
                }
            }
        }
    }

    // epilogue
    #pragma unroll
    for (int mt = 0; mt < 4; mt++) {
        int row = m0 + warpM + mt * 16 + g;
        #pragma unroll
        for (int nt = 0; nt < 4; nt++) {
            int col = n0 + warpN + nt * 8 + 2 * q;
            size_t i0 = (size_t)row * N + col;
            size_t i1 = (size_t)(row + 8) * N + col;
            if (outMode == 0) {
                *(float2*)&Cf[i0] = make_float2(acc[mt][nt][0], acc[mt][nt][1]);
                *(float2*)&Cf[i1] = make_float2(acc[mt][nt][2], acc[mt][nt][3]);
            } else if (outMode == 1) {
                *(uint32_t*)&Chi[i0] = pack_hi(acc[mt][nt][0], acc[mt][nt][1]);
                *(uint32_t*)&Clo[i0] = pack_lo(acc[mt][nt][0], acc[mt][nt][1]);
                *(uint32_t*)&Chi[i1] = pack_hi(acc[mt][nt][2], acc[mt][nt][3]);
                *(uint32_t*)&Clo[i1] = pack_lo(acc[mt][nt][2], acc[mt][nt][3]);
            } else {
                uint32_t h0 = packh_rn(acc[mt][nt][0], acc[mt][nt][1]);
                uint32_t h1 = packh_rn(acc[mt][nt][2], acc[mt][nt][3]);
                *(uint32_t*)&Chi[i0] = h0;
                *(uint32_t*)&Clo[i0] = packh_lo(acc[mt][nt][0], acc[mt][nt][1], h0);
                *(uint32_t*)&Chi[i1] = h1;
                *(uint32_t*)&Clo[i1] = packh_lo(acc[mt][nt][2], acc[mt][nt][3], h1);
            }
        }
    }
}

// ---------------------------------------------------------------------------
// LoRA-down split-K: part[s][M][32] = X[M, s-slice] @ A[s-slice, 32]
// grid (M/32, 8); then reduce+convert.
// ---------------------------------------------------------------------------
__global__ void __launch_bounds__(256) lora_down_partial(
    const float* __restrict__ X, const float* __restrict__ Amat,
    float* __restrict__ part, int M, int K)
{
    __shared__ __align__(16) float Xs[32][68];
    __shared__ __align__(16) float As2[64][36];

    const int tid = threadIdx.x;
    const int m0  = blockIdx.x * 32;
    const int s   = blockIdx.y;
    const int KS  = K >> 3;               // 256
    const int kb  = s * KS;
    const int n   = tid & 31;
    const int mq  = (tid >> 5) * 4;

    float acc[4] = {0.f, 0.f, 0.f, 0.f};

    for (int k0 = kb; k0 < kb + KS; k0 += 64) {
        __syncthreads();
        #pragma unroll
        for (int l = 0; l < 2; l++) {
            int idx = tid + l * 256;
            int m   = idx >> 4;
            int k4  = (idx & 15) << 2;
            *(float4*)&Xs[m][k4] =
                *(const float4*)&X[(size_t)(m0 + m) * K + k0 + k4];
        }
        #pragma unroll
        for (int l = 0; l < 2; l++) {
            int idx = tid + l * 256;
            int kk  = idx >> 3;
            int n4  = (idx & 7) << 2;
            *(float4*)&As2[kk][n4] =
                *(const float4*)&Amat[(size_t)(k0 + kk) * 32 + n4];
        }
        __syncthreads();
        #pragma unroll 16
        for (int kk = 0; kk < 64; kk++) {
            float a = As2[kk][n];
            acc[0] = fmaf(Xs[mq + 0][kk], a, acc[0]);
            acc[1] = fmaf(Xs[mq + 1][kk], a, acc[1]);
            acc[2] = fmaf(Xs[mq + 2][kk], a, acc[2]);
            acc[3] = fmaf(Xs[mq + 3][kk], a, acc[3]);
        }
    }
    float* dst = part + (size_t)s * M * 32;
    #pragma unroll
    for (int i = 0; i < 4; i++)
        dst[(size_t)(m0 + mq + i) * 32 + n] = acc[i];
}

__global__ void __launch_bounds__(256) lora_reduce(
    const float* __restrict__ part, __nv_bfloat16* __restrict__ outT, int n)
{
    int i = blockIdx.x * 256 + threadIdx.x;
    if (i >= n) return;
    float sum = 0.f;
    #pragma unroll
    for (int p = 0; p < 8; p++) sum += part[(size_t)p * n + i];
    outT[i] = __float2bfloat16(sum);
}

// ---------------------------------------------------------------------------
// Tensor-core flash attention, fp16 2-pass:
//   QK^T = qh*kh + ql*kh   (Q 2-term, K 1-term)
//   PV   = p*vh + p*vl     (P 1-term, V 2-term)
// CTA: 256 threads, 8 warps, 128 q-rows.  Grid: (S/128, H, B).
// ---------------------------------------------------------------------------
#define AROWB 272
#define QH_OFF 0
#define QL_OFF (128 * AROWB)
#define KV_OFF (2 * 128 * AROWB)
#define KHO 0
#define VHO (64 * AROWB)
#define VLO (2 * 64 * AROWB)
#define ST_B (3 * 64 * AROWB)
#define ATTN_SMEM (KV_OFF + 2 * ST_B)    // 174080

__global__ void __launch_bounds__(256, 1) attn_mma(
    const __half* __restrict__ qkvh, const __half* __restrict__ qkvl,
    const float* __restrict__ alibi, const float* __restrict__ pad,
    float* __restrict__ outf, uint16_t* __restrict__ outh,
    uint16_t* __restrict__ outl)
{
    extern __shared__ __align__(128) char smem[];
    const uint32_t sb = smem_u32(smem);
    const int tid = threadIdx.x, wid = tid >> 5, lane = tid & 31;
    const int g = lane >> 2, q = lane & 3, l7 = lane & 7;
    const int q0 = blockIdx.x * 128, h = blockIdx.y, b = blockIdx.z;

    const size_t tokbase = (size_t)(b * S_);

    // --- load Q (hi/lo) + KV tile 0 as group 0 ---
    {
        const __half* bH = qkvh + (tokbase + q0) * 6144 + h * 128;
        const __half* bL = qkvl + (tokbase + q0) * 6144 + h * 128;
        #pragma unroll
        for (int j = 0; j < 8; j++) {
            int idx = tid + j * 256;
            int row = idx >> 4, seg = idx & 15;
            uint32_t off = (uint32_t)row * AROWB + seg * 16;
            cp16(sb + QH_OFF + off, bH + (size_t)row * 6144 + seg * 8);
            cp16(sb + QL_OFF + off, bL + (size_t)row * 6144 + seg * 8);
        }
    }
    auto loadKV = [&](int kt, int st) {
        const uint32_t base = sb + KV_OFF + (uint32_t)st * ST_B;
        const __half* kH = qkvh + (tokbase + kt * 64) * 6144 + D_ + h * 128;
        const __half* vH = kH + D_;
        const __half* vL = qkvl + (tokbase + kt * 64) * 6144 + 2 * D_ + h * 128;
        #pragma unroll
        for (int j = 0; j < 4; j++) {
            int idx = tid + j * 256;
            int row = idx >> 4, seg = idx & 15;
            uint32_t off = (uint32_t)row * AROWB + seg * 16;
            size_t go = (size_t)row * 6144 + seg * 8;
            cp16(base + KHO + off, kH + go);
            cp16(base + VHO + off, vH + go);
            cp16(base + VLO + off, vL + go);
        }
    };
    loadKV(0, 0); cp_commit();
    loadKV(1, 1); cp_commit();

    float o[16][4];
    #pragma unroll
    for (int i = 0; i < 16; i++)
        #pragma unroll
        for (int e = 0; e < 4; e++) o[i][e] = 0.f;
    float m0r = -1e30f, m1r = -1e30f, l0r = 0.f, l1r = 0.f;

    const float sscale = 0.08838834764831845f;   // 1/sqrt(128)

    const uint32_t qoff = (uint32_t)(wid * 16 + ((lane >> 3) & 1) * 8 + l7) * AROWB
                        + ((lane >> 4) & 1) * 16;
    const uint32_t koff = (uint32_t)(((lane >> 4) & 1) * 8 + l7) * AROWB
                        + ((lane >> 3) & 1) * 16;
    const uint32_t voff = (uint32_t)(((lane >> 3) & 1) * 8 + l7) * AROWB
                        + ((lane >> 4) & 1) * 16;

    const float* arow0 = alibi + ((size_t)h * S_ + (q0 + wid * 16 + g)) * S_;
    const float* arow1 = arow0 + 8 * S_;
    const float* prow  = pad + (size_t)b * S_;

    for (int kt = 0; kt < S_ / 64; kt++) {
        cp_wait1();
        __syncthreads();
        const uint32_t st = sb + KV_OFF + (uint32_t)(kt & 1) * ST_B;
        const int k0 = kt * 64;

        // ---- QK^T (fp16, 2-pass) ----
        float c[8][4];
        #pragma unroll
        for (int i = 0; i < 8; i++)
            #pragma unroll
            for (int e = 0; e < 4; e++) c[i][e] = 0.f;

        #pragma unroll
        for (int kc = 0; kc < 8; kc++) {
            uint32_t qh4[4], ql4[4];
            ldm4(qh4[0], qh4[1], qh4[2], qh4[3], sb + QH_OFF + qoff + kc * 32);
            ldm4(ql4[0], ql4[1], ql4[2], ql4[3], sb + QL_OFF + qoff + kc * 32);
            #pragma unroll
            for (int np = 0; np < 4; np++) {
                uint32_t kh[4];
                uint32_t ka = st + KHO + koff + (uint32_t)np * (16 * AROWB) + kc * 32;
                ldm4(kh[0], kh[1], kh[2], kh[3], ka);
                mma16h(c[2 * np],     qh4, &kh[0]);
                mma16h(c[2 * np + 1], qh4, &kh[2]);
                mma16h(c[2 * np],     ql4, &kh[0]);
                mma16h(c[2 * np + 1], ql4, &kh[2]);
            }
        }

        // ---- bias + online softmax ----
        #pragma unroll
        for (int nt = 0; nt < 8; nt++) {
            int col = k0 + nt * 8 + 2 * q;
            float2 a0 = *(const float2*)(arow0 + col);
            float2 a1 = *(const float2*)(arow1 + col);
            float2 pd = *(const float2*)(prow + col);
            c[nt][0] = fmaf(c[nt][0], sscale, a0.x + pd.x);
            c[nt][1] = fmaf(c[nt][1], sscale, a0.y + pd.y);
            c[nt][2] = fmaf(c[nt][2], sscale, a1.x + pd.x);
            c[nt][3] = fmaf(c[nt][3], sscale, a1.y + pd.y);
        }
        float mx0 = -1e30f, mx1 = -1e30f;
        #pragma unroll
        for (int nt = 0; nt < 8; nt++) {
            mx0 = fmaxf(mx0, fmaxf(c[nt][0], c[nt][1]));
            mx1 = fmaxf(mx1, fmaxf(c[nt][2], c[nt][3]));
        }
        mx0 = fmaxf(mx0, __shfl_xor_sync(0xffffffffu, mx0, 1));
        mx0 = fmaxf(mx0, __shfl_xor_sync(0xffffffffu, mx0, 2));
        mx1 = fmaxf(mx1, __shfl_xor_sync(0xffffffffu, mx1, 1));
        mx1 = fmaxf(mx1, __shfl_xor_sync(0xffffffffu, mx1, 2));
        float mn0 = fmaxf(m0r, mx0), mn1 = fmaxf(m1r, mx1);
        float cr0 = __expf(m0r - mn0), cr1 = __expf(m1r - mn1);
        m0r = mn0; m1r = mn1;
        float s0 = 0.f, s1 = 0.f;
        #pragma unroll
        for (int nt = 0; nt < 8; nt++) {
            c[nt][0] = __expf(c[nt][0] - mn0);
            c[nt][1] = __expf(c[nt][1] - mn0);
            c[nt][2] = __expf(c[nt][2] - mn1);
            c[nt][3] = __expf(c[nt][3] - mn1);
            s0 += c[nt][0] + c[nt][1];
            s1 += c[nt][2] + c[nt][3];
        }
        s0 += __shfl_xor_sync(0xffffffffu, s0, 1);
        s0 += __shfl_xor_sync(0xffffffffu, s0, 2);
        s1 += __shfl_xor_sync(0xffffffffu, s1, 1);
        s1 += __shfl_xor_sync(0xffffffffu, s1, 2);
        l0r = l0r * cr0 + s0;
        l1r = l1r * cr1 + s1;
        #pragma unroll
        for (int i = 0; i < 16; i++) {
            o[i][0] *= cr0; o[i][1] *= cr0;
            o[i][2] *= cr1; o[i][3] *= cr1;
        }

        // ---- PV (fp16, 2-pass: P single, V hi+lo) ----
        #pragma unroll
        for (int kc = 0; kc < 4; kc++) {
            uint32_t ph[4];
            ph[0] = packh_rn(c[2 * kc][0],     c[2 * kc][1]);
            ph[1] = packh_rn(c[2 * kc][2],     c[2 * kc][3]);
            ph[2] = packh_rn(c[2 * kc + 1][0], c[2 * kc + 1][1]);
            ph[3] = packh_rn(c[2 * kc + 1][2], c[2 * kc + 1][3]);
            uint32_t vrow = st + VHO + voff + (uint32_t)kc * (16 * AROWB);
            #pragma unroll
            for (int dg = 0; dg < 8; dg++) {
                uint32_t vh[4], vl[4];
                ldm4t(vh[0], vh[1], vh[2], vh[3], vrow + dg * 32);
                ldm4t(vl[0], vl[1], vl[2], vl[3], vrow + dg * 32 + (VLO - VHO));
                mma16h(o[2 * dg],     ph, &vh[0]);
                mma16h(o[2 * dg + 1], ph, &vh[2]);
                mma16h(o[2 * dg],     ph, &vl[0]);
                mma16h(o[2 * dg + 1], ph, &vl[2]);
            }
        }

        __syncthreads();
        if (kt + 2 < S_ / 64) { loadKV(kt + 2, kt & 1); cp_commit(); }
        else cp_commit();
    }

    // ---- epilogue ----
    float inv0 = 1.0f / l0r, inv1 = 1.0f / l1r;
    size_t row0 = tokbase + q0 + wid * 16 + g;
    size_t row1 = row0 + 8;
    #pragma unroll
    for (int nt = 0; nt < 16; nt++) {
        int col = h * 128 + nt * 8 + 2 * q;
        float f0 = o[nt][0] * inv0, f1 = o[nt][1] * inv0;
        float f2 = o[nt][2] * inv1, f3 = o[nt][3] * inv1;
        *(float2*)&outf[row0 * D_ + col] = make_float2(f0, f1);
        *(float2*)&outf[row1 * D_ + col] = make_float2(f2, f3);
        *(uint32_t*)&outh[row0 * D_ + col] = pack_hi(f0, f1);
        *(uint32_t*)&outl[row0 * D_ + col] = pack_lo(f0, f1);
        *(uint32_t*)&outh[row1 * D_ + col] = pack_hi(f2, f3);
        *(uint32_t*)&outl[row1 * D_ + col] = pack_lo(f2, f3);
    }
}

// ---------------------------------------------------------------------------
// kernel_launch
// ---------------------------------------------------------------------------
extern "C" void kernel_launch(void* const* d_in, const int* in_sizes, int n_in,
                              void* d_out, int out_size)
{
    const float* x     = (const float*)d_in[0];
    const float* alibi = (const float*)d_in[1];
    const float* pad   = (const float*)d_in[2];
    const float* Wqkv  = (const float*)d_in[3];
    const float* Aqkv  = (const float*)d_in[4];
    const float* Bqkv  = (const float*)d_in[5];
    const float* Wout  = (const float*)d_in[6];
    const float* Aout  = (const float*)d_in[7];
    const float* Bout  = (const float*)d_in[8];
    float* out = (float*)d_out;

    float *attn_p, *tpart;
    __half *qkvh, *qkvl;
    __nv_bfloat16 *xh, *xl, *wqh, *wql, *woh, *wol, *ah, *al;
    __nv_bfloat16 *bqt, *bot, *t1h, *t2h;
    cudaGetSymbolAddress((void**)&attn_p, g_attn);
    cudaGetSymbolAddress((void**)&tpart, g_tpart);
    cudaGetSymbolAddress((void**)&qkvh, g_qkvh);
    cudaGetSymbolAddress((void**)&qkvl, g_qkvl);
    cudaGetSymbolAddress((void**)&xh,  g_xh);
    cudaGetSymbolAddress((void**)&xl,  g_xl);
    cudaGetSymbolAddress((void**)&wqh, g_wqh);
    cudaGetSymbolAddress((void**)&wql, g_wql);
    cudaGetSymbolAddress((void**)&woh, g_woh);
    cudaGetSymbolAddress((void**)&wol, g_wol);
    cudaGetSymbolAddress((void**)&ah,  g_ah);
    cudaGetSymbolAddress((void**)&al,  g_al);
    cudaGetSymbolAddress((void**)&bqt, g_bqt);
    cudaGetSymbolAddress((void**)&bot, g_bot);
    cudaGetSymbolAddress((void**)&t1h, g_t1h);
    cudaGetSymbolAddress((void**)&t2h, g_t2h);

    cudaFuncSetAttribute(tc_gemm_bf16,
                         cudaFuncAttributeMaxDynamicSharedMemorySize, TCG_SMEM);
    cudaFuncSetAttribute(attn_mma,
                         cudaFuncAttributeMaxDynamicSharedMemorySize, ATTN_SMEM);

    // pre-pass splits
    split_kernel<<<(M_TOK * D_ / 4 + 255) / 256, 256>>>(
        (const float4*)x, (uint2*)xh, (uint2*)xl, M_TOK * D_ / 4);
    split_kernel<<<(3 * D_ * D_ / 4 + 255) / 256, 256>>>(
        (const float4*)Wqkv, (uint2*)wqh, (uint2*)wql, 3 * D_ * D_ / 4);
    split_kernel<<<(D_ * D_ / 4 + 255) / 256, 256>>>(
        (const float4*)Wout, (uint2*)woh, (uint2*)wol, D_ * D_ / 4);
    transpose_scale_kernel<<<(3 * D_ * R_ + 255) / 256, 256>>>(
        Bqkv, bqt, 3 * D_, LORA_SCALE);
    transpose_scale_kernel<<<(D_ * R_ + 255) / 256, 256>>>(
        Bout, bot, D_, LORA_SCALE);

    // t1 = x @ Aqkv  (split-K)
    lora_down_partial<<<dim3(M_TOK / 32, 8), 256>>>(x, Aqkv, tpart, M_TOK, D_);
    lora_reduce<<<(M_TOK * R_ + 255) / 256, 256>>>(tpart, t1h, M_TOK * R_);

    // qkv = x @ Wqkv^T + lora  -> fp16 hi/lo (RN + residual)
    {
        dim3 grid((3 * D_) / 128, M_TOK / 128);
        tc_gemm_bf16<<<grid, 256, TCG_SMEM>>>(xh, xl, wqh, wql, t1h, bqt,
                                              nullptr, (uint16_t*)qkvh,
                                              (uint16_t*)qkvl,
                                              M_TOK, 3 * D_, D_, 2);
    }

    // attention (tensor-core, fp16 2-pass)
    {
        dim3 grid(S_ / 128, H_, B_);
        attn_mma<<<grid, 256, ATTN_SMEM>>>(qkvh, qkvl, alibi, pad,
                                           attn_p, (uint16_t*)ah, (uint16_t*)al);
    }

    // t2 = attn @ Aout  (split-K)
    lora_down_partial<<<dim3(M_TOK / 32, 8), 256>>>(attn_p, Aout, tpart, M_TOK, D_);
    lora_reduce<<<(M_TOK * R_ + 255) / 256, 256>>>(tpart, t2h, M_TOK * R_);

    // out = attn @ Wout^T + lora  -> fp32
    {
        dim3 grid(D_ / 128, M_TOK / 128);
        tc_gemm_bf16<<<grid, 256, TCG_SMEM>>>(ah, al, woh, wol, t2h, bot,
                                              out, nullptr, nullptr,
                                              M_TOK, D_, D_, 0);
    }
}

// round 8
// speedup vs baseline: 1.4369x; 1.2941x over previous
#include <cuda_runtime.h>
#include <cuda_bf16.h>
#include <cuda_fp16.h>
#include <cstdint>

// Problem constants
#define B_   2
#define S_   2048
#define D_   2048
#define H_   16
#define HD_  128
#define R_   32
#define M_TOK (B_ * S_)              // 4096 tokens
#define LORA_SCALE (1.0f / 32.0f)

// ---------------------------------------------------------------------------
// Scratch (allocation-free rule: __device__ globals)
// ---------------------------------------------------------------------------
static __device__ float g_attn[M_TOK * D_];      // fp32 attention output

static __device__ __align__(16) __half g_qkvh[M_TOK * 3 * D_];
static __device__ __align__(16) __half g_qkvl[M_TOK * 3 * D_];
static __device__ __align__(16) __half g_xh[M_TOK * D_];
static __device__ __align__(16) __half g_xl[M_TOK * D_];
static __device__ __align__(16) __half g_wqh[3 * D_ * D_];
static __device__ __align__(16) __half g_woh[D_ * D_];
static __device__ __align__(16) __half g_ah[M_TOK * D_];
static __device__ __align__(16) __half g_al[M_TOK * D_];
static __device__ __align__(16) __half g_bqt[3 * D_ * R_];   // [6144][32]
static __device__ __align__(16) __half g_bot[D_ * R_];       // [2048][32]
static __device__ __align__(16) __half g_t1h[M_TOK * R_];
static __device__ __align__(16) __half g_t2h[M_TOK * R_];
static __device__ float g_tpart[8 * M_TOK * R_];             // split-K partials

// ---------------------------------------------------------------------------
// helpers
// ---------------------------------------------------------------------------
__device__ __forceinline__ uint32_t smem_u32(const void* p) {
    uint32_t a;
    asm("{ .reg .u64 t; cvta.to.shared.u64 t, %1; cvt.u32.u64 %0, t; }"
        : "=r"(a) : "l"(p));
    return a;
}
__device__ __forceinline__ void cp16(uint32_t dst, const void* src) {
    asm volatile("cp.async.cg.shared.global [%0], [%1], 16;"
                 :: "r"(dst), "l"(src) : "memory");
}
__device__ __forceinline__ void cp_commit() {
    asm volatile("cp.async.commit_group;" ::: "memory");
}
__device__ __forceinline__ void cp_wait1() {
    asm volatile("cp.async.wait_group 1;" ::: "memory");
}
__device__ __forceinline__ void ldm4(uint32_t& r0, uint32_t& r1,
                                     uint32_t& r2, uint32_t& r3, uint32_t addr) {
    asm volatile("ldmatrix.sync.aligned.m8n8.x4.shared.b16 {%0,%1,%2,%3}, [%4];"
                 : "=r"(r0), "=r"(r1), "=r"(r2), "=r"(r3) : "r"(addr));
}
__device__ __forceinline__ void ldm4t(uint32_t& r0, uint32_t& r1,
                                      uint32_t& r2, uint32_t& r3, uint32_t addr) {
    asm volatile("ldmatrix.sync.aligned.m8n8.x4.trans.shared.b16 {%0,%1,%2,%3}, [%4];"
                 : "=r"(r0), "=r"(r1), "=r"(r2), "=r"(r3) : "r"(addr));
}
__device__ __forceinline__ void mma16h(float* c, const uint32_t* a, const uint32_t* b) {
    asm volatile(
        "mma.sync.aligned.m16n8k16.row.col.f32.f16.f16.f32 "
        "{%0,%1,%2,%3}, {%4,%5,%6,%7}, {%8,%9}, {%0,%1,%2,%3};"
        : "+f"(c[0]), "+f"(c[1]), "+f"(c[2]), "+f"(c[3])
        : "r"(a[0]), "r"(a[1]), "r"(a[2]), "r"(a[3]), "r"(b[0]), "r"(b[1]));
}
// fp16 packs (RN hi, RN residual lo)
__device__ __forceinline__ uint32_t packh_rn(float x, float y) {
    __half2 t = __floats2half2_rn(x, y);
    return *(uint32_t*)&t;
}
__device__ __forceinline__ uint32_t packh_lo(float x, float y, uint32_t hibits) {
    __half2 h = *(__half2*)&hibits;
    float rx = x - __half2float(__low2half(h));
    float ry = y - __half2float(__high2half(h));
    __half2 t = __floats2half2_rn(rx, ry);
    return *(uint32_t*)&t;
}

// ---------------------------------------------------------------------------
// Pre-pass: split fp32 -> fp16 hi (RN) + fp16 lo (RN residual)
// ---------------------------------------------------------------------------
__global__ void __launch_bounds__(256) splith_kernel(
    const float4* __restrict__ src, uint2* __restrict__ hi,
    uint2* __restrict__ lo, int n4)
{
    int i = blockIdx.x * 256 + threadIdx.x;
    if (i >= n4) return;
    float4 v = src[i];
    uint2 h, l;
    h.x = packh_rn(v.x, v.y);
    h.y = packh_rn(v.z, v.w);
    l.x = packh_lo(v.x, v.y, h.x);
    l.y = packh_lo(v.z, v.w, h.y);
    hi[i] = h;
    lo[i] = l;
}

// Pre-pass: fp32 -> fp16 RN (single term, for weights)
__global__ void __launch_bounds__(256) convh_kernel(
    const float4* __restrict__ src, uint2* __restrict__ dst, int n4)
{
    int i = blockIdx.x * 256 + threadIdx.x;
    if (i >= n4) return;
    float4 v = src[i];
    dst[i] = make_uint2(packh_rn(v.x, v.y), packh_rn(v.z, v.w));
}

// Pre-pass: Bq[32,N] -> out[N][32] fp16(RN), scaled
__global__ void __launch_bounds__(256) transpose_scale_kernel(
    const float* __restrict__ Bq, __half* __restrict__ out,
    int N, float scale)
{
    int idx = blockIdx.x * 256 + threadIdx.x;
    int k = idx & 31;
    int n = idx >> 5;
    if (n < N)
        out[(size_t)n * 32 + k] = __float2half(Bq[(size_t)k * N + n] * scale);
}

// ---------------------------------------------------------------------------
// fp16x2 fused GEMM (2-pass: A 2-term, B single):
//   C = (Ah+Al) @ Bh^T + T @ Bqt^T
// outMode: 0 = fp32 Cf, 2 = fp16 hi/lo (RN + residual)
// smem/stage: 3 tiles (Ah, Al, Bh), 128 rows x 48B each
// ---------------------------------------------------------------------------
#define OFF_AH 0
#define OFF_AL 6144
#define OFF_BH 12288
#define STAGE_B 18432
#define TCG_SMEM (3 * STAGE_B)      // 55296 bytes

__global__ void __launch_bounds__(256, 2) tc_gemm_fp16(
    const __half* __restrict__ Ah, const __half* __restrict__ Al,
    const __half* __restrict__ Bh,
    const __half* __restrict__ Tm, const __half* __restrict__ Bqt,
    float* __restrict__ Cf, uint16_t* __restrict__ Chi,
    uint16_t* __restrict__ Clo, int M, int N, int K, int outMode)
{
    extern __shared__ __align__(128) char smem[];
    const uint32_t sbase = smem_u32(smem);

    const int tid  = threadIdx.x;
    const int wid  = tid >> 5;
    const int lane = tid & 31;
    const int g    = lane >> 2;
    const int q    = lane & 3;
    const int warpM = (wid & 1) * 64;
    const int warpN = (wid >> 1) * 32;

    const int n0 = blockIdx.x * 128;
    const int m0 = blockIdx.y * 128;

    const int kc    = K >> 4;
    const int total = kc + 2;

    float acc[4][4][4];
    #pragma unroll
    for (int i = 0; i < 4; i++)
        #pragma unroll
        for (int j = 0; j < 4; j++)
            #pragma unroll
            for (int e = 0; e < 4; e++) acc[i][j][e] = 0.f;

    const int pr = tid >> 1;
    const int ps = tid & 1;
    auto issue = [&](int c, int s) {
        const uint32_t st = sbase + (uint32_t)s * STAGE_B;
        const uint32_t doff = (uint32_t)pr * 48u + (uint32_t)ps * 16u;
        if (c < kc) {
            size_t ao = (size_t)(m0 + pr) * K + c * 16 + ps * 8;
            size_t bo = (size_t)(n0 + pr) * K + c * 16 + ps * 8;
            cp16(st + OFF_AH + doff, Ah + ao);
            cp16(st + OFF_AL + doff, Al + ao);
            cp16(st + OFF_BH + doff, Bh + bo);
        } else {
            int kl = (c - kc) * 16 + ps * 8;
            cp16(st + OFF_AH + doff, Tm  + (size_t)(m0 + pr) * 32 + kl);
            cp16(st + OFF_BH + doff, Bqt + (size_t)(n0 + pr) * 32 + kl);
        }
        cp_commit();
    };

    issue(0, 0);
    issue(1, 1);

    const int mi = lane >> 3;
    const int l7 = lane & 7;

    for (int i = 0; i < total; i++) {
        cp_wait1();
        __syncthreads();
        if (i + 2 < total) issue(i + 2, (i + 2) % 3);
        else cp_commit();

        const uint32_t st = sbase + (uint32_t)(i % 3) * STAGE_B;
        const bool lora = (i >= kc);

        uint32_t bh[4][2];
        #pragma unroll
        for (int bg = 0; bg < 2; bg++) {
            uint32_t rowB = warpN + bg * 16 + ((mi >> 1) << 3) + l7;
            uint32_t addr = st + OFF_BH + rowB * 48u + (uint32_t)(mi & 1) * 16u;
            ldm4(bh[2 * bg][0], bh[2 * bg][1], bh[2 * bg + 1][0], bh[2 * bg + 1][1], addr);
        }
        #pragma unroll
        for (int mt = 0; mt < 4; mt++) {
            uint32_t rowA = warpM + mt * 16 + ((mi & 1) << 3) + l7;
            uint32_t addrA = st + OFF_AH + rowA * 48u + (uint32_t)(mi >> 1) * 16u;
            uint32_t ah[4], al[4];
            ldm4(ah[0], ah[1], ah[2], ah[3], addrA);
            if (!lora)
                ldm4(al[0], al[1], al[2], al[3], addrA + (OFF_AL - OFF_AH));
            #pragma unroll
            for (int nt = 0; nt < 4; nt++) {
                mma16h(acc[mt][nt], ah, bh[nt]);
                if (!lora)
                    mma16h(acc[mt][nt], al, bh[nt]);
            }
        }
    }

    // epilogue
    #pragma unroll
    for (int mt = 0; mt < 4; mt++) {
        int row = m0 + warpM + mt * 16 + g;
        #pragma unroll
        for (int nt = 0; nt < 4; nt++) {
            int col = n0 + warpN + nt * 8 + 2 * q;
            size_t i0 = (size_t)row * N + col;
            size_t i1 = (size_t)(row + 8) * N + col;
            if (outMode == 0) {
                *(float2*)&Cf[i0] = make_float2(acc[mt][nt][0], acc[mt][nt][1]);
                *(float2*)&Cf[i1] = make_float2(acc[mt][nt][2], acc[mt][nt][3]);
            } else {
                uint32_t h0 = packh_rn(acc[mt][nt][0], acc[mt][nt][1]);
                uint32_t h1 = packh_rn(acc[mt][nt][2], acc[mt][nt][3]);
                *(uint32_t*)&Chi[i0] = h0;
                *(uint32_t*)&Clo[i0] = packh_lo(acc[mt][nt][0], acc[mt][nt][1], h0);
                *(uint32_t*)&Chi[i1] = h1;
                *(uint32_t*)&Clo[i1] = packh_lo(acc[mt][nt][2], acc[mt][nt][3], h1);
            }
        }
    }
}

// ---------------------------------------------------------------------------
// LoRA-down split-K: part[s][M][32] = X[M, s-slice] @ A[s-slice, 32]
// ---------------------------------------------------------------------------
__global__ void __launch_bounds__(256) lora_down_partial(
    const float* __restrict__ X, const float* __restrict__ Amat,
    float* __restrict__ part, int M, int K)
{
    __shared__ __align__(16) float Xs[32][68];
    __shared__ __align__(16) float As2[64][36];

    const int tid = threadIdx.x;
    const int m0  = blockIdx.x * 32;
    const int s   = blockIdx.y;
    const int KS  = K >> 3;               // 256
    const int kb  = s * KS;
    const int n   = tid & 31;
    const int mq  = (tid >> 5) * 4;

    float acc[4] = {0.f, 0.f, 0.f, 0.f};

    for (int k0 = kb; k0 < kb + KS; k0 += 64) {
        __syncthreads();
        #pragma unroll
        for (int l = 0; l < 2; l++) {
            int idx = tid + l * 256;
            int m   = idx >> 4;
            int k4  = (idx & 15) << 2;
            *(float4*)&Xs[m][k4] =
                *(const float4*)&X[(size_t)(m0 + m) * K + k0 + k4];
        }
        #pragma unroll
        for (int l = 0; l < 2; l++) {
            int idx = tid + l * 256;
            int kk  = idx >> 3;
            int n4  = (idx & 7) << 2;
            *(float4*)&As2[kk][n4] =
                *(const float4*)&Amat[(size_t)(k0 + kk) * 32 + n4];
        }
        __syncthreads();
        #pragma unroll 16
        for (int kk = 0; kk < 64; kk++) {
            float a = As2[kk][n];
            acc[0] = fmaf(Xs[mq + 0][kk], a, acc[0]);
            acc[1] = fmaf(Xs[mq + 1][kk], a, acc[1]);
            acc[2] = fmaf(Xs[mq + 2][kk], a, acc[2]);
            acc[3] = fmaf(Xs[mq + 3][kk], a, acc[3]);
        }
    }
    float* dst = part + (size_t)s * M * 32;
    #pragma unroll
    for (int i = 0; i < 4; i++)
        dst[(size_t)(m0 + mq + i) * 32 + n] = acc[i];
}

__global__ void __launch_bounds__(256) lora_reduce(
    const float* __restrict__ part, __half* __restrict__ outT, int n)
{
    int i = blockIdx.x * 256 + threadIdx.x;
    if (i >= n) return;
    float sum = 0.f;
    #pragma unroll
    for (int p = 0; p < 8; p++) sum += part[(size_t)p * n + i];
    outT[i] = __float2half(sum);
}

// ---------------------------------------------------------------------------
// Tensor-core flash attention, fp16:
//   QK^T = qh*kh + ql*kh   (Q 2-term, K 1-term)
//   PV   = p*vh             (P 1-term, V 1-term)
// CTA: 256 threads, 8 warps, 128 q-rows.  Grid: (S/128, H, B).
// ---------------------------------------------------------------------------
#define AROWB 272
#define QH_OFF 0
#define QL_OFF (128 * AROWB)
#define KV_OFF (2 * 128 * AROWB)
#define KHO 0
#define VHO (64 * AROWB)
#define ST_B (2 * 64 * AROWB)
#define ATTN_SMEM (KV_OFF + 2 * ST_B)    // 139264

__global__ void __launch_bounds__(256, 1) attn_mma(
    const __half* __restrict__ qkvh, const __half* __restrict__ qkvl,
    const float* __restrict__ alibi, const float* __restrict__ pad,
    float* __restrict__ outf, uint16_t* __restrict__ outh,
    uint16_t* __restrict__ outl)
{
    extern __shared__ __align__(128) char smem[];
    const uint32_t sb = smem_u32(smem);
    const int tid = threadIdx.x, wid = tid >> 5, lane = tid & 31;
    const int g = lane >> 2, q = lane & 3, l7 = lane & 7;
    const int q0 = blockIdx.x * 128, h = blockIdx.y, b = blockIdx.z;

    const size_t tokbase = (size_t)(b * S_);

    // --- load Q (hi/lo) ---
    {
        const __half* bH = qkvh + (tokbase + q0) * 6144 + h * 128;
        const __half* bL = qkvl + (tokbase + q0) * 6144 + h * 128;
        #pragma unroll
        for (int j = 0; j < 8; j++) {
            int idx = tid + j * 256;
            int row = idx >> 4, seg = idx & 15;
            uint32_t off = (uint32_t)row * AROWB + seg * 16;
            cp16(sb + QH_OFF + off, bH + (size_t)row * 6144 + seg * 8);
            cp16(sb + QL_OFF + off, bL + (size_t)row * 6144 + seg * 8);
        }
    }
    auto loadKV = [&](int kt, int st) {
        const uint32_t base = sb + KV_OFF + (uint32_t)st * ST_B;
        const __half* kH = qkvh + (tokbase + kt * 64) * 6144 + D_ + h * 128;
        const __half* vH = kH + D_;
        #pragma unroll
        for (int j = 0; j < 4; j++) {
            int idx = tid + j * 256;
            int row = idx >> 4, seg = idx & 15;
            uint32_t off = (uint32_t)row * AROWB + seg * 16;
            size_t go = (size_t)row * 6144 + seg * 8;
            cp16(base + KHO + off, kH + go);
            cp16(base + VHO + off, vH + go);
        }
    };
    loadKV(0, 0); cp_commit();
    loadKV(1, 1); cp_commit();

    float o[16][4];
    #pragma unroll
    for (int i = 0; i < 16; i++)
        #pragma unroll
        for (int e = 0; e < 4; e++) o[i][e] = 0.f;
    float m0r = -1e30f, m1r = -1e30f, l0r = 0.f, l1r = 0.f;

    const float sscale = 0.08838834764831845f;   // 1/sqrt(128)

    const uint32_t qoff = (uint32_t)(wid * 16 + ((lane >> 3) & 1) * 8 + l7) * AROWB
                        + ((lane >> 4) & 1) * 16;
    const uint32_t koff = (uint32_t)(((lane >> 4) & 1) * 8 + l7) * AROWB
                        + ((lane >> 3) & 1) * 16;
    const uint32_t voff = (uint32_t)(((lane >> 3) & 1) * 8 + l7) * AROWB
                        + ((lane >> 4) & 1) * 16;

    const float* arow0 = alibi + ((size_t)h * S_ + (q0 + wid * 16 + g)) * S_;
    const float* arow1 = arow0 + 8 * S_;
    const float* prow  = pad + (size_t)b * S_;

    for (int kt = 0; kt < S_ / 64; kt++) {
        cp_wait1();
        __syncthreads();
        const uint32_t st = sb + KV_OFF + (uint32_t)(kt & 1) * ST_B;
        const int k0 = kt * 64;

        // ---- QK^T (fp16, 2-pass) ----
        float c[8][4];
        #pragma unroll
        for (int i = 0; i < 8; i++)
            #pragma unroll
            for (int e = 0; e < 4; e++) c[i][e] = 0.f;

        #pragma unroll
        for (int kc = 0; kc < 8; kc++) {
            uint32_t qh4[4], ql4[4];
            ldm4(qh4[0], qh4[1], qh4[2], qh4[3], sb + QH_OFF + qoff + kc * 32);
            ldm4(ql4[0], ql4[1], ql4[2], ql4[3], sb + QL_OFF + qoff + kc * 32);
            #pragma unroll
            for (int np = 0; np < 4; np++) {
                uint32_t kh[4];
                uint32_t ka = st + KHO + koff + (uint32_t)np * (16 * AROWB) + kc * 32;
                ldm4(kh[0], kh[1], kh[2], kh[3], ka);
                mma16h(c[2 * np],     qh4, &kh[0]);
                mma16h(c[2 * np + 1], qh4, &kh[2]);
                mma16h(c[2 * np],     ql4, &kh[0]);
                mma16h(c[2 * np + 1], ql4, &kh[2]);
            }
        }

        // ---- bias + online softmax ----
        #pragma unroll
        for (int nt = 0; nt < 8; nt++) {
            int col = k0 + nt * 8 + 2 * q;
            float2 a0 = *(const float2*)(arow0 + col);
            float2 a1 = *(const float2*)(arow1 + col);
            float2 pd = *(const float2*)(prow + col);
            c[nt][0] = fmaf(c[nt][0], sscale, a0.x + pd.x);
            c[nt][1] = fmaf(c[nt][1], sscale, a0.y + pd.y);
            c[nt][2] = fmaf(c[nt][2], sscale, a1.x + pd.x);
            c[nt][3] = fmaf(c[nt][3], sscale, a1.y + pd.y);
        }
        float mx0 = -1e30f, mx1 = -1e30f;
        #pragma unroll
        for (int nt = 0; nt < 8; nt++) {
            mx0 = fmaxf(mx0, fmaxf(c[nt][0], c[nt][1]));
            mx1 = fmaxf(mx1, fmaxf(c[nt][2], c[nt][3]));
        }
        mx0 = fmaxf(mx0, __shfl_xor_sync(0xffffffffu, mx0, 1));
        mx0 = fmaxf(mx0, __shfl_xor_sync(0xffffffffu, mx0, 2));
        mx1 = fmaxf(mx1, __shfl_xor_sync(0xffffffffu, mx1, 1));
        mx1 = fmaxf(mx1, __shfl_xor_sync(0xffffffffu, mx1, 2));
        float mn0 = fmaxf(m0r, mx0), mn1 = fmaxf(m1r, mx1);
        float cr0 = __expf(m0r - mn0), cr1 = __expf(m1r - mn1);
        m0r = mn0; m1r = mn1;
        float s0 = 0.f, s1 = 0.f;
        #pragma unroll
        for (int nt = 0; nt < 8; nt++) {
            c[nt][0] = __expf(c[nt][0] - mn0);
            c[nt][1] = __expf(c[nt][1] - mn0);
            c[nt][2] = __expf(c[nt][2] - mn1);
            c[nt][3] = __expf(c[nt][3] - mn1);
            s0 += c[nt][0] + c[nt][1];
            s1 += c[nt][2] + c[nt][3];
        }
        s0 += __shfl_xor_sync(0xffffffffu, s0, 1);
        s0 += __shfl_xor_sync(0xffffffffu, s0, 2);
        s1 += __shfl_xor_sync(0xffffffffu, s1, 1);
        s1 += __shfl_xor_sync(0xffffffffu, s1, 2);
        l0r = l0r * cr0 + s0;
        l1r = l1r * cr1 + s1;
        #pragma unroll
        for (int i = 0; i < 16; i++) {
            o[i][0] *= cr0; o[i][1] *= cr0;
            o[i][2] *= cr1; o[i][3] *= cr1;
        }

        // ---- PV (fp16, 1-pass) ----
        #pragma unroll
        for (int kc = 0; kc < 4; kc++) {
            uint32_t ph[4];
            ph[0] = packh_rn(c[2 * kc][0],     c[2 * kc][1]);
            ph[1] = packh_rn(c[2 * kc][2],     c[2 * kc][3]);
            ph[2] = packh_rn(c[2 * kc + 1][0], c[2 * kc + 1][1]);
            ph[3] = packh_rn(c[2 * kc + 1][2], c[2 * kc + 1][3]);
            uint32_t vrow = st + VHO + voff + (uint32_t)kc * (16 * AROWB);
            #pragma unroll
            for (int dg = 0; dg < 8; dg++) {
                uint32_t vh[4];
                ldm4t(vh[0], vh[1], vh[2], vh[3], vrow + dg * 32);
                mma16h(o[2 * dg],     ph, &vh[0]);
                mma16h(o[2 * dg + 1], ph, &vh[2]);
            }
        }

        __syncthreads();
        if (kt + 2 < S_ / 64) { loadKV(kt + 2, kt & 1); cp_commit(); }
        else cp_commit();
    }

    // ---- epilogue ----
    float inv0 = 1.0f / l0r, inv1 = 1.0f / l1r;
    size_t row0 = tokbase + q0 + wid * 16 + g;
    size_t row1 = row0 + 8;
    #pragma unroll
    for (int nt = 0; nt < 16; nt++) {
        int col = h * 128 + nt * 8 + 2 * q;
        float f0 = o[nt][0] * inv0, f1 = o[nt][1] * inv0;
        float f2 = o[nt][2] * inv1, f3 = o[nt][3] * inv1;
        *(float2*)&outf[row0 * D_ + col] = make_float2(f0, f1);
        *(float2*)&outf[row1 * D_ + col] = make_float2(f2, f3);
        uint32_t h0 = packh_rn(f0, f1);
        uint32_t h1 = packh_rn(f2, f3);
        *(uint32_t*)&outh[row0 * D_ + col] = h0;
        *(uint32_t*)&outl[row0 * D_ + col] = packh_lo(f0, f1, h0);
        *(uint32_t*)&outh[row1 * D_ + col] = h1;
        *(uint32_t*)&outl[row1 * D_ + col] = packh_lo(f2, f3, h1);
    }
}

// ---------------------------------------------------------------------------
// kernel_launch
// ---------------------------------------------------------------------------
extern "C" void kernel_launch(void* const* d_in, const int* in_sizes, int n_in,
                              void* d_out, int out_size)
{
    const float* x     = (const float*)d_in[0];
    const float* alibi = (const float*)d_in[1];
    const float* pad   = (const float*)d_in[2];
    const float* Wqkv  = (const float*)d_in[3];
    const float* Aqkv  = (const float*)d_in[4];
    const float* Bqkv  = (const float*)d_in[5];
    const float* Wout  = (const float*)d_in[6];
    const float* Aout  = (const float*)d_in[7];
    const float* Bout  = (const float*)d_in[8];
    float* out = (float*)d_out;

    float *attn_p, *tpart;
    __half *qkvh, *qkvl, *xh, *xl, *wqh, *woh, *ah, *al;
    __half *bqt, *bot, *t1h, *t2h;
    cudaGetSymbolAddress((void**)&attn_p, g_attn);
    cudaGetSymbolAddress((void**)&tpart, g_tpart);
    cudaGetSymbolAddress((void**)&qkvh, g_qkvh);
    cudaGetSymbolAddress((void**)&qkvl, g_qkvl);
    cudaGetSymbolAddress((void**)&xh,  g_xh);
    cudaGetSymbolAddress((void**)&xl,  g_xl);
    cudaGetSymbolAddress((void**)&wqh, g_wqh);
    cudaGetSymbolAddress((void**)&woh, g_woh);
    cudaGetSymbolAddress((void**)&ah,  g_ah);
    cudaGetSymbolAddress((void**)&al,  g_al);
    cudaGetSymbolAddress((void**)&bqt, g_bqt);
    cudaGetSymbolAddress((void**)&bot, g_bot);
    cudaGetSymbolAddress((void**)&t1h, g_t1h);
    cudaGetSymbolAddress((void**)&t2h, g_t2h);

    cudaFuncSetAttribute(tc_gemm_fp16,
                         cudaFuncAttributeMaxDynamicSharedMemorySize, TCG_SMEM);
    cudaFuncSetAttribute(attn_mma,
                         cudaFuncAttributeMaxDynamicSharedMemorySize, ATTN_SMEM);

    // pre-pass: x split (2-term), weights single fp16
    splith_kernel<<<(M_TOK * D_ / 4 + 255) / 256, 256>>>(
        (const float4*)x, (uint2*)xh, (uint2*)xl, M_TOK * D_ / 4);
    convh_kernel<<<(3 * D_ * D_ / 4 + 255) / 256, 256>>>(
        (const float4*)Wqkv, (uint2*)wqh, 3 * D_ * D_ / 4);
    convh_kernel<<<(D_ * D_ / 4 + 255) / 256, 256>>>(
        (const float4*)Wout, (uint2*)woh, D_ * D_ / 4);
    transpose_scale_kernel<<<(3 * D_ * R_ + 255) / 256, 256>>>(
        Bqkv, bqt, 3 * D_, LORA_SCALE);
    transpose_scale_kernel<<<(D_ * R_ + 255) / 256, 256>>>(
        Bout, bot, D_, LORA_SCALE);

    // t1 = x @ Aqkv  (split-K)
    lora_down_partial<<<dim3(M_TOK / 32, 8), 256>>>(x, Aqkv, tpart, M_TOK, D_);
    lora_reduce<<<(M_TOK * R_ + 255) / 256, 256>>>(tpart, t1h, M_TOK * R_);

    // qkv = x @ Wqkv^T + lora  -> fp16 hi/lo (2-pass fp16x2)
    {
        dim3 grid((3 * D_) / 128, M_TOK / 128);
        tc_gemm_fp16<<<grid, 256, TCG_SMEM>>>(xh, xl, wqh, t1h, bqt,
                                              nullptr, (uint16_t*)qkvh,
                                              (uint16_t*)qkvl,
                                              M_TOK, 3 * D_, D_, 2);
    }

    // attention (tensor-core fp16: QK 2-pass, PV 1-pass)
    {
        dim3 grid(S_ / 128, H_, B_);
        attn_mma<<<grid, 256, ATTN_SMEM>>>(qkvh, qkvl, alibi, pad,
                                           attn_p, (uint16_t*)ah, (uint16_t*)al);
    }

    // t2 = attn @ Aout  (split-K)
    lora_down_partial<<<dim3(M_TOK / 32, 8), 256>>>(attn_p, Aout, tpart, M_TOK, D_);
    lora_reduce<<<(M_TOK * R_ + 255) / 256, 256>>>(tpart, t2h, M_TOK * R_);

    // out = attn @ Wout^T + lora  -> fp32 (2-pass fp16x2)
    {
        dim3 grid(D_ / 128, M_TOK / 128);
        tc_gemm_fp16<<<grid, 256, TCG_SMEM>>>(ah, al, woh, t2h, bot,
                                              out, nullptr, nullptr,
                                              M_TOK, D_, D_, 0);
    }
}

// round 9
// speedup vs baseline: 1.5642x; 1.0886x over previous
#include <cuda_runtime.h>
#include <cuda_bf16.h>
#include <cuda_fp16.h>
#include <cstdint>

// Problem constants
#define B_   2
#define S_   2048
#define D_   2048
#define H_   16
#define HD_  128
#define R_   32
#define M_TOK (B_ * S_)              // 4096 tokens
#define LORA_SCALE (1.0f / 32.0f)

// ---------------------------------------------------------------------------
// Scratch (allocation-free rule: __device__ globals)
// ---------------------------------------------------------------------------
static __device__ float g_attn[M_TOK * D_];      // fp32 attention output

static __device__ __align__(16) __half g_qkvh[M_TOK * 3 * D_];
static __device__ __align__(16) __half g_qkvl[M_TOK * 3 * D_];
static __device__ __align__(16) __half g_xh[M_TOK * D_];
static __device__ __align__(16) __half g_wqh[3 * D_ * D_];
static __device__ __align__(16) __half g_woh[D_ * D_];
static __device__ __align__(16) __half g_ah[M_TOK * D_];
static __device__ __align__(16) __half g_al[M_TOK * D_];
static __device__ __align__(16) __half g_bqt[3 * D_ * R_];   // [6144][32]
static __device__ __align__(16) __half g_bot[D_ * R_];       // [2048][32]
static __device__ __align__(16) __half g_t1h[M_TOK * R_];
static __device__ __align__(16) __half g_t2h[M_TOK * R_];
static __device__ float g_tpart[8 * M_TOK * R_];             // split-K partials

// ---------------------------------------------------------------------------
// helpers
// ---------------------------------------------------------------------------
__device__ __forceinline__ uint32_t smem_u32(const void* p) {
    uint32_t a;
    asm("{ .reg .u64 t; cvta.to.shared.u64 t, %1; cvt.u32.u64 %0, t; }"
        : "=r"(a) : "l"(p));
    return a;
}
__device__ __forceinline__ void cp16(uint32_t dst, const void* src) {
    asm volatile("cp.async.cg.shared.global [%0], [%1], 16;"
                 :: "r"(dst), "l"(src) : "memory");
}
__device__ __forceinline__ void cp_commit() {
    asm volatile("cp.async.commit_group;" ::: "memory");
}
__device__ __forceinline__ void cp_wait1() {
    asm volatile("cp.async.wait_group 1;" ::: "memory");
}
__device__ __forceinline__ void ldm4(uint32_t& r0, uint32_t& r1,
                                     uint32_t& r2, uint32_t& r3, uint32_t addr) {
    asm volatile("ldmatrix.sync.aligned.m8n8.x4.shared.b16 {%0,%1,%2,%3}, [%4];"
                 : "=r"(r0), "=r"(r1), "=r"(r2), "=r"(r3) : "r"(addr));
}
__device__ __forceinline__ void ldm4t(uint32_t& r0, uint32_t& r1,
                                      uint32_t& r2, uint32_t& r3, uint32_t addr) {
    asm volatile("ldmatrix.sync.aligned.m8n8.x4.trans.shared.b16 {%0,%1,%2,%3}, [%4];"
                 : "=r"(r0), "=r"(r1), "=r"(r2), "=r"(r3) : "r"(addr));
}
__device__ __forceinline__ void mma16h(float* c, const uint32_t* a, const uint32_t* b) {
    asm volatile(
        "mma.sync.aligned.m16n8k16.row.col.f32.f16.f16.f32 "
        "{%0,%1,%2,%3}, {%4,%5,%6,%7}, {%8,%9}, {%0,%1,%2,%3};"
        : "+f"(c[0]), "+f"(c[1]), "+f"(c[2]), "+f"(c[3])
        : "r"(a[0]), "r"(a[1]), "r"(a[2]), "r"(a[3]), "r"(b[0]), "r"(b[1]));
}
// fp16 packs (RN hi, RN residual lo)
__device__ __forceinline__ uint32_t packh_rn(float x, float y) {
    __half2 t = __floats2half2_rn(x, y);
    return *(uint32_t*)&t;
}
__device__ __forceinline__ uint32_t packh_lo(float x, float y, uint32_t hibits) {
    __half2 h = *(__half2*)&hibits;
    float rx = x - __half2float(__low2half(h));
    float ry = y - __half2float(__high2half(h));
    __half2 t = __floats2half2_rn(rx, ry);
    return *(uint32_t*)&t;
}

// ---------------------------------------------------------------------------
// Pre-pass: fp32 -> fp16 RN (single term)
// ---------------------------------------------------------------------------
__global__ void __launch_bounds__(256) convh_kernel(
    const float4* __restrict__ src, uint2* __restrict__ dst, int n4)
{
    int i = blockIdx.x * 256 + threadIdx.x;
    if (i >= n4) return;
    float4 v = src[i];
    dst[i] = make_uint2(packh_rn(v.x, v.y), packh_rn(v.z, v.w));
}

// Pre-pass: Bq[32,N] -> out[N][32] fp16(RN), scaled
__global__ void __launch_bounds__(256) transpose_scale_kernel(
    const float* __restrict__ Bq, __half* __restrict__ out,
    int N, float scale)
{
    int idx = blockIdx.x * 256 + threadIdx.x;
    int k = idx & 31;
    int n = idx >> 5;
    if (n < N)
        out[(size_t)n * 32 + k] = __float2half(Bq[(size_t)k * N + n] * scale);
}

// ---------------------------------------------------------------------------
// fp16 fused GEMM:
//   C = (Ah[+Al]) @ Bh^T + T @ Bqt^T      (Al == nullptr -> 1-pass)
// outMode: 0 = fp32 Cf, 2 = fp16 hi/lo (RN + residual)
// smem/stage: 3 tile slots (Ah, Al, Bh), 128 rows x 48B each
// ---------------------------------------------------------------------------
#define OFF_AH 0
#define OFF_AL 6144
#define OFF_BH 12288
#define STAGE_B 18432
#define TCG_SMEM (3 * STAGE_B)      // 55296 bytes

__global__ void __launch_bounds__(256, 2) tc_gemm_fp16(
    const __half* __restrict__ Ah, const __half* __restrict__ Al,
    const __half* __restrict__ Bh,
    const __half* __restrict__ Tm, const __half* __restrict__ Bqt,
    float* __restrict__ Cf, uint16_t* __restrict__ Chi,
    uint16_t* __restrict__ Clo, int M, int N, int K, int outMode)
{
    extern __shared__ __align__(128) char smem[];
    const uint32_t sbase = smem_u32(smem);

    const int tid  = threadIdx.x;
    const int wid  = tid >> 5;
    const int lane = tid & 31;
    const int g    = lane >> 2;
    const int q    = lane & 3;
    const int warpM = (wid & 1) * 64;
    const int warpN = (wid >> 1) * 32;

    const int n0 = blockIdx.x * 128;
    const int m0 = blockIdx.y * 128;

    const int kc    = K >> 4;
    const int total = kc + 2;
    const bool twoA = (Al != nullptr);

    float acc[4][4][4];
    #pragma unroll
    for (int i = 0; i < 4; i++)
        #pragma unroll
        for (int j = 0; j < 4; j++)
            #pragma unroll
            for (int e = 0; e < 4; e++) acc[i][j][e] = 0.f;

    const int pr = tid >> 1;
    const int ps = tid & 1;
    auto issue = [&](int c, int s) {
        const uint32_t st = sbase + (uint32_t)s * STAGE_B;
        const uint32_t doff = (uint32_t)pr * 48u + (uint32_t)ps * 16u;
        if (c < kc) {
            size_t ao = (size_t)(m0 + pr) * K + c * 16 + ps * 8;
            size_t bo = (size_t)(n0 + pr) * K + c * 16 + ps * 8;
            cp16(st + OFF_AH + doff, Ah + ao);
            if (twoA) cp16(st + OFF_AL + doff, Al + ao);
            cp16(st + OFF_BH + doff, Bh + bo);
        } else {
            int kl = (c - kc) * 16 + ps * 8;
            cp16(st + OFF_AH + doff, Tm  + (size_t)(m0 + pr) * 32 + kl);
            cp16(st + OFF_BH + doff, Bqt + (size_t)(n0 + pr) * 32 + kl);
        }
        cp_commit();
    };

    issue(0, 0);
    issue(1, 1);

    const int mi = lane >> 3;
    const int l7 = lane & 7;

    for (int i = 0; i < total; i++) {
        cp_wait1();
        __syncthreads();
        if (i + 2 < total) issue(i + 2, (i + 2) % 3);
        else cp_commit();

        const uint32_t st = sbase + (uint32_t)(i % 3) * STAGE_B;
        const bool lora = (i >= kc);

        uint32_t bh[4][2];
        #pragma unroll
        for (int bg = 0; bg < 2; bg++) {
            uint32_t rowB = warpN + bg * 16 + ((mi >> 1) << 3) + l7;
            uint32_t addr = st + OFF_BH + rowB * 48u + (uint32_t)(mi & 1) * 16u;
            ldm4(bh[2 * bg][0], bh[2 * bg][1], bh[2 * bg + 1][0], bh[2 * bg + 1][1], addr);
        }
        #pragma unroll
        for (int mt = 0; mt < 4; mt++) {
            uint32_t rowA = warpM + mt * 16 + ((mi & 1) << 3) + l7;
            uint32_t addrA = st + OFF_AH + rowA * 48u + (uint32_t)(mi >> 1) * 16u;
            uint32_t ah[4], al[4];
            ldm4(ah[0], ah[1], ah[2], ah[3], addrA);
            if (twoA && !lora)
                ldm4(al[0], al[1], al[2], al[3], addrA + (OFF_AL - OFF_AH));
            #pragma unroll
            for (int nt = 0; nt < 4; nt++) {
                mma16h(acc[mt][nt], ah, bh[nt]);
                if (twoA && !lora)
                    mma16h(acc[mt][nt], al, bh[nt]);
            }
        }
    }

    // epilogue
    #pragma unroll
    for (int mt = 0; mt < 4; mt++) {
        int row = m0 + warpM + mt * 16 + g;
        #pragma unroll
        for (int nt = 0; nt < 4; nt++) {
            int col = n0 + warpN + nt * 8 + 2 * q;
            size_t i0 = (size_t)row * N + col;
            size_t i1 = (size_t)(row + 8) * N + col;
            if (outMode == 0) {
                *(float2*)&Cf[i0] = make_float2(acc[mt][nt][0], acc[mt][nt][1]);
                *(float2*)&Cf[i1] = make_float2(acc[mt][nt][2], acc[mt][nt][3]);
            } else {
                uint32_t h0 = packh_rn(acc[mt][nt][0], acc[mt][nt][1]);
                uint32_t h1 = packh_rn(acc[mt][nt][2], acc[mt][nt][3]);
                *(uint32_t*)&Chi[i0] = h0;
                *(uint32_t*)&Clo[i0] = packh_lo(acc[mt][nt][0], acc[mt][nt][1], h0);
                *(uint32_t*)&Chi[i1] = h1;
                *(uint32_t*)&Clo[i1] = packh_lo(acc[mt][nt][2], acc[mt][nt][3], h1);
            }
        }
    }
}

// ---------------------------------------------------------------------------
// LoRA-down split-K: part[s][M][32] = X[M, s-slice] @ A[s-slice, 32]
// ---------------------------------------------------------------------------
__global__ void __launch_bounds__(256) lora_down_partial(
    const float* __restrict__ X, const float* __restrict__ Amat,
    float* __restrict__ part, int M, int K)
{
    __shared__ __align__(16) float Xs[32][68];
    __shared__ __align__(16) float As2[64][36];

    const int tid = threadIdx.x;
    const int m0  = blockIdx.x * 32;
    const int s   = blockIdx.y;
    const int KS  = K >> 3;               // 256
    const int kb  = s * KS;
    const int n   = tid & 31;
    const int mq  = (tid >> 5) * 4;

    float acc[4] = {0.f, 0.f, 0.f, 0.f};

    for (int k0 = kb; k0 < kb + KS; k0 += 64) {
        __syncthreads();
        #pragma unroll
        for (int l = 0; l < 2; l++) {
            int idx = tid + l * 256;
            int m   = idx >> 4;
            int k4  = (idx & 15) << 2;
            *(float4*)&Xs[m][k4] =
                *(const float4*)&X[(size_t)(m0 + m) * K + k0 + k4];
        }
        #pragma unroll
        for (int l = 0; l < 2; l++) {
            int idx = tid + l * 256;
            int kk  = idx >> 3;
            int n4  = (idx & 7) << 2;
            *(float4*)&As2[kk][n4] =
                *(const float4*)&Amat[(size_t)(k0 + kk) * 32 + n4];
        }
        __syncthreads();
        #pragma unroll 16
        for (int kk = 0; kk < 64; kk++) {
            float a = As2[kk][n];
            acc[0] = fmaf(Xs[mq + 0][kk], a, acc[0]);
            acc[1] = fmaf(Xs[mq + 1][kk], a, acc[1]);
            acc[2] = fmaf(Xs[mq + 2][kk], a, acc[2]);
            acc[3] = fmaf(Xs[mq + 3][kk], a, acc[3]);
        }
    }
    float* dst = part + (size_t)s * M * 32;
    #pragma unroll
    for (int i = 0; i < 4; i++)
        dst[(size_t)(m0 + mq + i) * 32 + n] = acc[i];
}

__global__ void __launch_bounds__(256) lora_reduce(
    const float* __restrict__ part, __half* __restrict__ outT, int n)
{
    int i = blockIdx.x * 256 + threadIdx.x;
    if (i >= n) return;
    float sum = 0.f;
    #pragma unroll
    for (int p = 0; p < 8; p++) sum += part[(size_t)p * n + i];
    outT[i] = __float2half(sum);
}

// ---------------------------------------------------------------------------
// Tensor-core flash attention, fp16:
//   QK^T = qh*kh + ql*kh   (Q 2-term, K 1-term)
//   PV   = p*vh             (P 1-term, V 1-term)
// CTA: 256 threads, 8 warps, 128 q-rows.  Grid: (S/128, H, B).
// ---------------------------------------------------------------------------
#define AROWB 272
#define QH_OFF 0
#define QL_OFF (128 * AROWB)
#define KV_OFF (2 * 128 * AROWB)
#define KHO 0
#define VHO (64 * AROWB)
#define ST_B (2 * 64 * AROWB)
#define ATTN_SMEM (KV_OFF + 2 * ST_B)    // 139264

__global__ void __launch_bounds__(256, 1) attn_mma(
    const __half* __restrict__ qkvh, const __half* __restrict__ qkvl,
    const float* __restrict__ alibi, const float* __restrict__ pad,
    float* __restrict__ outf, uint16_t* __restrict__ outh,
    uint16_t* __restrict__ outl)
{
    extern __shared__ __align__(128) char smem[];
    const uint32_t sb = smem_u32(smem);
    const int tid = threadIdx.x, wid = tid >> 5, lane = tid & 31;
    const int g = lane >> 2, q = lane & 3, l7 = lane & 7;
    const int q0 = blockIdx.x * 128, h = blockIdx.y, b = blockIdx.z;

    const size_t tokbase = (size_t)(b * S_);

    // --- load Q (hi/lo) ---
    {
        const __half* bH = qkvh + (tokbase + q0) * 6144 + h * 128;
        const __half* bL = qkvl + (tokbase + q0) * 6144 + h * 128;
        #pragma unroll
        for (int j = 0; j < 8; j++) {
            int idx = tid + j * 256;
            int row = idx >> 4, seg = idx & 15;
            uint32_t off = (uint32_t)row * AROWB + seg * 16;
            cp16(sb + QH_OFF + off, bH + (size_t)row * 6144 + seg * 8);
            cp16(sb + QL_OFF + off, bL + (size_t)row * 6144 + seg * 8);
        }
    }
    auto loadKV = [&](int kt, int st) {
        const uint32_t base = sb + KV_OFF + (uint32_t)st * ST_B;
        const __half* kH = qkvh + (tokbase + kt * 64) * 6144 + D_ + h * 128;
        const __half* vH = kH + D_;
        #pragma unroll
        for (int j = 0; j < 4; j++) {
            int idx = tid + j * 256;
            int row = idx >> 4, seg = idx & 15;
            uint32_t off = (uint32_t)row * AROWB + seg * 16;
            size_t go = (size_t)row * 6144 + seg * 8;
            cp16(base + KHO + off, kH + go);
            cp16(base + VHO + off, vH + go);
        }
    };
    loadKV(0, 0); cp_commit();
    loadKV(1, 1); cp_commit();

    float o[16][4];
    #pragma unroll
    for (int i = 0; i < 16; i++)
        #pragma unroll
        for (int e = 0; e < 4; e++) o[i][e] = 0.f;
    float m0r = -1e30f, m1r = -1e30f, l0r = 0.f, l1r = 0.f;

    const float sscale = 0.08838834764831845f;   // 1/sqrt(128)

    const uint32_t qoff = (uint32_t)(wid * 16 + ((lane >> 3) & 1) * 8 + l7) * AROWB
                        + ((lane >> 4) & 1) * 16;
    const uint32_t koff = (uint32_t)(((lane >> 4) & 1) * 8 + l7) * AROWB
                        + ((lane >> 3) & 1) * 16;
    const uint32_t voff = (uint32_t)(((lane >> 3) & 1) * 8 + l7) * AROWB
                        + ((lane >> 4) & 1) * 16;

    const float* arow0 = alibi + ((size_t)h * S_ + (q0 + wid * 16 + g)) * S_;
    const float* arow1 = arow0 + 8 * S_;
    const float* prow  = pad + (size_t)b * S_;

    for (int kt = 0; kt < S_ / 64; kt++) {
        cp_wait1();
        __syncthreads();
        const uint32_t st = sb + KV_OFF + (uint32_t)(kt & 1) * ST_B;
        const int k0 = kt * 64;

        // ---- QK^T (fp16, 2-pass) ----
        float c[8][4];
        #pragma unroll
        for (int i = 0; i < 8; i++)
            #pragma unroll
            for (int e = 0; e < 4; e++) c[i][e] = 0.f;

        #pragma unroll
        for (int kc = 0; kc < 8; kc++) {
            uint32_t qh4[4], ql4[4];
            ldm4(qh4[0], qh4[1], qh4[2], qh4[3], sb + QH_OFF + qoff + kc * 32);
            ldm4(ql4[0], ql4[1], ql4[2], ql4[3], sb + QL_OFF + qoff + kc * 32);
            #pragma unroll
            for (int np = 0; np < 4; np++) {
                uint32_t kh[4];
                uint32_t ka = st + KHO + koff + (uint32_t)np * (16 * AROWB) + kc * 32;
                ldm4(kh[0], kh[1], kh[2], kh[3], ka);
                mma16h(c[2 * np],     qh4, &kh[0]);
                mma16h(c[2 * np + 1], qh4, &kh[2]);
                mma16h(c[2 * np],     ql4, &kh[0]);
                mma16h(c[2 * np + 1], ql4, &kh[2]);
            }
        }

        // ---- bias + online softmax ----
        #pragma unroll
        for (int nt = 0; nt < 8; nt++) {
            int col = k0 + nt * 8 + 2 * q;
            float2 a0 = *(const float2*)(arow0 + col);
            float2 a1 = *(const float2*)(arow1 + col);
            float2 pd = *(const float2*)(prow + col);
            c[nt][0] = fmaf(c[nt][0], sscale, a0.x + pd.x);
            c[nt][1] = fmaf(c[nt][1], sscale, a0.y + pd.y);
            c[nt][2] = fmaf(c[nt][2], sscale, a1.x + pd.x);
            c[nt][3] = fmaf(c[nt][3], sscale, a1.y + pd.y);
        }
        float mx0 = -1e30f, mx1 = -1e30f;
        #pragma unroll
        for (int nt = 0; nt < 8; nt++) {
            mx0 = fmaxf(mx0, fmaxf(c[nt][0], c[nt][1]));
            mx1 = fmaxf(mx1, fmaxf(c[nt][2], c[nt][3]));
        }
        mx0 = fmaxf(mx0, __shfl_xor_sync(0xffffffffu, mx0, 1));
        mx0 = fmaxf(mx0, __shfl_xor_sync(0xffffffffu, mx0, 2));
        mx1 = fmaxf(mx1, __shfl_xor_sync(0xffffffffu, mx1, 1));
        mx1 = fmaxf(mx1, __shfl_xor_sync(0xffffffffu, mx1, 2));
        float mn0 = fmaxf(m0r, mx0), mn1 = fmaxf(m1r, mx1);
        float cr0 = __expf(m0r - mn0), cr1 = __expf(m1r - mn1);
        m0r = mn0; m1r = mn1;
        float s0 = 0.f, s1 = 0.f;
        #pragma unroll
        for (int nt = 0; nt < 8; nt++) {
            c[nt][0] = __expf(c[nt][0] - mn0);
            c[nt][1] = __expf(c[nt][1] - mn0);
            c[nt][2] = __expf(c[nt][2] - mn1);
            c[nt][3] = __expf(c[nt][3] - mn1);
            s0 += c[nt][0] + c[nt][1];
            s1 += c[nt][2] + c[nt][3];
        }
        s0 += __shfl_xor_sync(0xffffffffu, s0, 1);
        s0 += __shfl_xor_sync(0xffffffffu, s0, 2);
        s1 += __shfl_xor_sync(0xffffffffu, s1, 1);
        s1 += __shfl_xor_sync(0xffffffffu, s1, 2);
        l0r = l0r * cr0 + s0;
        l1r = l1r * cr1 + s1;
        #pragma unroll
        for (int i = 0; i < 16; i++) {
            o[i][0] *= cr0; o[i][1] *= cr0;
            o[i][2] *= cr1; o[i][3] *= cr1;
        }

        // ---- PV (fp16, 1-pass) ----
        #pragma unroll
        for (int kc = 0; kc < 4; kc++) {
            uint32_t ph[4];
            ph[0] = packh_rn(c[2 * kc][0],     c[2 * kc][1]);
            ph[1] = packh_rn(c[2 * kc][2],     c[2 * kc][3]);
            ph[2] = packh_rn(c[2 * kc + 1][0], c[2 * kc + 1][1]);
            ph[3] = packh_rn(c[2 * kc + 1][2], c[2 * kc + 1][3]);
            uint32_t vrow = st + VHO + voff + (uint32_t)kc * (16 * AROWB);
            #pragma unroll
            for (int dg = 0; dg < 8; dg++) {
                uint32_t vh[4];
                ldm4t(vh[0], vh[1], vh[2], vh[3], vrow + dg * 32);
                mma16h(o[2 * dg],     ph, &vh[0]);
                mma16h(o[2 * dg + 1], ph, &vh[2]);
            }
        }

        __syncthreads();
        if (kt + 2 < S_ / 64) { loadKV(kt + 2, kt & 1); cp_commit(); }
        else cp_commit();
    }

    // ---- epilogue ----
    float inv0 = 1.0f / l0r, inv1 = 1.0f / l1r;
    size_t row0 = tokbase + q0 + wid * 16 + g;
    size_t row1 = row0 + 8;
    #pragma unroll
    for (int nt = 0; nt < 16; nt++) {
        int col = h * 128 + nt * 8 + 2 * q;
        float f0 = o[nt][0] * inv0, f1 = o[nt][1] * inv0;
        float f2 = o[nt][2] * inv1, f3 = o[nt][3] * inv1;
        *(float2*)&outf[row0 * D_ + col] = make_float2(f0, f1);
        *(float2*)&outf[row1 * D_ + col] = make_float2(f2, f3);
        uint32_t h0 = packh_rn(f0, f1);
        uint32_t h1 = packh_rn(f2, f3);
        *(uint32_t*)&outh[row0 * D_ + col] = h0;
        *(uint32_t*)&outl[row0 * D_ + col] = packh_lo(f0, f1, h0);
        *(uint32_t*)&outh[row1 * D_ + col] = h1;
        *(uint32_t*)&outl[row1 * D_ + col] = packh_lo(f2, f3, h1);
    }
}

// ---------------------------------------------------------------------------
// kernel_launch
// ---------------------------------------------------------------------------
extern "C" void kernel_launch(void* const* d_in, const int* in_sizes, int n_in,
                              void* d_out, int out_size)
{
    const float* x     = (const float*)d_in[0];
    const float* alibi = (const float*)d_in[1];
    const float* pad   = (const float*)d_in[2];
    const float* Wqkv  = (const float*)d_in[3];
    const float* Aqkv  = (const float*)d_in[4];
    const float* Bqkv  = (const float*)d_in[5];
    const float* Wout  = (const float*)d_in[6];
    const float* Aout  = (const float*)d_in[7];
    const float* Bout  = (const float*)d_in[8];
    float* out = (float*)d_out;

    float *attn_p, *tpart;
    __half *qkvh, *qkvl, *xh, *wqh, *woh, *ah, *al;
    __half *bqt, *bot, *t1h, *t2h;
    cudaGetSymbolAddress((void**)&attn_p, g_attn);
    cudaGetSymbolAddress((void**)&tpart, g_tpart);
    cudaGetSymbolAddress((void**)&qkvh, g_qkvh);
    cudaGetSymbolAddress((void**)&qkvl, g_qkvl);
    cudaGetSymbolAddress((void**)&xh,  g_xh);
    cudaGetSymbolAddress((void**)&wqh, g_wqh);
    cudaGetSymbolAddress((void**)&woh, g_woh);
    cudaGetSymbolAddress((void**)&ah,  g_ah);
    cudaGetSymbolAddress((void**)&al,  g_al);
    cudaGetSymbolAddress((void**)&bqt, g_bqt);
    cudaGetSymbolAddress((void**)&bot, g_bot);
    cudaGetSymbolAddress((void**)&t1h, g_t1h);
    cudaGetSymbolAddress((void**)&t2h, g_t2h);

    cudaFuncSetAttribute(tc_gemm_fp16,
                         cudaFuncAttributeMaxDynamicSharedMemorySize, TCG_SMEM);
    cudaFuncSetAttribute(attn_mma,
                         cudaFuncAttributeMaxDynamicSharedMemorySize, ATTN_SMEM);

    // pre-pass: x and weights -> single fp16
    convh_kernel<<<(M_TOK * D_ / 4 + 255) / 256, 256>>>(
        (const float4*)x, (uint2*)xh, M_TOK * D_ / 4);
    convh_kernel<<<(3 * D_ * D_ / 4 + 255) / 256, 256>>>(
        (const float4*)Wqkv, (uint2*)wqh, 3 * D_ * D_ / 4);
    convh_kernel<<<(D_ * D_ / 4 + 255) / 256, 256>>>(
        (const float4*)Wout, (uint2*)woh, D_ * D_ / 4);
    transpose_scale_kernel<<<(3 * D_ * R_ + 255) / 256, 256>>>(
        Bqkv, bqt, 3 * D_, LORA_SCALE);
    transpose_scale_kernel<<<(D_ * R_ + 255) / 256, 256>>>(
        Bout, bot, D_, LORA_SCALE);

    // t1 = x @ Aqkv  (split-K, fp32 inputs)
    lora_down_partial<<<dim3(M_TOK / 32, 8), 256>>>(x, Aqkv, tpart, M_TOK, D_);
    lora_reduce<<<(M_TOK * R_ + 255) / 256, 256>>>(tpart, t1h, M_TOK * R_);

    // qkv = x @ Wqkv^T + lora  -> fp16 hi/lo   (1-pass fp16)
    {
        dim3 grid((3 * D_) / 128, M_TOK / 128);
        tc_gemm_fp16<<<grid, 256, TCG_SMEM>>>(xh, nullptr, wqh, t1h, bqt,
                                              nullptr, (uint16_t*)qkvh,
                                              (uint16_t*)qkvl,
                                              M_TOK, 3 * D_, D_, 2);
    }

    // attention (tensor-core fp16: QK 2-pass, PV 1-pass)
    {
        dim3 grid(S_ / 128, H_, B_);
        attn_mma<<<grid, 256, ATTN_SMEM>>>(qkvh, qkvl, alibi, pad,
                                           attn_p, (uint16_t*)ah, (uint16_t*)al);
    }

    // t2 = attn @ Aout  (split-K)
    lora_down_partial<<<dim3(M_TOK / 32, 8), 256>>>(attn_p, Aout, tpart, M_TOK, D_);
    lora_reduce<<<(M_TOK * R_ + 255) / 256, 256>>>(tpart, t2h, M_TOK * R_);

    // out = attn @ Wout^T + lora  -> fp32 (2-pass: attn hi/lo)
    {
        dim3 grid(D_ / 128, M_TOK / 128);
        tc_gemm_fp16<<<grid, 256, TCG_SMEM>>>(ah, al, woh, t2h, bot,
                                              out, nullptr, nullptr,
                                              M_TOK, D_, D_, 0);
    }
}

// round 10
// speedup vs baseline: 2.1918x; 1.4012x over previous
#include <cuda_runtime.h>
#include <cuda_fp16.h>
#include <cstdint>

// Problem constants
#define B_   2
#define S_   2048
#define D_   2048
#define H_   16
#define HD_  128
#define R_   32
#define M_TOK (B_ * S_)              // 4096 tokens
#define LORA_SCALE (1.0f / 32.0f)

// ---------------------------------------------------------------------------
// Scratch (allocation-free rule: __device__ globals)
// ---------------------------------------------------------------------------
static __device__ __align__(16) __half g_qkvh[M_TOK * 3 * D_];
static __device__ __align__(16) __half g_xh[M_TOK * D_];
static __device__ __align__(16) __half g_wqh[3 * D_ * D_];
static __device__ __align__(16) __half g_woh[D_ * D_];
static __device__ __align__(16) __half g_ah[M_TOK * D_];
static __device__ __align__(16) __half g_bqt[3 * D_ * R_];   // [6144][32]
static __device__ __align__(16) __half g_bot[D_ * R_];       // [2048][32]
static __device__ __align__(16) __half g_t1h[M_TOK * R_];
static __device__ __align__(16) __half g_t2h[M_TOK * R_];
static __device__ float g_tpart[8 * M_TOK * R_];             // split-K partials

// ---------------------------------------------------------------------------
// helpers
// ---------------------------------------------------------------------------
__device__ __forceinline__ uint32_t smem_u32(const void* p) {
    uint32_t a;
    asm("{ .reg .u64 t; cvta.to.shared.u64 t, %1; cvt.u32.u64 %0, t; }"
        : "=r"(a) : "l"(p));
    return a;
}
__device__ __forceinline__ void cp16(uint32_t dst, const void* src) {
    asm volatile("cp.async.cg.shared.global [%0], [%1], 16;"
                 :: "r"(dst), "l"(src) : "memory");
}
__device__ __forceinline__ void cp_commit() {
    asm volatile("cp.async.commit_group;" ::: "memory");
}
__device__ __forceinline__ void cp_wait1() {
    asm volatile("cp.async.wait_group 1;" ::: "memory");
}
__device__ __forceinline__ void ldm4(uint32_t& r0, uint32_t& r1,
                                     uint32_t& r2, uint32_t& r3, uint32_t addr) {
    asm volatile("ldmatrix.sync.aligned.m8n8.x4.shared.b16 {%0,%1,%2,%3}, [%4];"
                 : "=r"(r0), "=r"(r1), "=r"(r2), "=r"(r3) : "r"(addr));
}
__device__ __forceinline__ void ldm4t(uint32_t& r0, uint32_t& r1,
                                      uint32_t& r2, uint32_t& r3, uint32_t addr) {
    asm volatile("ldmatrix.sync.aligned.m8n8.x4.trans.shared.b16 {%0,%1,%2,%3}, [%4];"
                 : "=r"(r0), "=r"(r1), "=r"(r2), "=r"(r3) : "r"(addr));
}
__device__ __forceinline__ void mma16h(float* c, const uint32_t* a, const uint32_t* b) {
    asm volatile(
        "mma.sync.aligned.m16n8k16.row.col.f32.f16.f16.f32 "
        "{%0,%1,%2,%3}, {%4,%5,%6,%7}, {%8,%9}, {%0,%1,%2,%3};"
        : "+f"(c[0]), "+f"(c[1]), "+f"(c[2]), "+f"(c[3])
        : "r"(a[0]), "r"(a[1]), "r"(a[2]), "r"(a[3]), "r"(b[0]), "r"(b[1]));
}
__device__ __forceinline__ uint32_t packh_rn(float x, float y) {
    __half2 t = __floats2half2_rn(x, y);
    return *(uint32_t*)&t;
}

// ---------------------------------------------------------------------------
// Pre-pass: fp32 -> fp16 RN (single term)
// ---------------------------------------------------------------------------
__global__ void __launch_bounds__(256) convh_kernel(
    const float4* __restrict__ src, uint2* __restrict__ dst, int n4)
{
    int i = blockIdx.x * 256 + threadIdx.x;
    if (i >= n4) return;
    float4 v = src[i];
    dst[i] = make_uint2(packh_rn(v.x, v.y), packh_rn(v.z, v.w));
}

// Pre-pass: Bq[32,N] -> out[N][32] fp16(RN), scaled
__global__ void __launch_bounds__(256) transpose_scale_kernel(
    const float* __restrict__ Bq, __half* __restrict__ out,
    int N, float scale)
{
    int idx = blockIdx.x * 256 + threadIdx.x;
    int k = idx & 31;
    int n = idx >> 5;
    if (n < N)
        out[(size_t)n * 32 + k] = __float2half(Bq[(size_t)k * N + n] * scale);
}

// ---------------------------------------------------------------------------
// fp16 fused GEMM (1-pass):
//   C = Ah @ Bh^T + T @ Bqt^T
// outMode: 0 = fp32 Cf, 1 = fp16 (RN) Chi
// smem/stage: 2 tiles (Ah, Bh), 128 rows x 48B each
// ---------------------------------------------------------------------------
#define OFF_AH 0
#define OFF_BH 6144
#define STAGE_B 12288
#define TCG_SMEM (3 * STAGE_B)      // 36864 bytes

__global__ void __launch_bounds__(256, 2) tc_gemm_fp16(
    const __half* __restrict__ Ah, const __half* __restrict__ Bh,
    const __half* __restrict__ Tm, const __half* __restrict__ Bqt,
    float* __restrict__ Cf, uint16_t* __restrict__ Chi,
    int M, int N, int K, int outMode)
{
    extern __shared__ __align__(128) char smem[];
    const uint32_t sbase = smem_u32(smem);

    const int tid  = threadIdx.x;
    const int wid  = tid >> 5;
    const int lane = tid & 31;
    const int g    = lane >> 2;
    const int q    = lane & 3;
    const int warpM = (wid & 1) * 64;
    const int warpN = (wid >> 1) * 32;

    const int n0 = blockIdx.x * 128;
    const int m0 = blockIdx.y * 128;

    const int kc    = K >> 4;
    const int total = kc + 2;

    float acc[4][4][4];
    #pragma unroll
    for (int i = 0; i < 4; i++)
        #pragma unroll
        for (int j = 0; j < 4; j++)
            #pragma unroll
            for (int e = 0; e < 4; e++) acc[i][j][e] = 0.f;

    const int pr = tid >> 1;
    const int ps = tid & 1;
    auto issue = [&](int c, int s) {
        const uint32_t st = sbase + (uint32_t)s * STAGE_B;
        const uint32_t doff = (uint32_t)pr * 48u + (uint32_t)ps * 16u;
        if (c < kc) {
            size_t ao = (size_t)(m0 + pr) * K + c * 16 + ps * 8;
            size_t bo = (size_t)(n0 + pr) * K + c * 16 + ps * 8;
            cp16(st + OFF_AH + doff, Ah + ao);
            cp16(st + OFF_BH + doff, Bh + bo);
        } else {
            int kl = (c - kc) * 16 + ps * 8;
            cp16(st + OFF_AH + doff, Tm  + (size_t)(m0 + pr) * 32 + kl);
            cp16(st + OFF_BH + doff, Bqt + (size_t)(n0 + pr) * 32 + kl);
        }
        cp_commit();
    };

    issue(0, 0);
    issue(1, 1);

    const int mi = lane >> 3;
    const int l7 = lane & 7;

    for (int i = 0; i < total; i++) {
        cp_wait1();
        __syncthreads();
        if (i + 2 < total) issue(i + 2, (i + 2) % 3);
        else cp_commit();

        const uint32_t st = sbase + (uint32_t)(i % 3) * STAGE_B;

        uint32_t bh[4][2];
        #pragma unroll
        for (int bg = 0; bg < 2; bg++) {
            uint32_t rowB = warpN + bg * 16 + ((mi >> 1) << 3) + l7;
            uint32_t addr = st + OFF_BH + rowB * 48u + (uint32_t)(mi & 1) * 16u;
            ldm4(bh[2 * bg][0], bh[2 * bg][1], bh[2 * bg + 1][0], bh[2 * bg + 1][1], addr);
        }
        #pragma unroll
        for (int mt = 0; mt < 4; mt++) {
            uint32_t rowA = warpM + mt * 16 + ((mi & 1) << 3) + l7;
            uint32_t addrA = st + OFF_AH + rowA * 48u + (uint32_t)(mi >> 1) * 16u;
            uint32_t ah[4];
            ldm4(ah[0], ah[1], ah[2], ah[3], addrA);
            #pragma unroll
            for (int nt = 0; nt < 4; nt++)
                mma16h(acc[mt][nt], ah, bh[nt]);
        }
    }

    // epilogue
    #pragma unroll
    for (int mt = 0; mt < 4; mt++) {
        int row = m0 + warpM + mt * 16 + g;
        #pragma unroll
        for (int nt = 0; nt < 4; nt++) {
            int col = n0 + warpN + nt * 8 + 2 * q;
            size_t i0 = (size_t)row * N + col;
            size_t i1 = (size_t)(row + 8) * N + col;
            if (outMode == 0) {
                *(float2*)&Cf[i0] = make_float2(acc[mt][nt][0], acc[mt][nt][1]);
                *(float2*)&Cf[i1] = make_float2(acc[mt][nt][2], acc[mt][nt][3]);
            } else {
                *(uint32_t*)&Chi[i0] = packh_rn(acc[mt][nt][0], acc[mt][nt][1]);
                *(uint32_t*)&Chi[i1] = packh_rn(acc[mt][nt][2], acc[mt][nt][3]);
            }
        }
    }
}

// ---------------------------------------------------------------------------
// LoRA-down split-K (fp16 X): part[s][M][32] = X[M, s-slice] @ A[s-slice, 32]
// ---------------------------------------------------------------------------
__global__ void __launch_bounds__(256) lora_down_partial_h(
    const __half* __restrict__ X, const float* __restrict__ Amat,
    float* __restrict__ part, int M, int K)
{
    __shared__ __align__(16) float Xs[32][68];
    __shared__ __align__(16) float As2[64][36];

    const int tid = threadIdx.x;
    const int m0  = blockIdx.x * 32;
    const int s   = blockIdx.y;
    const int KS  = K >> 3;               // 256
    const int kb  = s * KS;
    const int n   = tid & 31;
    const int mq  = (tid >> 5) * 4;

    float acc[4] = {0.f, 0.f, 0.f, 0.f};

    for (int k0 = kb; k0 < kb + KS; k0 += 64) {
        __syncthreads();
        // X tile 32x64 fp16: 256 threads x 8 halves (uint4)
        {
            int m  = tid >> 3;
            int k8 = (tid & 7) << 3;
            uint4 v = *(const uint4*)&X[(size_t)(m0 + m) * K + k0 + k8];
            const __half2* hp = (const __half2*)&v;
            #pragma unroll
            for (int e = 0; e < 4; e++) {
                float2 f = __half22float2(hp[e]);
                Xs[m][k8 + 2 * e]     = f.x;
                Xs[m][k8 + 2 * e + 1] = f.y;
            }
        }
        #pragma unroll
        for (int l = 0; l < 2; l++) {
            int idx = tid + l * 256;
            int kk  = idx >> 3;
            int n4  = (idx & 7) << 2;
            *(float4*)&As2[kk][n4] =
                *(const float4*)&Amat[(size_t)(k0 + kk) * 32 + n4];
        }
        __syncthreads();
        #pragma unroll 16
        for (int kk = 0; kk < 64; kk++) {
            float a = As2[kk][n];
            acc[0] = fmaf(Xs[mq + 0][kk], a, acc[0]);
            acc[1] = fmaf(Xs[mq + 1][kk], a, acc[1]);
            acc[2] = fmaf(Xs[mq + 2][kk], a, acc[2]);
            acc[3] = fmaf(Xs[mq + 3][kk], a, acc[3]);
        }
    }
    float* dst = part + (size_t)s * M * 32;
    #pragma unroll
    for (int i = 0; i < 4; i++)
        dst[(size_t)(m0 + mq + i) * 32 + n] = acc[i];
}

__global__ void __launch_bounds__(256) lora_reduce(
    const float* __restrict__ part, __half* __restrict__ outT, int n)
{
    int i = blockIdx.x * 256 + threadIdx.x;
    if (i >= n) return;
    float sum = 0.f;
    #pragma unroll
    for (int p = 0; p < 8; p++) sum += part[(size_t)p * n + i];
    outT[i] = __float2half(sum);
}

// ---------------------------------------------------------------------------
// Tensor-core flash attention, fp16 1-pass both stages:
//   QK^T = qh*kh ; PV = p*vh
// CTA: 256 threads, 8 warps, 128 q-rows.  Grid: (S/128, H, B).
// Output: fp16 `outh` only (consumed by lora-down + out GEMM).
// ---------------------------------------------------------------------------
#define AROWB 272
#define QH_OFF 0
#define KV_OFF (128 * AROWB)
#define KHO 0
#define VHO (64 * AROWB)
#define ST_B (2 * 64 * AROWB)
#define ATTN_SMEM (KV_OFF + 2 * ST_B)    // 104448

__global__ void __launch_bounds__(256, 1) attn_mma(
    const __half* __restrict__ qkvh,
    const float* __restrict__ alibi, const float* __restrict__ pad,
    uint16_t* __restrict__ outh)
{
    extern __shared__ __align__(128) char smem[];
    const uint32_t sb = smem_u32(smem);
    const int tid = threadIdx.x, wid = tid >> 5, lane = tid & 31;
    const int g = lane >> 2, q = lane & 3, l7 = lane & 7;
    const int q0 = blockIdx.x * 128, h = blockIdx.y, b = blockIdx.z;

    const size_t tokbase = (size_t)(b * S_);

    // --- load Q (hi only) ---
    {
        const __half* bH = qkvh + (tokbase + q0) * 6144 + h * 128;
        #pragma unroll
        for (int j = 0; j < 8; j++) {
            int idx = tid + j * 256;
            int row = idx >> 4, seg = idx & 15;
            uint32_t off = (uint32_t)row * AROWB + seg * 16;
            cp16(sb + QH_OFF + off, bH + (size_t)row * 6144 + seg * 8);
        }
    }
    auto loadKV = [&](int kt, int st) {
        const uint32_t base = sb + KV_OFF + (uint32_t)st * ST_B;
        const __half* kH = qkvh + (tokbase + kt * 64) * 6144 + D_ + h * 128;
        const __half* vH = kH + D_;
        #pragma unroll
        for (int j = 0; j < 4; j++) {
            int idx = tid + j * 256;
            int row = idx >> 4, seg = idx & 15;
            uint32_t off = (uint32_t)row * AROWB + seg * 16;
            size_t go = (size_t)row * 6144 + seg * 8;
            cp16(base + KHO + off, kH + go);
            cp16(base + VHO + off, vH + go);
        }
    };
    loadKV(0, 0); cp_commit();
    loadKV(1, 1); cp_commit();

    float o[16][4];
    #pragma unroll
    for (int i = 0; i < 16; i++)
        #pragma unroll
        for (int e = 0; e < 4; e++) o[i][e] = 0.f;
    float m0r = -1e30f, m1r = -1e30f, l0r = 0.f, l1r = 0.f;

    const float sscale = 0.08838834764831845f;   // 1/sqrt(128)

    const uint32_t qoff = (uint32_t)(wid * 16 + ((lane >> 3) & 1) * 8 + l7) * AROWB
                        + ((lane >> 4) & 1) * 16;
    const uint32_t koff = (uint32_t)(((lane >> 4) & 1) * 8 + l7) * AROWB
                        + ((lane >> 3) & 1) * 16;
    const uint32_t voff = (uint32_t)(((lane >> 3) & 1) * 8 + l7) * AROWB
                        + ((lane >> 4) & 1) * 16;

    const float* arow0 = alibi + ((size_t)h * S_ + (q0 + wid * 16 + g)) * S_;
    const float* arow1 = arow0 + 8 * S_;
    const float* prow  = pad + (size_t)b * S_;

    for (int kt = 0; kt < S_ / 64; kt++) {
        cp_wait1();
        __syncthreads();
        const uint32_t st = sb + KV_OFF + (uint32_t)(kt & 1) * ST_B;
        const int k0 = kt * 64;

        // ---- QK^T (fp16, 1-pass) ----
        float c[8][4];
        #pragma unroll
        for (int i = 0; i < 8; i++)
            #pragma unroll
            for (int e = 0; e < 4; e++) c[i][e] = 0.f;

        #pragma unroll
        for (int kc = 0; kc < 8; kc++) {
            uint32_t qh4[4];
            ldm4(qh4[0], qh4[1], qh4[2], qh4[3], sb + QH_OFF + qoff + kc * 32);
            #pragma unroll
            for (int np = 0; np < 4; np++) {
                uint32_t kh[4];
                uint32_t ka = st + KHO + koff + (uint32_t)np * (16 * AROWB) + kc * 32;
                ldm4(kh[0], kh[1], kh[2], kh[3], ka);
                mma16h(c[2 * np],     qh4, &kh[0]);
                mma16h(c[2 * np + 1], qh4, &kh[2]);
            }
        }

        // ---- bias + online softmax ----
        #pragma unroll
        for (int nt = 0; nt < 8; nt++) {
            int col = k0 + nt * 8 + 2 * q;
            float2 a0 = *(const float2*)(arow0 + col);
            float2 a1 = *(const float2*)(arow1 + col);
            float2 pd = *(const float2*)(prow + col);
            c[nt][0] = fmaf(c[nt][0], sscale, a0.x + pd.x);
            c[nt][1] = fmaf(c[nt][1], sscale, a0.y + pd.y);
            c[nt][2] = fmaf(c[nt][2], sscale, a1.x + pd.x);
            c[nt][3] = fmaf(c[nt][3], sscale, a1.y + pd.y);
        }
        float mx0 = -1e30f, mx1 = -1e30f;
        #pragma unroll
        for (int nt = 0; nt < 8; nt++) {
            mx0 = fmaxf(mx0, fmaxf(c[nt][0], c[nt][1]));
            mx1 = fmaxf(mx1, fmaxf(c[nt][2], c[nt][3]));
        }
        mx0 = fmaxf(mx0, __shfl_xor_sync(0xffffffffu, mx0, 1));
        mx0 = fmaxf(mx0, __shfl_xor_sync(0xffffffffu, mx0, 2));
        mx1 = fmaxf(mx1, __shfl_xor_sync(0xffffffffu, mx1, 1));
        mx1 = fmaxf(mx1, __shfl_xor_sync(0xffffffffu, mx1, 2));
        float mn0 = fmaxf(m0r, mx0), mn1 = fmaxf(m1r, mx1);
        float cr0 = __expf(m0r - mn0), cr1 = __expf(m1r - mn1);
        m0r = mn0; m1r = mn1;
        float s0 = 0.f, s1 = 0.f;
        #pragma unroll
        for (int nt = 0; nt < 8; nt++) {
            c[nt][0] = __expf(c[nt][0] - mn0);
            c[nt][1] = __expf(c[nt][1] - mn0);
            c[nt][2] = __expf(c[nt][2] - mn1);
            c[nt][3] = __expf(c[nt][3] - mn1);
            s0 += c[nt][0] + c[nt][1];
            s1 += c[nt][2] + c[nt][3];
        }
        s0 += __shfl_xor_sync(0xffffffffu, s0, 1);
        s0 += __shfl_xor_sync(0xffffffffu, s0, 2);
        s1 += __shfl_xor_sync(0xffffffffu, s1, 1);
        s1 += __shfl_xor_sync(0xffffffffu, s1, 2);
        l0r = l0r * cr0 + s0;
        l1r = l1r * cr1 + s1;
        #pragma unroll
        for (int i = 0; i < 16; i++) {
            o[i][0] *= cr0; o[i][1] *= cr0;
            o[i][2] *= cr1; o[i][3] *= cr1;
        }

        // ---- PV (fp16, 1-pass) ----
        #pragma unroll
        for (int kc = 0; kc < 4; kc++) {
            uint32_t ph[4];
            ph[0] = packh_rn(c[2 * kc][0],     c[2 * kc][1]);
            ph[1] = packh_rn(c[2 * kc][2],     c[2 * kc][3]);
            ph[2] = packh_rn(c[2 * kc + 1][0], c[2 * kc + 1][1]);
            ph[3] = packh_rn(c[2 * kc + 1][2], c[2 * kc + 1][3]);
            uint32_t vrow = st + VHO + voff + (uint32_t)kc * (16 * AROWB);
            #pragma unroll
            for (int dg = 0; dg < 8; dg++) {
                uint32_t vh[4];
                ldm4t(vh[0], vh[1], vh[2], vh[3], vrow + dg * 32);
                mma16h(o[2 * dg],     ph, &vh[0]);
                mma16h(o[2 * dg + 1], ph, &vh[2]);
            }
        }

        __syncthreads();
        if (kt + 2 < S_ / 64) { loadKV(kt + 2, kt & 1); cp_commit(); }
        else cp_commit();
    }

    // ---- epilogue: fp16 out only ----
    float inv0 = 1.0f / l0r, inv1 = 1.0f / l1r;
    size_t row0 = tokbase + q0 + wid * 16 + g;
    size_t row1 = row0 + 8;
    #pragma unroll
    for (int nt = 0; nt < 16; nt++) {
        int col = h * 128 + nt * 8 + 2 * q;
        *(uint32_t*)&outh[row0 * D_ + col] =
            packh_rn(o[nt][0] * inv0, o[nt][1] * inv0);
        *(uint32_t*)&outh[row1 * D_ + col] =
            packh_rn(o[nt][2] * inv1, o[nt][3] * inv1);
    }
}

// ---------------------------------------------------------------------------
// kernel_launch
// ---------------------------------------------------------------------------
extern "C" void kernel_launch(void* const* d_in, const int* in_sizes, int n_in,
                              void* d_out, int out_size)
{
    const float* x     = (const float*)d_in[0];
    const float* alibi = (const float*)d_in[1];
    const float* pad   = (const float*)d_in[2];
    const float* Wqkv  = (const float*)d_in[3];
    const float* Aqkv  = (const float*)d_in[4];
    const float* Bqkv  = (const float*)d_in[5];
    const float* Wout  = (const float*)d_in[6];
    const float* Aout  = (const float*)d_in[7];
    const float* Bout  = (const float*)d_in[8];
    float* out = (float*)d_out;

    float *tpart;
    __half *qkvh, *xh, *wqh, *woh, *ah;
    __half *bqt, *bot, *t1h, *t2h;
    cudaGetSymbolAddress((void**)&tpart, g_tpart);
    cudaGetSymbolAddress((void**)&qkvh, g_qkvh);
    cudaGetSymbolAddress((void**)&xh,  g_xh);
    cudaGetSymbolAddress((void**)&wqh, g_wqh);
    cudaGetSymbolAddress((void**)&woh, g_woh);
    cudaGetSymbolAddress((void**)&ah,  g_ah);
    cudaGetSymbolAddress((void**)&bqt, g_bqt);
    cudaGetSymbolAddress((void**)&bot, g_bot);
    cudaGetSymbolAddress((void**)&t1h, g_t1h);
    cudaGetSymbolAddress((void**)&t2h, g_t2h);

    cudaFuncSetAttribute(tc_gemm_fp16,
                         cudaFuncAttributeMaxDynamicSharedMemorySize, TCG_SMEM);
    cudaFuncSetAttribute(attn_mma,
                         cudaFuncAttributeMaxDynamicSharedMemorySize, ATTN_SMEM);

    // pre-pass: x and weights -> single fp16
    convh_kernel<<<(M_TOK * D_ / 4 + 255) / 256, 256>>>(
        (const float4*)x, (uint2*)xh, M_TOK * D_ / 4);
    convh_kernel<<<(3 * D_ * D_ / 4 + 255) / 256, 256>>>(
        (const float4*)Wqkv, (uint2*)wqh, 3 * D_ * D_ / 4);
    convh_kernel<<<(D_ * D_ / 4 + 255) / 256, 256>>>(
        (const float4*)Wout, (uint2*)woh, D_ * D_ / 4);
    transpose_scale_kernel<<<(3 * D_ * R_ + 255) / 256, 256>>>(
        Bqkv, bqt, 3 * D_, LORA_SCALE);
    transpose_scale_kernel<<<(D_ * R_ + 255) / 256, 256>>>(
        Bout, bot, D_, LORA_SCALE);

    // t1 = x @ Aqkv  (split-K, fp16 x)
    lora_down_partial_h<<<dim3(M_TOK / 32, 8), 256>>>(xh, Aqkv, tpart, M_TOK, D_);
    lora_reduce<<<(M_TOK * R_ + 255) / 256, 256>>>(tpart, t1h, M_TOK * R_);

    // qkv = x @ Wqkv^T + lora  -> fp16 (1-pass)
    {
        dim3 grid((3 * D_) / 128, M_TOK / 128);
        tc_gemm_fp16<<<grid, 256, TCG_SMEM>>>(xh, wqh, t1h, bqt,
                                              nullptr, (uint16_t*)qkvh,
                                              M_TOK, 3 * D_, D_, 1);
    }

    // attention (tensor-core fp16, 1-pass QK and PV) -> fp16 ah
    {
        dim3 grid(S_ / 128, H_, B_);
        attn_mma<<<grid, 256, ATTN_SMEM>>>(qkvh, alibi, pad, (uint16_t*)ah);
    }

    // t2 = attn @ Aout  (split-K, fp16 attn)
    lora_down_partial_h<<<dim3(M_TOK / 32, 8), 256>>>(ah, Aout, tpart, M_TOK, D_);
    lora_reduce<<<(M_TOK * R_ + 255) / 256, 256>>>(tpart, t2h, M_TOK * R_);

    // out = attn @ Wout^T + lora  -> fp32 (1-pass)
    {
        dim3 grid(D_ / 128, M_TOK / 128);
        tc_gemm_fp16<<<grid, 256, TCG_SMEM>>>(ah, woh, t2h, bot,
                                              out, nullptr,
                                              M_TOK, D_, D_, 0);
    }
}

// round 11
// speedup vs baseline: 2.2732x; 1.0371x over previous
#include <cuda_runtime.h>
#include <cuda_fp16.h>
#include <cstdint>

// Problem constants
#define B_   2
#define S_   2048
#define D_   2048
#define H_   16
#define HD_  128
#define R_   32
#define M_TOK (B_ * S_)              // 4096 tokens
#define LORA_SCALE (1.0f / 32.0f)

// ---------------------------------------------------------------------------
// Scratch (allocation-free rule: __device__ globals)
// ---------------------------------------------------------------------------
static __device__ __align__(16) __half g_qkvh[M_TOK * 3 * D_];
static __device__ __align__(16) __half g_xh[M_TOK * D_];
static __device__ __align__(16) __half g_wqh[3 * D_ * D_];
static __device__ __align__(16) __half g_woh[D_ * D_];
static __device__ __align__(16) __half g_ah[M_TOK * D_];
static __device__ __align__(16) __half g_bqt[3 * D_ * R_];   // [6144][32]
static __device__ __align__(16) __half g_bot[D_ * R_];       // [2048][32]
static __device__ __align__(16) __half g_t1h[M_TOK * R_];
static __device__ __align__(16) __half g_t2h[M_TOK * R_];
static __device__ float g_tpart[8 * M_TOK * R_];             // split-K partials

// ---------------------------------------------------------------------------
// helpers
// ---------------------------------------------------------------------------
__device__ __forceinline__ uint32_t smem_u32(const void* p) {
    uint32_t a;
    asm("{ .reg .u64 t; cvta.to.shared.u64 t, %1; cvt.u32.u64 %0, t; }"
        : "=r"(a) : "l"(p));
    return a;
}
__device__ __forceinline__ void cp16(uint32_t dst, const void* src) {
    asm volatile("cp.async.cg.shared.global [%0], [%1], 16;"
                 :: "r"(dst), "l"(src) : "memory");
}
__device__ __forceinline__ void cp_commit() {
    asm volatile("cp.async.commit_group;" ::: "memory");
}
__device__ __forceinline__ void cp_wait1() {
    asm volatile("cp.async.wait_group 1;" ::: "memory");
}
__device__ __forceinline__ void ldm4(uint32_t& r0, uint32_t& r1,
                                     uint32_t& r2, uint32_t& r3, uint32_t addr) {
    asm volatile("ldmatrix.sync.aligned.m8n8.x4.shared.b16 {%0,%1,%2,%3}, [%4];"
                 : "=r"(r0), "=r"(r1), "=r"(r2), "=r"(r3) : "r"(addr));
}
__device__ __forceinline__ void ldm4t(uint32_t& r0, uint32_t& r1,
                                      uint32_t& r2, uint32_t& r3, uint32_t addr) {
    asm volatile("ldmatrix.sync.aligned.m8n8.x4.trans.shared.b16 {%0,%1,%2,%3}, [%4];"
                 : "=r"(r0), "=r"(r1), "=r"(r2), "=r"(r3) : "r"(addr));
}
__device__ __forceinline__ void mma16h(float* c, const uint32_t* a, const uint32_t* b) {
    asm volatile(
        "mma.sync.aligned.m16n8k16.row.col.f32.f16.f16.f32 "
        "{%0,%1,%2,%3}, {%4,%5,%6,%7}, {%8,%9}, {%0,%1,%2,%3};"
        : "+f"(c[0]), "+f"(c[1]), "+f"(c[2]), "+f"(c[3])
        : "r"(a[0]), "r"(a[1]), "r"(a[2]), "r"(a[3]), "r"(b[0]), "r"(b[1]));
}
__device__ __forceinline__ uint32_t packh_rn(float x, float y) {
    __half2 t = __floats2half2_rn(x, y);
    return *(uint32_t*)&t;
}

// ---------------------------------------------------------------------------
// Pre-pass: fused fp32 -> fp16 conversion over x, Wqkv, Wout
// ---------------------------------------------------------------------------
#define CONV_N0 (M_TOK * D_ / 4)
#define CONV_N1 (3 * D_ * D_ / 4)
#define CONV_N2 (D_ * D_ / 4)
__global__ void __launch_bounds__(256) conv_all_kernel(
    const float4* __restrict__ s0, uint2* __restrict__ d0,
    const float4* __restrict__ s1, uint2* __restrict__ d1,
    const float4* __restrict__ s2, uint2* __restrict__ d2)
{
    int i = blockIdx.x * 256 + threadIdx.x;
    const float4* s; uint2* d;
    if (i < CONV_N0)                  { s = s0;  d = d0; }
    else if (i < CONV_N0 + CONV_N1)   { s = s1 - CONV_N0; d = d1 - CONV_N0; }
    else if (i < CONV_N0 + CONV_N1 + CONV_N2)
                                      { s = s2 - CONV_N0 - CONV_N1; d = d2 - CONV_N0 - CONV_N1; }
    else return;
    float4 v = s[i];
    d[i] = make_uint2(packh_rn(v.x, v.y), packh_rn(v.z, v.w));
}

// Pre-pass: both LoRA-B transposes: Bq[32,N] -> out[N][32] fp16 * scale
__global__ void __launch_bounds__(256) trans_all_kernel(
    const float* __restrict__ B0, __half* __restrict__ o0,
    const float* __restrict__ B1, __half* __restrict__ o1, float scale)
{
    int idx = blockIdx.x * 256 + threadIdx.x;
    const int N0 = 3 * D_;
    if (idx < N0 * 32) {
        int k = idx & 31, n = idx >> 5;
        o0[(size_t)n * 32 + k] = __float2half(B0[(size_t)k * N0 + n] * scale);
    } else if (idx < N0 * 32 + D_ * 32) {
        int j = idx - N0 * 32;
        int k = j & 31, n = j >> 5;
        o1[(size_t)n * 32 + k] = __float2half(B1[(size_t)k * D_ + n] * scale);
    }
}

// ---------------------------------------------------------------------------
// fp16 fused GEMM (1-pass):  C = Ah @ Bh^T + T @ Bqt^T
// outMode: 0 = fp32 Cf, 1 = fp16 (RN) Chi
// ---------------------------------------------------------------------------
#define OFF_AH 0
#define OFF_BH 6144
#define STAGE_B 12288
#define TCG_SMEM (3 * STAGE_B)      // 36864 bytes

__global__ void __launch_bounds__(256, 2) tc_gemm_fp16(
    const __half* __restrict__ Ah, const __half* __restrict__ Bh,
    const __half* __restrict__ Tm, const __half* __restrict__ Bqt,
    float* __restrict__ Cf, uint16_t* __restrict__ Chi,
    int M, int N, int K, int outMode)
{
    extern __shared__ __align__(128) char smem[];
    const uint32_t sbase = smem_u32(smem);

    const int tid  = threadIdx.x;
    const int wid  = tid >> 5;
    const int lane = tid & 31;
    const int g    = lane >> 2;
    const int q    = lane & 3;
    const int warpM = (wid & 1) * 64;
    const int warpN = (wid >> 1) * 32;

    const int n0 = blockIdx.x * 128;
    const int m0 = blockIdx.y * 128;

    const int kc    = K >> 4;
    const int total = kc + 2;

    float acc[4][4][4];
    #pragma unroll
    for (int i = 0; i < 4; i++)
        #pragma unroll
        for (int j = 0; j < 4; j++)
            #pragma unroll
            for (int e = 0; e < 4; e++) acc[i][j][e] = 0.f;

    const int pr = tid >> 1;
    const int ps = tid & 1;
    auto issue = [&](int c, int s) {
        const uint32_t st = sbase + (uint32_t)s * STAGE_B;
        const uint32_t doff = (uint32_t)pr * 48u + (uint32_t)ps * 16u;
        if (c < kc) {
            size_t ao = (size_t)(m0 + pr) * K + c * 16 + ps * 8;
            size_t bo = (size_t)(n0 + pr) * K + c * 16 + ps * 8;
            cp16(st + OFF_AH + doff, Ah + ao);
            cp16(st + OFF_BH + doff, Bh + bo);
        } else {
            int kl = (c - kc) * 16 + ps * 8;
            cp16(st + OFF_AH + doff, Tm  + (size_t)(m0 + pr) * 32 + kl);
            cp16(st + OFF_BH + doff, Bqt + (size_t)(n0 + pr) * 32 + kl);
        }
        cp_commit();
    };

    issue(0, 0);
    issue(1, 1);

    const int mi = lane >> 3;
    const int l7 = lane & 7;

    for (int i = 0; i < total; i++) {
        cp_wait1();
        __syncthreads();
        if (i + 2 < total) issue(i + 2, (i + 2) % 3);
        else cp_commit();

        const uint32_t st = sbase + (uint32_t)(i % 3) * STAGE_B;

        uint32_t bh[4][2];
        #pragma unroll
        for (int bg = 0; bg < 2; bg++) {
            uint32_t rowB = warpN + bg * 16 + ((mi >> 1) << 3) + l7;
            uint32_t addr = st + OFF_BH + rowB * 48u + (uint32_t)(mi & 1) * 16u;
            ldm4(bh[2 * bg][0], bh[2 * bg][1], bh[2 * bg + 1][0], bh[2 * bg + 1][1], addr);
        }
        #pragma unroll
        for (int mt = 0; mt < 4; mt++) {
            uint32_t rowA = warpM + mt * 16 + ((mi & 1) << 3) + l7;
            uint32_t addrA = st + OFF_AH + rowA * 48u + (uint32_t)(mi >> 1) * 16u;
            uint32_t ah[4];
            ldm4(ah[0], ah[1], ah[2], ah[3], addrA);
            #pragma unroll
            for (int nt = 0; nt < 4; nt++)
                mma16h(acc[mt][nt], ah, bh[nt]);
        }
    }

    // epilogue
    #pragma unroll
    for (int mt = 0; mt < 4; mt++) {
        int row = m0 + warpM + mt * 16 + g;
        #pragma unroll
        for (int nt = 0; nt < 4; nt++) {
            int col = n0 + warpN + nt * 8 + 2 * q;
            size_t i0 = (size_t)row * N + col;
            size_t i1 = (size_t)(row + 8) * N + col;
            if (outMode == 0) {
                *(float2*)&Cf[i0] = make_float2(acc[mt][nt][0], acc[mt][nt][1]);
                *(float2*)&Cf[i1] = make_float2(acc[mt][nt][2], acc[mt][nt][3]);
            } else {
                *(uint32_t*)&Chi[i0] = packh_rn(acc[mt][nt][0], acc[mt][nt][1]);
                *(uint32_t*)&Chi[i1] = packh_rn(acc[mt][nt][2], acc[mt][nt][3]);
            }
        }
    }
}

// ---------------------------------------------------------------------------
// LoRA-down split-K (fp16 X): part[s][M][32] = X[M, s-slice] @ A[s-slice, 32]
// ---------------------------------------------------------------------------
__global__ void __launch_bounds__(256) lora_down_partial_h(
    const __half* __restrict__ X, const float* __restrict__ Amat,
    float* __restrict__ part, int M, int K)
{
    __shared__ __align__(16) float Xs[32][68];
    __shared__ __align__(16) float As2[64][36];

    const int tid = threadIdx.x;
    const int m0  = blockIdx.x * 32;
    const int s   = blockIdx.y;
    const int KS  = K >> 3;               // 256
    const int kb  = s * KS;
    const int n   = tid & 31;
    const int mq  = (tid >> 5) * 4;

    float acc[4] = {0.f, 0.f, 0.f, 0.f};

    for (int k0 = kb; k0 < kb + KS; k0 += 64) {
        __syncthreads();
        {
            int m  = tid >> 3;
            int k8 = (tid & 7) << 3;
            uint4 v = *(const uint4*)&X[(size_t)(m0 + m) * K + k0 + k8];
            const __half2* hp = (const __half2*)&v;
            #pragma unroll
            for (int e = 0; e < 4; e++) {
                float2 f = __half22float2(hp[e]);
                Xs[m][k8 + 2 * e]     = f.x;
                Xs[m][k8 + 2 * e + 1] = f.y;
            }
        }
        #pragma unroll
        for (int l = 0; l < 2; l++) {
            int idx = tid + l * 256;
            int kk  = idx >> 3;
            int n4  = (idx & 7) << 2;
            *(float4*)&As2[kk][n4] =
                *(const float4*)&Amat[(size_t)(k0 + kk) * 32 + n4];
        }
        __syncthreads();
        #pragma unroll 16
        for (int kk = 0; kk < 64; kk++) {
            float a = As2[kk][n];
            acc[0] = fmaf(Xs[mq + 0][kk], a, acc[0]);
            acc[1] = fmaf(Xs[mq + 1][kk], a, acc[1]);
            acc[2] = fmaf(Xs[mq + 2][kk], a, acc[2]);
            acc[3] = fmaf(Xs[mq + 3][kk], a, acc[3]);
        }
    }
    float* dst = part + (size_t)s * M * 32;
    #pragma unroll
    for (int i = 0; i < 4; i++)
        dst[(size_t)(m0 + mq + i) * 32 + n] = acc[i];
}

__global__ void __launch_bounds__(256) lora_reduce(
    const float* __restrict__ part, __half* __restrict__ outT, int n)
{
    int i = blockIdx.x * 256 + threadIdx.x;
    if (i >= n) return;
    float sum = 0.f;
    #pragma unroll
    for (int p = 0; p < 8; p++) sum += part[(size_t)p * n + i];
    outT[i] = __float2half(sum);
}

// ---------------------------------------------------------------------------
// Tensor-core flash attention, fp16 1-pass, OCCUPANCY-2 variant:
// CTA: 128 threads (4 warps), 64 q-rows.  Grid: (S/64, H, B).
// Each warp: 16 q-rows x full n=64 per ktile (identical math to round 10).
// pad row staged in smem once.  smem/CTA = 93 KB -> 2 CTAs/SM.
// ---------------------------------------------------------------------------
#define AROWB 272
#define PAD_OFF 0
#define PAD_B   (S_ * 4)                       // 8192
#define QH_OFF  PAD_B
#define KV_OFF  (QH_OFF + 64 * AROWB)          // 8192 + 17408
#define KHO 0
#define VHO (64 * AROWB)
#define ST_B (2 * 64 * AROWB)                  // 34816
#define ATTN_SMEM (KV_OFF + 2 * ST_B)          // 95232

__global__ void __launch_bounds__(128, 2) attn_mma(
    const __half* __restrict__ qkvh,
    const float* __restrict__ alibi, const float* __restrict__ pad,
    uint16_t* __restrict__ outh)
{
    extern __shared__ __align__(128) char smem[];
    const uint32_t sb = smem_u32(smem);
    const int tid = threadIdx.x, wid = tid >> 5, lane = tid & 31;
    const int g = lane >> 2, q = lane & 3, l7 = lane & 7;
    const int q0 = blockIdx.x * 64, h = blockIdx.y, b = blockIdx.z;

    const size_t tokbase = (size_t)(b * S_);

    // --- group 0: pad row (2048 fp32) + Q tile (64 rows) ---
    {
        const float* prow = pad + (size_t)b * S_;
        #pragma unroll
        for (int j = 0; j < 4; j++) {
            int idx = tid + j * 128;           // 512 x 16B
            cp16(sb + PAD_OFF + idx * 16, prow + idx * 4);
        }
        const __half* bH = qkvh + (tokbase + q0) * 6144 + h * 128;
        #pragma unroll
        for (int j = 0; j < 8; j++) {
            int idx = tid + j * 128;           // 1024 positions
            int row = idx >> 4, seg = idx & 15;
            cp16(sb + QH_OFF + (uint32_t)row * AROWB + seg * 16,
                 bH + (size_t)row * 6144 + seg * 8);
        }
    }
    auto loadKV = [&](int kt, int st) {
        const uint32_t base = sb + KV_OFF + (uint32_t)st * ST_B;
        const __half* kH = qkvh + (tokbase + kt * 64) * 6144 + D_ + h * 128;
        const __half* vH = kH + D_;
        #pragma unroll
        for (int j = 0; j < 8; j++) {
            int idx = tid + j * 128;
            int row = idx >> 4, seg = idx & 15;
            uint32_t off = (uint32_t)row * AROWB + seg * 16;
            size_t go = (size_t)row * 6144 + seg * 8;
            cp16(base + KHO + off, kH + go);
            cp16(base + VHO + off, vH + go);
        }
    };
    cp_commit();                 // group: pad + Q
    loadKV(0, 0); cp_commit();
    loadKV(1, 1); cp_commit();

    float o[16][4];
    #pragma unroll
    for (int i = 0; i < 16; i++)
        #pragma unroll
        for (int e = 0; e < 4; e++) o[i][e] = 0.f;
    float m0r = -1e30f, m1r = -1e30f, l0r = 0.f, l1r = 0.f;

    const float sscale = 0.08838834764831845f;   // 1/sqrt(128)

    const uint32_t qoff = (uint32_t)(wid * 16 + ((lane >> 3) & 1) * 8 + l7) * AROWB
                        + ((lane >> 4) & 1) * 16 + QH_OFF;
    const uint32_t koff = (uint32_t)(((lane >> 4) & 1) * 8 + l7) * AROWB
                        + ((lane >> 3) & 1) * 16;
    const uint32_t voff = (uint32_t)(((lane >> 3) & 1) * 8 + l7) * AROWB
                        + ((lane >> 4) & 1) * 16;

    const float* arow0 = alibi + ((size_t)h * S_ + (q0 + wid * 16 + g)) * S_;
    const float* arow1 = arow0 + 8 * S_;
    const float* padS  = (const float*)smem;     // PAD_OFF == 0

    for (int kt = 0; kt < S_ / 64; kt++) {
        cp_wait1();
        __syncthreads();
        const uint32_t st = sb + KV_OFF + (uint32_t)(kt & 1) * ST_B;
        const int k0 = kt * 64;

        // ---- QK^T (fp16, 1-pass) ----
        float c[8][4];
        #pragma unroll
        for (int i = 0; i < 8; i++)
            #pragma unroll
            for (int e = 0; e < 4; e++) c[i][e] = 0.f;

        #pragma unroll
        for (int kc = 0; kc < 8; kc++) {
            uint32_t qh4[4];
            ldm4(qh4[0], qh4[1], qh4[2], qh4[3], sb + qoff + kc * 32);
            #pragma unroll
            for (int np = 0; np < 4; np++) {
                uint32_t kh[4];
                uint32_t ka = st + KHO + koff + (uint32_t)np * (16 * AROWB) + kc * 32;
                ldm4(kh[0], kh[1], kh[2], kh[3], ka);
                mma16h(c[2 * np],     qh4, &kh[0]);
                mma16h(c[2 * np + 1], qh4, &kh[2]);
            }
        }

        // ---- bias + online softmax ----
        #pragma unroll
        for (int nt = 0; nt < 8; nt++) {
            int col = k0 + nt * 8 + 2 * q;
            float2 a0 = *(const float2*)(arow0 + col);
            float2 a1 = *(const float2*)(arow1 + col);
            float2 pd = *(const float2*)(padS + col);
            c[nt][0] = fmaf(c[nt][0], sscale, a0.x + pd.x);
            c[nt][1] = fmaf(c[nt][1], sscale, a0.y + pd.y);
            c[nt][2] = fmaf(c[nt][2], sscale, a1.x + pd.x);
            c[nt][3] = fmaf(c[nt][3], sscale, a1.y + pd.y);
        }
        float mx0 = -1e30f, mx1 = -1e30f;
        #pragma unroll
        for (int nt = 0; nt < 8; nt++) {
            mx0 = fmaxf(mx0, fmaxf(c[nt][0], c[nt][1]));
            mx1 = fmaxf(mx1, fmaxf(c[nt][2], c[nt][3]));
        }
        mx0 = fmaxf(mx0, __shfl_xor_sync(0xffffffffu, mx0, 1));
        mx0 = fmaxf(mx0, __shfl_xor_sync(0xffffffffu, mx0, 2));
        mx1 = fmaxf(mx1, __shfl_xor_sync(0xffffffffu, mx1, 1));
        mx1 = fmaxf(mx1, __shfl_xor_sync(0xffffffffu, mx1, 2));
        float mn0 = fmaxf(m0r, mx0), mn1 = fmaxf(m1r, mx1);
        float cr0 = __expf(m0r - mn0), cr1 = __expf(m1r - mn1);
        m0r = mn0; m1r = mn1;
        float s0 = 0.f, s1 = 0.f;
        #pragma unroll
        for (int nt = 0; nt < 8; nt++) {
            c[nt][0] = __expf(c[nt][0] - mn0);
            c[nt][1] = __expf(c[nt][1] - mn0);
            c[nt][2] = __expf(c[nt][2] - mn1);
            c[nt][3] = __expf(c[nt][3] - mn1);
            s0 += c[nt][0] + c[nt][1];
            s1 += c[nt][2] + c[nt][3];
        }
        s0 += __shfl_xor_sync(0xffffffffu, s0, 1);
        s0 += __shfl_xor_sync(0xffffffffu, s0, 2);
        s1 += __shfl_xor_sync(0xffffffffu, s1, 1);
        s1 += __shfl_xor_sync(0xffffffffu, s1, 2);
        l0r = l0r * cr0 + s0;
        l1r = l1r * cr1 + s1;
        #pragma unroll
        for (int i = 0; i < 16; i++) {
            o[i][0] *= cr0; o[i][1] *= cr0;
            o[i][2] *= cr1; o[i][3] *= cr1;
        }

        // ---- PV (fp16, 1-pass) ----
        #pragma unroll
        for (int kc = 0; kc < 4; kc++) {
            uint32_t ph[4];
            ph[0] = packh_rn(c[2 * kc][0],     c[2 * kc][1]);
            ph[1] = packh_rn(c[2 * kc][2],     c[2 * kc][3]);
            ph[2] = packh_rn(c[2 * kc + 1][0], c[2 * kc + 1][1]);
            ph[3] = packh_rn(c[2 * kc + 1][2], c[2 * kc + 1][3]);
            uint32_t vrow = st + VHO + voff + (uint32_t)kc * (16 * AROWB);
            #pragma unroll
            for (int dg = 0; dg < 8; dg++) {
                uint32_t vh[4];
                ldm4t(vh[0], vh[1], vh[2], vh[3], vrow + dg * 32);
                mma16h(o[2 * dg],     ph, &vh[0]);
                mma16h(o[2 * dg + 1], ph, &vh[2]);
            }
        }

        __syncthreads();
        if (kt + 2 < S_ / 64) { loadKV(kt + 2, kt & 1); cp_commit(); }
        else cp_commit();
    }

    // ---- epilogue: fp16 out ----
    float inv0 = 1.0f / l0r, inv1 = 1.0f / l1r;
    size_t row0 = tokbase + q0 + wid * 16 + g;
    size_t row1 = row0 + 8;
    #pragma unroll
    for (int nt = 0; nt < 16; nt++) {
        int col = h * 128 + nt * 8 + 2 * q;
        *(uint32_t*)&outh[row0 * D_ + col] =
            packh_rn(o[nt][0] * inv0, o[nt][1] * inv0);
        *(uint32_t*)&outh[row1 * D_ + col] =
            packh_rn(o[nt][2] * inv1, o[nt][3] * inv1);
    }
}

// ---------------------------------------------------------------------------
// kernel_launch
// ---------------------------------------------------------------------------
extern "C" void kernel_launch(void* const* d_in, const int* in_sizes, int n_in,
                              void* d_out, int out_size)
{
    const float* x     = (const float*)d_in[0];
    const float* alibi = (const float*)d_in[1];
    const float* pad   = (const float*)d_in[2];
    const float* Wqkv  = (const float*)d_in[3];
    const float* Aqkv  = (const float*)d_in[4];
    const float* Bqkv  = (const float*)d_in[5];
    const float* Wout  = (const float*)d_in[6];
    const float* Aout  = (const float*)d_in[7];
    const float* Bout  = (const float*)d_in[8];
    float* out = (float*)d_out;

    float *tpart;
    __half *qkvh, *xh, *wqh, *woh, *ah;
    __half *bqt, *bot, *t1h, *t2h;
    cudaGetSymbolAddress((void**)&tpart, g_tpart);
    cudaGetSymbolAddress((void**)&qkvh, g_qkvh);
    cudaGetSymbolAddress((void**)&xh,  g_xh);
    cudaGetSymbolAddress((void**)&wqh, g_wqh);
    cudaGetSymbolAddress((void**)&woh, g_woh);
    cudaGetSymbolAddress((void**)&ah,  g_ah);
    cudaGetSymbolAddress((void**)&bqt, g_bqt);
    cudaGetSymbolAddress((void**)&bot, g_bot);
    cudaGetSymbolAddress((void**)&t1h, g_t1h);
    cudaGetSymbolAddress((void**)&t2h, g_t2h);

    cudaFuncSetAttribute(tc_gemm_fp16,
                         cudaFuncAttributeMaxDynamicSharedMemorySize, TCG_SMEM);
    cudaFuncSetAttribute(attn_mma,
                         cudaFuncAttributeMaxDynamicSharedMemorySize, ATTN_SMEM);

    // pre-pass: fused conversions + transposes
    {
        int totalq = CONV_N0 + CONV_N1 + CONV_N2;
        conv_all_kernel<<<(totalq + 255) / 256, 256>>>(
            (const float4*)x, (uint2*)xh,
            (const float4*)Wqkv, (uint2*)wqh,
            (const float4*)Wout, (uint2*)woh);
        int totalt = (3 * D_ + D_) * R_;
        trans_all_kernel<<<(totalt + 255) / 256, 256>>>(
            Bqkv, bqt, Bout, bot, LORA_SCALE);
    }

    // t1 = x @ Aqkv  (split-K, fp16 x)
    lora_down_partial_h<<<dim3(M_TOK / 32, 8), 256>>>(xh, Aqkv, tpart, M_TOK, D_);
    lora_reduce<<<(M_TOK * R_ + 255) / 256, 256>>>(tpart, t1h, M_TOK * R_);

    // qkv = x @ Wqkv^T + lora  -> fp16 (1-pass)
    {
        dim3 grid((3 * D_) / 128, M_TOK / 128);
        tc_gemm_fp16<<<grid, 256, TCG_SMEM>>>(xh, wqh, t1h, bqt,
                                              nullptr, (uint16_t*)qkvh,
                                              M_TOK, 3 * D_, D_, 1);
    }

    // attention (tensor-core fp16, occ-2, 64 q-rows/CTA) -> fp16 ah
    {
        dim3 grid(S_ / 64, H_, B_);
        attn_mma<<<grid, 128, ATTN_SMEM>>>(qkvh, alibi, pad, (uint16_t*)ah);
    }

    // t2 = attn @ Aout  (split-K, fp16 attn)
    lora_down_partial_h<<<dim3(M_TOK / 32, 8), 256>>>(ah, Aout, tpart, M_TOK, D_);
    lora_reduce<<<(M_TOK * R_ + 255) / 256, 256>>>(tpart, t2h, M_TOK * R_);

    // out = attn @ Wout^T + lora  -> fp32 (1-pass)
    {
        dim3 grid(D_ / 128, M_TOK / 128);
        tc_gemm_fp16<<<grid, 256, TCG_SMEM>>>(ah, woh, t2h, bot,
                                              out, nullptr,
                                              M_TOK, D_, D_, 0);
    }
}

// round 12
// speedup vs baseline: 2.6329x; 1.1582x over previous
#include <cuda_runtime.h>
#include <cuda_fp16.h>
#include <cstdint>

// Problem constants
#define B_   2
#define S_   2048
#define D_   2048
#define H_   16
#define HD_  128
#define R_   32
#define M_TOK (B_ * S_)              // 4096 tokens
#define LORA_SCALE (1.0f / 32.0f)

// ---------------------------------------------------------------------------
// Scratch (allocation-free rule: __device__ globals)
// ---------------------------------------------------------------------------
static __device__ __align__(16) __half g_qkvh[M_TOK * 3 * D_];
static __device__ __align__(16) __half g_xh[M_TOK * D_];
static __device__ __align__(16) __half g_wqh[3 * D_ * D_];   // Wqkv + LoRA folded
static __device__ __align__(16) __half g_woh[D_ * D_];       // Wout + LoRA folded
static __device__ __align__(16) __half g_ah[M_TOK * D_];

// ---------------------------------------------------------------------------
// helpers
// ---------------------------------------------------------------------------
__device__ __forceinline__ uint32_t smem_u32(const void* p) {
    uint32_t a;
    asm("{ .reg .u64 t; cvta.to.shared.u64 t, %1; cvt.u32.u64 %0, t; }"
        : "=r"(a) : "l"(p));
    return a;
}
__device__ __forceinline__ void cp16(uint32_t dst, const void* src) {
    asm volatile("cp.async.cg.shared.global [%0], [%1], 16;"
                 :: "r"(dst), "l"(src) : "memory");
}
__device__ __forceinline__ void cp_commit() {
    asm volatile("cp.async.commit_group;" ::: "memory");
}
__device__ __forceinline__ void cp_wait1() {
    asm volatile("cp.async.wait_group 1;" ::: "memory");
}
__device__ __forceinline__ void ldm4(uint32_t& r0, uint32_t& r1,
                                     uint32_t& r2, uint32_t& r3, uint32_t addr) {
    asm volatile("ldmatrix.sync.aligned.m8n8.x4.shared.b16 {%0,%1,%2,%3}, [%4];"
                 : "=r"(r0), "=r"(r1), "=r"(r2), "=r"(r3) : "r"(addr));
}
__device__ __forceinline__ void ldm4t(uint32_t& r0, uint32_t& r1,
                                      uint32_t& r2, uint32_t& r3, uint32_t addr) {
    asm volatile("ldmatrix.sync.aligned.m8n8.x4.trans.shared.b16 {%0,%1,%2,%3}, [%4];"
                 : "=r"(r0), "=r"(r1), "=r"(r2), "=r"(r3) : "r"(addr));
}
__device__ __forceinline__ void mma16h(float* c, const uint32_t* a, const uint32_t* b) {
    asm volatile(
        "mma.sync.aligned.m16n8k16.row.col.f32.f16.f16.f32 "
        "{%0,%1,%2,%3}, {%4,%5,%6,%7}, {%8,%9}, {%0,%1,%2,%3};"
        : "+f"(c[0]), "+f"(c[1]), "+f"(c[2]), "+f"(c[3])
        : "r"(a[0]), "r"(a[1]), "r"(a[2]), "r"(a[3]), "r"(b[0]), "r"(b[1]));
}
__device__ __forceinline__ uint32_t packh_rn(float x, float y) {
    __half2 t = __floats2half2_rn(x, y);
    return *(uint32_t*)&t;
}

// ---------------------------------------------------------------------------
// Pre-pass: fp32 -> fp16 RN (x only)
// ---------------------------------------------------------------------------
__global__ void __launch_bounds__(256) convh_kernel(
    const float4* __restrict__ src, uint2* __restrict__ dst, int n4)
{
    int i = blockIdx.x * 256 + threadIdx.x;
    if (i >= n4) return;
    float4 v = src[i];
    dst[i] = make_uint2(packh_rn(v.x, v.y), packh_rn(v.z, v.w));
}

// ---------------------------------------------------------------------------
// Pre-pass: fold LoRA into weight, fp32 -> fp16:
//   Weff[n][k] = W[n][k] + scale * sum_r A[k][r] * Bm[r][n]
// W: [N, K] row-major, A: [K, 32], Bm: [32, N].  Block: 64n x 64k tile.
// ---------------------------------------------------------------------------
__global__ void __launch_bounds__(256) weff_kernel(
    const float* __restrict__ W, const float* __restrict__ A,
    const float* __restrict__ Bm, __half* __restrict__ outW,
    int N, int K, float scale)
{
    __shared__ float As[64][33];   // [k][r]
    __shared__ float Bs[64][33];   // [n][r]

    const int tid = threadIdx.x;
    const int k0 = blockIdx.x * 64;
    const int n0 = blockIdx.y * 64;

    #pragma unroll
    for (int j = 0; j < 8; j++) {
        int idx = tid + j * 256;           // 0..2047
        int kk = idx >> 5, r = idx & 31;
        As[kk][r] = A[(size_t)(k0 + kk) * 32 + r];
    }
    #pragma unroll
    for (int j = 0; j < 8; j++) {
        int idx = tid + j * 256;
        int r = idx >> 6, nn = idx & 63;
        Bs[nn][r] = Bm[(size_t)r * N + n0 + nn];
    }
    __syncthreads();

    const int tk = tid & 15;     // 4 k each
    const int tn = tid >> 4;     // 4 n each

    float acc[4][4];
    #pragma unroll
    for (int i = 0; i < 4; i++)
        #pragma unroll
        for (int j = 0; j < 4; j++) acc[i][j] = 0.f;

    #pragma unroll
    for (int r = 0; r < 32; r++) {
        float a[4], b[4];
        #pragma unroll
        for (int j = 0; j < 4; j++) a[j] = As[tk * 4 + j][r];
        #pragma unroll
        for (int i = 0; i < 4; i++) b[i] = Bs[tn * 4 + i][r];
        #pragma unroll
        for (int i = 0; i < 4; i++)
            #pragma unroll
            for (int j = 0; j < 4; j++)
                acc[i][j] = fmaf(b[i], a[j], acc[i][j]);
    }

    #pragma unroll
    for (int i = 0; i < 4; i++) {
        int n = n0 + tn * 4 + i;
        float4 w = *(const float4*)&W[(size_t)n * K + k0 + tk * 4];
        uint2 o;
        o.x = packh_rn(fmaf(scale, acc[i][0], w.x), fmaf(scale, acc[i][1], w.y));
        o.y = packh_rn(fmaf(scale, acc[i][2], w.z), fmaf(scale, acc[i][3], w.w));
        *(uint2*)&outW[(size_t)n * K + k0 + tk * 4] = o;
    }
}

// ---------------------------------------------------------------------------
// fp16 GEMM (1-pass, LoRA pre-folded into B):  C = Ah @ Bh^T
// K-chunk 32, row stride 80B (conflict-free ldmatrix), 3-stage cp.async.
// outMode: 0 = fp32 Cf, 1 = fp16 (RN) Chi
// ---------------------------------------------------------------------------
#define GROW 80
#define OFF_B 10240
#define STAGE_B 20480
#define TCG_SMEM (3 * STAGE_B)      // 61440 bytes

__global__ void __launch_bounds__(256, 2) tc_gemm_fp16(
    const __half* __restrict__ Ah, const __half* __restrict__ Bh,
    float* __restrict__ Cf, uint16_t* __restrict__ Chi,
    int M, int N, int K, int outMode)
{
    extern __shared__ __align__(128) char smem[];
    const uint32_t sbase = smem_u32(smem);

    const int tid  = threadIdx.x;
    const int wid  = tid >> 5;
    const int lane = tid & 31;
    const int g    = lane >> 2;
    const int q    = lane & 3;
    const int warpM = (wid & 1) * 64;
    const int warpN = (wid >> 1) * 32;

    const int n0 = blockIdx.x * 128;
    const int m0 = blockIdx.y * 128;

    const int kc = K >> 5;           // chunks of 32

    float acc[4][4][4];
    #pragma unroll
    for (int i = 0; i < 4; i++)
        #pragma unroll
        for (int j = 0; j < 4; j++)
            #pragma unroll
            for (int e = 0; e < 4; e++) acc[i][j][e] = 0.f;

    auto issue = [&](int c, int s) {
        const uint32_t st = sbase + (uint32_t)s * STAGE_B;
        #pragma unroll
        for (int j = 0; j < 2; j++) {
            int idx = tid + j * 256;          // 0..511
            int row = idx >> 2;
            int seg = idx & 3;
            uint32_t doff = (uint32_t)row * GROW + (uint32_t)seg * 16u;
            cp16(st + doff,         Ah + (size_t)(m0 + row) * K + c * 32 + seg * 8);
            cp16(st + OFF_B + doff, Bh + (size_t)(n0 + row) * K + c * 32 + seg * 8);
        }
        cp_commit();
    };

    issue(0, 0);
    issue(1, 1);

    const int mi = lane >> 3;
    const int l7 = lane & 7;

    for (int i = 0; i < kc; i++) {
        cp_wait1();
        __syncthreads();
        if (i + 2 < kc) issue(i + 2, (i + 2) % 3);
        else cp_commit();

        const uint32_t st = sbase + (uint32_t)(i % 3) * STAGE_B;

        #pragma unroll
        for (int kh = 0; kh < 2; kh++) {
            uint32_t bh[4][2];
            #pragma unroll
            for (int bg = 0; bg < 2; bg++) {
                uint32_t rowB = warpN + bg * 16 + ((mi >> 1) << 3) + l7;
                uint32_t addr = st + OFF_B + rowB * GROW
                              + (uint32_t)(mi & 1) * 16u + kh * 32u;
                ldm4(bh[2 * bg][0], bh[2 * bg][1],
                     bh[2 * bg + 1][0], bh[2 * bg + 1][1], addr);
            }
            #pragma unroll
            for (int mt = 0; mt < 4; mt++) {
                uint32_t rowA = warpM + mt * 16 + ((mi & 1) << 3) + l7;
                uint32_t addrA = st + rowA * GROW
                               + (uint32_t)(mi >> 1) * 16u + kh * 32u;
                uint32_t ah[4];
                ldm4(ah[0], ah[1], ah[2], ah[3], addrA);
                #pragma unroll
                for (int nt = 0; nt < 4; nt++)
                    mma16h(acc[mt][nt], ah, bh[nt]);
            }
        }
    }

    // epilogue
    #pragma unroll
    for (int mt = 0; mt < 4; mt++) {
        int row = m0 + warpM + mt * 16 + g;
        #pragma unroll
        for (int nt = 0; nt < 4; nt++) {
            int col = n0 + warpN + nt * 8 + 2 * q;
            size_t i0 = (size_t)row * N + col;
            size_t i1 = (size_t)(row + 8) * N + col;
            if (outMode == 0) {
                *(float2*)&Cf[i0] = make_float2(acc[mt][nt][0], acc[mt][nt][1]);
                *(float2*)&Cf[i1] = make_float2(acc[mt][nt][2], acc[mt][nt][3]);
            } else {
                *(uint32_t*)&Chi[i0] = packh_rn(acc[mt][nt][0], acc[mt][nt][1]);
                *(uint32_t*)&Chi[i1] = packh_rn(acc[mt][nt][2], acc[mt][nt][3]);
            }
        }
    }
}

// ---------------------------------------------------------------------------
// Tensor-core flash attention, fp16 1-pass, occupancy-2:
// CTA: 128 threads (4 warps), 64 q-rows.  Grid: (S/64, H, B).
// (unchanged from round 11 — passing, near floor)
// ---------------------------------------------------------------------------
#define AROWB 272
#define PAD_OFF 0
#define PAD_B   (S_ * 4)                       // 8192
#define QH_OFF  PAD_B
#define KV_OFF  (QH_OFF + 64 * AROWB)
#define KHO 0
#define VHO (64 * AROWB)
#define ST_B (2 * 64 * AROWB)
#define ATTN_SMEM (KV_OFF + 2 * ST_B)          // 95232

__global__ void __launch_bounds__(128, 2) attn_mma(
    const __half* __restrict__ qkvh,
    const float* __restrict__ alibi, const float* __restrict__ pad,
    uint16_t* __restrict__ outh)
{
    extern __shared__ __align__(128) char smem[];
    const uint32_t sb = smem_u32(smem);
    const int tid = threadIdx.x, wid = tid >> 5, lane = tid & 31;
    const int g = lane >> 2, q = lane & 3, l7 = lane & 7;
    const int q0 = blockIdx.x * 64, h = blockIdx.y, b = blockIdx.z;

    const size_t tokbase = (size_t)(b * S_);

    {
        const float* prow = pad + (size_t)b * S_;
        #pragma unroll
        for (int j = 0; j < 4; j++) {
            int idx = tid + j * 128;
            cp16(sb + PAD_OFF + idx * 16, prow + idx * 4);
        }
        const __half* bH = qkvh + (tokbase + q0) * 6144 + h * 128;
        #pragma unroll
        for (int j = 0; j < 8; j++) {
            int idx = tid + j * 128;
            int row = idx >> 4, seg = idx & 15;
            cp16(sb + QH_OFF + (uint32_t)row * AROWB + seg * 16,
                 bH + (size_t)row * 6144 + seg * 8);
        }
    }
    auto loadKV = [&](int kt, int st) {
        const uint32_t base = sb + KV_OFF + (uint32_t)st * ST_B;
        const __half* kH = qkvh + (tokbase + kt * 64) * 6144 + D_ + h * 128;
        const __half* vH = kH + D_;
        #pragma unroll
        for (int j = 0; j < 8; j++) {
            int idx = tid + j * 128;
            int row = idx >> 4, seg = idx & 15;
            uint32_t off = (uint32_t)row * AROWB + seg * 16;
            size_t go = (size_t)row * 6144 + seg * 8;
            cp16(base + KHO + off, kH + go);
            cp16(base + VHO + off, vH + go);
        }
    };
    cp_commit();
    loadKV(0, 0); cp_commit();
    loadKV(1, 1); cp_commit();

    float o[16][4];
    #pragma unroll
    for (int i = 0; i < 16; i++)
        #pragma unroll
        for (int e = 0; e < 4; e++) o[i][e] = 0.f;
    float m0r = -1e30f, m1r = -1e30f, l0r = 0.f, l1r = 0.f;

    const float sscale = 0.08838834764831845f;   // 1/sqrt(128)

    const uint32_t qoff = (uint32_t)(wid * 16 + ((lane >> 3) & 1) * 8 + l7) * AROWB
                        + ((lane >> 4) & 1) * 16 + QH_OFF;
    const uint32_t koff = (uint32_t)(((lane >> 4) & 1) * 8 + l7) * AROWB
                        + ((lane >> 3) & 1) * 16;
    const uint32_t voff = (uint32_t)(((lane >> 3) & 1) * 8 + l7) * AROWB
                        + ((lane >> 4) & 1) * 16;

    const float* arow0 = alibi + ((size_t)h * S_ + (q0 + wid * 16 + g)) * S_;
    const float* arow1 = arow0 + 8 * S_;
    const float* padS  = (const float*)smem;

    for (int kt = 0; kt < S_ / 64; kt++) {
        cp_wait1();
        __syncthreads();
        const uint32_t st = sb + KV_OFF + (uint32_t)(kt & 1) * ST_B;
        const int k0 = kt * 64;

        float c[8][4];
        #pragma unroll
        for (int i = 0; i < 8; i++)
            #pragma unroll
            for (int e = 0; e < 4; e++) c[i][e] = 0.f;

        #pragma unroll
        for (int kc2 = 0; kc2 < 8; kc2++) {
            uint32_t qh4[4];
            ldm4(qh4[0], qh4[1], qh4[2], qh4[3], sb + qoff + kc2 * 32);
            #pragma unroll
            for (int np = 0; np < 4; np++) {
                uint32_t kh[4];
                uint32_t ka = st + KHO + koff + (uint32_t)np * (16 * AROWB) + kc2 * 32;
                ldm4(kh[0], kh[1], kh[2], kh[3], ka);
                mma16h(c[2 * np],     qh4, &kh[0]);
                mma16h(c[2 * np + 1], qh4, &kh[2]);
            }
        }

        #pragma unroll
        for (int nt = 0; nt < 8; nt++) {
            int col = k0 + nt * 8 + 2 * q;
            float2 a0 = *(const float2*)(arow0 + col);
            float2 a1 = *(const float2*)(arow1 + col);
            float2 pd = *(const float2*)(padS + col);
            c[nt][0] = fmaf(c[nt][0], sscale, a0.x + pd.x);
            c[nt][1] = fmaf(c[nt][1], sscale, a0.y + pd.y);
            c[nt][2] = fmaf(c[nt][2], sscale, a1.x + pd.x);
            c[nt][3] = fmaf(c[nt][3], sscale, a1.y + pd.y);
        }
        float mx0 = -1e30f, mx1 = -1e30f;
        #pragma unroll
        for (int nt = 0; nt < 8; nt++) {
            mx0 = fmaxf(mx0, fmaxf(c[nt][0], c[nt][1]));
            mx1 = fmaxf(mx1, fmaxf(c[nt][2], c[nt][3]));
        }
        mx0 = fmaxf(mx0, __shfl_xor_sync(0xffffffffu, mx0, 1));
        mx0 = fmaxf(mx0, __shfl_xor_sync(0xffffffffu, mx0, 2));
        mx1 = fmaxf(mx1, __shfl_xor_sync(0xffffffffu, mx1, 1));
        mx1 = fmaxf(mx1, __shfl_xor_sync(0xffffffffu, mx1, 2));
        float mn0 = fmaxf(m0r, mx0), mn1 = fmaxf(m1r, mx1);
        float cr0 = __expf(m0r - mn0), cr1 = __expf(m1r - mn1);
        m0r = mn0; m1r = mn1;
        float s0 = 0.f, s1 = 0.f;
        #pragma unroll
        for (int nt = 0; nt < 8; nt++) {
            c[nt][0] = __expf(c[nt][0] - mn0);
            c[nt][1] = __expf(c[nt][1] - mn0);
            c[nt][2] = __expf(c[nt][2] - mn1);
            c[nt][3] = __expf(c[nt][3] - mn1);
            s0 += c[nt][0] + c[nt][1];
            s1 += c[nt][2] + c[nt][3];
        }
        s0 += __shfl_xor_sync(0xffffffffu, s0, 1);
        s0 += __shfl_xor_sync(0xffffffffu, s0, 2);
        s1 += __shfl_xor_sync(0xffffffffu, s1, 1);
        s1 += __shfl_xor_sync(0xffffffffu, s1, 2);
        l0r = l0r * cr0 + s0;
        l1r = l1r * cr1 + s1;
        #pragma unroll
        for (int i = 0; i < 16; i++) {
            o[i][0] *= cr0; o[i][1] *= cr0;
            o[i][2] *= cr1; o[i][3] *= cr1;
        }

        #pragma unroll
        for (int kc2 = 0; kc2 < 4; kc2++) {
            uint32_t ph[4];
            ph[0] = packh_rn(c[2 * kc2][0],     c[2 * kc2][1]);
            ph[1] = packh_rn(c[2 * kc2][2],     c[2 * kc2][3]);
            ph[2] = packh_rn(c[2 * kc2 + 1][0], c[2 * kc2 + 1][1]);
            ph[3] = packh_rn(c[2 * kc2 + 1][2], c[2 * kc2 + 1][3]);
            uint32_t vrow = st + VHO + voff + (uint32_t)kc2 * (16 * AROWB);
            #pragma unroll
            for (int dg = 0; dg < 8; dg++) {
                uint32_t vh[4];
                ldm4t(vh[0], vh[1], vh[2], vh[3], vrow + dg * 32);
                mma16h(o[2 * dg],     ph, &vh[0]);
                mma16h(o[2 * dg + 1], ph, &vh[2]);
            }
        }

        __syncthreads();
        if (kt + 2 < S_ / 64) { loadKV(kt + 2, kt & 1); cp_commit(); }
        else cp_commit();
    }

    float inv0 = 1.0f / l0r, inv1 = 1.0f / l1r;
    size_t row0 = tokbase + q0 + wid * 16 + g;
    size_t row1 = row0 + 8;
    #pragma unroll
    for (int nt = 0; nt < 16; nt++) {
        int col = h * 128 + nt * 8 + 2 * q;
        *(uint32_t*)&outh[row0 * D_ + col] =
            packh_rn(o[nt][0] * inv0, o[nt][1] * inv0);
        *(uint32_t*)&outh[row1 * D_ + col] =
            packh_rn(o[nt][2] * inv1, o[nt][3] * inv1);
    }
}

// ---------------------------------------------------------------------------
// kernel_launch
// ---------------------------------------------------------------------------
extern "C" void kernel_launch(void* const* d_in, const int* in_sizes, int n_in,
                              void* d_out, int out_size)
{
    const float* x     = (const float*)d_in[0];
    const float* alibi = (const float*)d_in[1];
    const float* pad   = (const float*)d_in[2];
    const float* Wqkv  = (const float*)d_in[3];
    const float* Aqkv  = (const float*)d_in[4];
    const float* Bqkv  = (const float*)d_in[5];
    const float* Wout  = (const float*)d_in[6];
    const float* Aout  = (const float*)d_in[7];
    const float* Bout  = (const float*)d_in[8];
    float* out = (float*)d_out;

    __half *qkvh, *xh, *wqh, *woh, *ah;
    cudaGetSymbolAddress((void**)&qkvh, g_qkvh);
    cudaGetSymbolAddress((void**)&xh,  g_xh);
    cudaGetSymbolAddress((void**)&wqh, g_wqh);
    cudaGetSymbolAddress((void**)&woh, g_woh);
    cudaGetSymbolAddress((void**)&ah,  g_ah);

    cudaFuncSetAttribute(tc_gemm_fp16,
                         cudaFuncAttributeMaxDynamicSharedMemorySize, TCG_SMEM);
    cudaFuncSetAttribute(attn_mma,
                         cudaFuncAttributeMaxDynamicSharedMemorySize, ATTN_SMEM);

    // pre-pass: x -> fp16; weights -> fp16 with LoRA folded in fp32
    convh_kernel<<<(M_TOK * D_ / 4 + 255) / 256, 256>>>(
        (const float4*)x, (uint2*)xh, M_TOK * D_ / 4);
    {
        dim3 gq(D_ / 64, (3 * D_) / 64);     // (32, 96)
        weff_kernel<<<gq, 256>>>(Wqkv, Aqkv, Bqkv, wqh, 3 * D_, D_, LORA_SCALE);
        dim3 go(D_ / 64, D_ / 64);           // (32, 32)
        weff_kernel<<<go, 256>>>(Wout, Aout, Bout, woh, D_, D_, LORA_SCALE);
    }

    // qkv = x @ Weff_qkv^T  -> fp16 (1-pass)
    {
        dim3 grid((3 * D_) / 128, M_TOK / 128);
        tc_gemm_fp16<<<grid, 256, TCG_SMEM>>>(xh, wqh,
                                              nullptr, (uint16_t*)qkvh,
                                              M_TOK, 3 * D_, D_, 1);
    }

    // attention -> fp16 ah
    {
        dim3 grid(S_ / 64, H_, B_);
        attn_mma<<<grid, 128, ATTN_SMEM>>>(qkvh, alibi, pad, (uint16_t*)ah);
    }

    // out = attn @ Weff_out^T  -> fp32 (1-pass)
    {
        dim3 grid(D_ / 128, M_TOK / 128);
        tc_gemm_fp16<<<grid, 256, TCG_SMEM>>>(ah, woh,
                                              out, nullptr,
                                              M_TOK, D_, D_, 0);
    }
}

// round 13
// speedup vs baseline: 2.6437x; 1.0041x over previous
#include <cuda_runtime.h>
#include <cuda_fp16.h>
#include <cstdint>

// Problem constants
#define B_   2
#define S_   2048
#define D_   2048
#define H_   16
#define HD_  128
#define R_   32
#define M_TOK (B_ * S_)              // 4096 tokens
#define LORA_SCALE (1.0f / 32.0f)

// ---------------------------------------------------------------------------
// Scratch (allocation-free rule: __device__ globals)
// ---------------------------------------------------------------------------
static __device__ __align__(16) __half g_qkvh[M_TOK * 3 * D_];
static __device__ __align__(16) __half g_xh[M_TOK * D_];
static __device__ __align__(16) __half g_wqh[3 * D_ * D_];   // Wqkv + LoRA folded
static __device__ __align__(16) __half g_woh[D_ * D_];       // Wout + LoRA folded
static __device__ __align__(16) __half g_ah[M_TOK * D_];

// ---------------------------------------------------------------------------
// helpers
// ---------------------------------------------------------------------------
__device__ __forceinline__ uint32_t smem_u32(const void* p) {
    uint32_t a;
    asm("{ .reg .u64 t; cvta.to.shared.u64 t, %1; cvt.u32.u64 %0, t; }"
        : "=r"(a) : "l"(p));
    return a;
}
__device__ __forceinline__ void cp16(uint32_t dst, const void* src) {
    asm volatile("cp.async.cg.shared.global [%0], [%1], 16;"
                 :: "r"(dst), "l"(src) : "memory");
}
__device__ __forceinline__ void cp_commit() {
    asm volatile("cp.async.commit_group;" ::: "memory");
}
__device__ __forceinline__ void cp_wait1() {
    asm volatile("cp.async.wait_group 1;" ::: "memory");
}
__device__ __forceinline__ void ldm4(uint32_t& r0, uint32_t& r1,
                                     uint32_t& r2, uint32_t& r3, uint32_t addr) {
    asm volatile("ldmatrix.sync.aligned.m8n8.x4.shared.b16 {%0,%1,%2,%3}, [%4];"
                 : "=r"(r0), "=r"(r1), "=r"(r2), "=r"(r3) : "r"(addr));
}
__device__ __forceinline__ void ldm4t(uint32_t& r0, uint32_t& r1,
                                      uint32_t& r2, uint32_t& r3, uint32_t addr) {
    asm volatile("ldmatrix.sync.aligned.m8n8.x4.trans.shared.b16 {%0,%1,%2,%3}, [%4];"
                 : "=r"(r0), "=r"(r1), "=r"(r2), "=r"(r3) : "r"(addr));
}
__device__ __forceinline__ void mma16h(float* c, const uint32_t* a, const uint32_t* b) {
    asm volatile(
        "mma.sync.aligned.m16n8k16.row.col.f32.f16.f16.f32 "
        "{%0,%1,%2,%3}, {%4,%5,%6,%7}, {%8,%9}, {%0,%1,%2,%3};"
        : "+f"(c[0]), "+f"(c[1]), "+f"(c[2]), "+f"(c[3])
        : "r"(a[0]), "r"(a[1]), "r"(a[2]), "r"(a[3]), "r"(b[0]), "r"(b[1]));
}
__device__ __forceinline__ uint32_t packh_rn(float x, float y) {
    __half2 t = __floats2half2_rn(x, y);
    return *(uint32_t*)&t;
}

// ---------------------------------------------------------------------------
// Pre-pass: fp32 -> fp16 RN (x only)
// ---------------------------------------------------------------------------
__global__ void __launch_bounds__(256) convh_kernel(
    const float4* __restrict__ src, uint2* __restrict__ dst, int n4)
{
    int i = blockIdx.x * 256 + threadIdx.x;
    if (i >= n4) return;
    float4 v = src[i];
    dst[i] = make_uint2(packh_rn(v.x, v.y), packh_rn(v.z, v.w));
}

// ---------------------------------------------------------------------------
// Pre-pass: fold LoRA into weight, fp32 -> fp16:
//   Weff[n][k] = W[n][k] + scale * sum_r A[k][r] * Bm[r][n]
// ---------------------------------------------------------------------------
__global__ void __launch_bounds__(256) weff_kernel(
    const float* __restrict__ W, const float* __restrict__ A,
    const float* __restrict__ Bm, __half* __restrict__ outW,
    int N, int K, float scale)
{
    __shared__ float As[64][33];   // [k][r]
    __shared__ float Bs[64][33];   // [n][r]

    const int tid = threadIdx.x;
    const int k0 = blockIdx.x * 64;
    const int n0 = blockIdx.y * 64;

    #pragma unroll
    for (int j = 0; j < 8; j++) {
        int idx = tid + j * 256;
        int kk = idx >> 5, r = idx & 31;
        As[kk][r] = A[(size_t)(k0 + kk) * 32 + r];
    }
    #pragma unroll
    for (int j = 0; j < 8; j++) {
        int idx = tid + j * 256;
        int r = idx >> 6, nn = idx & 63;
        Bs[nn][r] = Bm[(size_t)r * N + n0 + nn];
    }
    __syncthreads();

    const int tk = tid & 15;
    const int tn = tid >> 4;

    float acc[4][4];
    #pragma unroll
    for (int i = 0; i < 4; i++)
        #pragma unroll
        for (int j = 0; j < 4; j++) acc[i][j] = 0.f;

    #pragma unroll
    for (int r = 0; r < 32; r++) {
        float a[4], b[4];
        #pragma unroll
        for (int j = 0; j < 4; j++) a[j] = As[tk * 4 + j][r];
        #pragma unroll
        for (int i = 0; i < 4; i++) b[i] = Bs[tn * 4 + i][r];
        #pragma unroll
        for (int i = 0; i < 4; i++)
            #pragma unroll
            for (int j = 0; j < 4; j++)
                acc[i][j] = fmaf(b[i], a[j], acc[i][j]);
    }

    #pragma unroll
    for (int i = 0; i < 4; i++) {
        int n = n0 + tn * 4 + i;
        float4 w = *(const float4*)&W[(size_t)n * K + k0 + tk * 4];
        uint2 o;
        o.x = packh_rn(fmaf(scale, acc[i][0], w.x), fmaf(scale, acc[i][1], w.y));
        o.y = packh_rn(fmaf(scale, acc[i][2], w.z), fmaf(scale, acc[i][3], w.w));
        *(uint2*)&outW[(size_t)n * K + k0 + tk * 4] = o;
    }
}

// ---------------------------------------------------------------------------
// fp16 GEMM (1-pass, LoRA pre-folded into B):  C = Ah @ Bh^T
// (unchanged from round 12 — passing)
// ---------------------------------------------------------------------------
#define GROW 80
#define OFF_B 10240
#define STAGE_B 20480
#define TCG_SMEM (3 * STAGE_B)      // 61440 bytes

__global__ void __launch_bounds__(256, 2) tc_gemm_fp16(
    const __half* __restrict__ Ah, const __half* __restrict__ Bh,
    float* __restrict__ Cf, uint16_t* __restrict__ Chi,
    int M, int N, int K, int outMode)
{
    extern __shared__ __align__(128) char smem[];
    const uint32_t sbase = smem_u32(smem);

    const int tid  = threadIdx.x;
    const int wid  = tid >> 5;
    const int lane = tid & 31;
    const int g    = lane >> 2;
    const int q    = lane & 3;
    const int warpM = (wid & 1) * 64;
    const int warpN = (wid >> 1) * 32;

    const int n0 = blockIdx.x * 128;
    const int m0 = blockIdx.y * 128;

    const int kc = K >> 5;

    float acc[4][4][4];
    #pragma unroll
    for (int i = 0; i < 4; i++)
        #pragma unroll
        for (int j = 0; j < 4; j++)
            #pragma unroll
            for (int e = 0; e < 4; e++) acc[i][j][e] = 0.f;

    auto issue = [&](int c, int s) {
        const uint32_t st = sbase + (uint32_t)s * STAGE_B;
        #pragma unroll
        for (int j = 0; j < 2; j++) {
            int idx = tid + j * 256;
            int row = idx >> 2;
            int seg = idx & 3;
            uint32_t doff = (uint32_t)row * GROW + (uint32_t)seg * 16u;
            cp16(st + doff,         Ah + (size_t)(m0 + row) * K + c * 32 + seg * 8);
            cp16(st + OFF_B + doff, Bh + (size_t)(n0 + row) * K + c * 32 + seg * 8);
        }
        cp_commit();
    };

    issue(0, 0);
    issue(1, 1);

    const int mi = lane >> 3;
    const int l7 = lane & 7;

    for (int i = 0; i < kc; i++) {
        cp_wait1();
        __syncthreads();
        if (i + 2 < kc) issue(i + 2, (i + 2) % 3);
        else cp_commit();

        const uint32_t st = sbase + (uint32_t)(i % 3) * STAGE_B;

        #pragma unroll
        for (int kh = 0; kh < 2; kh++) {
            uint32_t bh[4][2];
            #pragma unroll
            for (int bg = 0; bg < 2; bg++) {
                uint32_t rowB = warpN + bg * 16 + ((mi >> 1) << 3) + l7;
                uint32_t addr = st + OFF_B + rowB * GROW
                              + (uint32_t)(mi & 1) * 16u + kh * 32u;
                ldm4(bh[2 * bg][0], bh[2 * bg][1],
                     bh[2 * bg + 1][0], bh[2 * bg + 1][1], addr);
            }
            #pragma unroll
            for (int mt = 0; mt < 4; mt++) {
                uint32_t rowA = warpM + mt * 16 + ((mi & 1) << 3) + l7;
                uint32_t addrA = st + rowA * GROW
                               + (uint32_t)(mi >> 1) * 16u + kh * 32u;
                uint32_t ah[4];
                ldm4(ah[0], ah[1], ah[2], ah[3], addrA);
                #pragma unroll
                for (int nt = 0; nt < 4; nt++)
                    mma16h(acc[mt][nt], ah, bh[nt]);
            }
        }
    }

    #pragma unroll
    for (int mt = 0; mt < 4; mt++) {
        int row = m0 + warpM + mt * 16 + g;
        #pragma unroll
        for (int nt = 0; nt < 4; nt++) {
            int col = n0 + warpN + nt * 8 + 2 * q;
            size_t i0 = (size_t)row * N + col;
            size_t i1 = (size_t)(row + 8) * N + col;
            if (outMode == 0) {
                *(float2*)&Cf[i0] = make_float2(acc[mt][nt][0], acc[mt][nt][1]);
                *(float2*)&Cf[i1] = make_float2(acc[mt][nt][2], acc[mt][nt][3]);
            } else {
                *(uint32_t*)&Chi[i0] = packh_rn(acc[mt][nt][0], acc[mt][nt][1]);
                *(uint32_t*)&Chi[i1] = packh_rn(acc[mt][nt][2], acc[mt][nt][3]);
            }
        }
    }
}

// ---------------------------------------------------------------------------
// Tensor-core flash attention, fp16 1-pass, occupancy-2, register-pipelined:
//   - Q fragments resident in registers (loaded once)
//   - K fragments double-buffered across kc2 steps
//   - V fragments double-buffered across dg steps
// mma order identical to round 12 -> numerics unchanged.
// CTA: 128 threads (4 warps), 64 q-rows.  Grid: (S/64, H, B).
// ---------------------------------------------------------------------------
#define AROWB 272
#define PAD_OFF 0
#define PAD_B   (S_ * 4)                       // 8192
#define QH_OFF  PAD_B
#define KV_OFF  (QH_OFF + 64 * AROWB)
#define KHO 0
#define VHO (64 * AROWB)
#define ST_B (2 * 64 * AROWB)
#define ATTN_SMEM (KV_OFF + 2 * ST_B)          // 95232

__global__ void __launch_bounds__(128, 2) attn_mma(
    const __half* __restrict__ qkvh,
    const float* __restrict__ alibi, const float* __restrict__ pad,
    uint16_t* __restrict__ outh)
{
    extern __shared__ __align__(128) char smem[];
    const uint32_t sb = smem_u32(smem);
    const int tid = threadIdx.x, wid = tid >> 5, lane = tid & 31;
    const int g = lane >> 2, q = lane & 3, l7 = lane & 7;
    const int q0 = blockIdx.x * 64, h = blockIdx.y, b = blockIdx.z;

    const size_t tokbase = (size_t)(b * S_);

    {
        const float* prow = pad + (size_t)b * S_;
        #pragma unroll
        for (int j = 0; j < 4; j++) {
            int idx = tid + j * 128;
            cp16(sb + PAD_OFF + idx * 16, prow + idx * 4);
        }
        const __half* bH = qkvh + (tokbase + q0) * 6144 + h * 128;
        #pragma unroll
        for (int j = 0; j < 8; j++) {
            int idx = tid + j * 128;
            int row = idx >> 4, seg = idx & 15;
            cp16(sb + QH_OFF + (uint32_t)row * AROWB + seg * 16,
                 bH + (size_t)row * 6144 + seg * 8);
        }
    }
    auto loadKV = [&](int kt, int st) {
        const uint32_t base = sb + KV_OFF + (uint32_t)st * ST_B;
        const __half* kH = qkvh + (tokbase + kt * 64) * 6144 + D_ + h * 128;
        const __half* vH = kH + D_;
        #pragma unroll
        for (int j = 0; j < 8; j++) {
            int idx = tid + j * 128;
            int row = idx >> 4, seg = idx & 15;
            uint32_t off = (uint32_t)row * AROWB + seg * 16;
            size_t go = (size_t)row * 6144 + seg * 8;
            cp16(base + KHO + off, kH + go);
            cp16(base + VHO + off, vH + go);
        }
    };
    cp_commit();
    loadKV(0, 0); cp_commit();
    loadKV(1, 1); cp_commit();

    float o[16][4];
    #pragma unroll
    for (int i = 0; i < 16; i++)
        #pragma unroll
        for (int e = 0; e < 4; e++) o[i][e] = 0.f;
    float m0r = -1e30f, m1r = -1e30f, l0r = 0.f, l1r = 0.f;

    const float sscale = 0.08838834764831845f;   // 1/sqrt(128)

    const uint32_t qoff = (uint32_t)(wid * 16 + ((lane >> 3) & 1) * 8 + l7) * AROWB
                        + ((lane >> 4) & 1) * 16 + QH_OFF;
    const uint32_t koff = (uint32_t)(((lane >> 4) & 1) * 8 + l7) * AROWB
                        + ((lane >> 3) & 1) * 16;
    const uint32_t voff = (uint32_t)(((lane >> 3) & 1) * 8 + l7) * AROWB
                        + ((lane >> 4) & 1) * 16;

    const float* arow0 = alibi + ((size_t)h * S_ + (q0 + wid * 16 + g)) * S_;
    const float* arow1 = arow0 + 8 * S_;
    const float* padS  = (const float*)smem;

    // ---- Q fragments resident (pad+Q group complete after this wait) ----
    cp_wait1();
    __syncthreads();
    uint32_t qf[8][4];
    #pragma unroll
    for (int kc2 = 0; kc2 < 8; kc2++)
        ldm4(qf[kc2][0], qf[kc2][1], qf[kc2][2], qf[kc2][3],
             sb + qoff + kc2 * 32);

    for (int kt = 0; kt < S_ / 64; kt++) {
        cp_wait1();
        __syncthreads();
        const uint32_t st = sb + KV_OFF + (uint32_t)(kt & 1) * ST_B;
        const int k0 = kt * 64;

        // ---- QK^T (fp16, 1-pass; K double-buffered) ----
        float c[8][4];
        #pragma unroll
        for (int i = 0; i < 8; i++)
            #pragma unroll
            for (int e = 0; e < 4; e++) c[i][e] = 0.f;

        uint32_t kf[2][4][4];
        #pragma unroll
        for (int np = 0; np < 4; np++)
            ldm4(kf[0][np][0], kf[0][np][1], kf[0][np][2], kf[0][np][3],
                 st + KHO + koff + (uint32_t)np * (16 * AROWB));

        #pragma unroll
        for (int kc2 = 0; kc2 < 8; kc2++) {
            const int cur = kc2 & 1, nxt = cur ^ 1;
            if (kc2 < 7) {
                #pragma unroll
                for (int np = 0; np < 4; np++)
                    ldm4(kf[nxt][np][0], kf[nxt][np][1],
                         kf[nxt][np][2], kf[nxt][np][3],
                         st + KHO + koff + (uint32_t)np * (16 * AROWB)
                            + (kc2 + 1) * 32);
            }
            #pragma unroll
            for (int np = 0; np < 4; np++) {
                mma16h(c[2 * np],     qf[kc2], &kf[cur][np][0]);
                mma16h(c[2 * np + 1], qf[kc2], &kf[cur][np][2]);
            }
        }

        // ---- bias + online softmax ----
        #pragma unroll
        for (int nt = 0; nt < 8; nt++) {
            int col = k0 + nt * 8 + 2 * q;
            float2 a0 = *(const float2*)(arow0 + col);
            float2 a1 = *(const float2*)(arow1 + col);
            float2 pd = *(const float2*)(padS + col);
            c[nt][0] = fmaf(c[nt][0], sscale, a0.x + pd.x);
            c[nt][1] = fmaf(c[nt][1], sscale, a0.y + pd.y);
            c[nt][2] = fmaf(c[nt][2], sscale, a1.x + pd.x);
            c[nt][3] = fmaf(c[nt][3], sscale, a1.y + pd.y);
        }
        float mx0 = -1e30f, mx1 = -1e30f;
        #pragma unroll
        for (int nt = 0; nt < 8; nt++) {
            mx0 = fmaxf(mx0, fmaxf(c[nt][0], c[nt][1]));
            mx1 = fmaxf(mx1, fmaxf(c[nt][2], c[nt][3]));
        }
        mx0 = fmaxf(mx0, __shfl_xor_sync(0xffffffffu, mx0, 1));
        mx0 = fmaxf(mx0, __shfl_xor_sync(0xffffffffu, mx0, 2));
        mx1 = fmaxf(mx1, __shfl_xor_sync(0xffffffffu, mx1, 1));
        mx1 = fmaxf(mx1, __shfl_xor_sync(0xffffffffu, mx1, 2));
        float mn0 = fmaxf(m0r, mx0), mn1 = fmaxf(m1r, mx1);
        float cr0 = __expf(m0r - mn0), cr1 = __expf(m1r - mn1);
        m0r = mn0; m1r = mn1;
        float s0 = 0.f, s1 = 0.f;
        #pragma unroll
        for (int nt = 0; nt < 8; nt++) {
            c[nt][0] = __expf(c[nt][0] - mn0);
            c[nt][1] = __expf(c[nt][1] - mn0);
            c[nt][2] = __expf(c[nt][2] - mn1);
            c[nt][3] = __expf(c[nt][3] - mn1);
            s0 += c[nt][0] + c[nt][1];
            s1 += c[nt][2] + c[nt][3];
        }
        s0 += __shfl_xor_sync(0xffffffffu, s0, 1);
        s0 += __shfl_xor_sync(0xffffffffu, s0, 2);
        s1 += __shfl_xor_sync(0xffffffffu, s1, 1);
        s1 += __shfl_xor_sync(0xffffffffu, s1, 2);
        l0r = l0r * cr0 + s0;
        l1r = l1r * cr1 + s1;
        #pragma unroll
        for (int i = 0; i < 16; i++) {
            o[i][0] *= cr0; o[i][1] *= cr0;
            o[i][2] *= cr1; o[i][3] *= cr1;
        }

        // ---- PV (fp16, 1-pass; V double-buffered) ----
        #pragma unroll
        for (int kc2 = 0; kc2 < 4; kc2++) {
            uint32_t ph[4];
            ph[0] = packh_rn(c[2 * kc2][0],     c[2 * kc2][1]);
            ph[1] = packh_rn(c[2 * kc2][2],     c[2 * kc2][3]);
            ph[2] = packh_rn(c[2 * kc2 + 1][0], c[2 * kc2 + 1][1]);
            ph[3] = packh_rn(c[2 * kc2 + 1][2], c[2 * kc2 + 1][3]);
            uint32_t vrow = st + VHO + voff + (uint32_t)kc2 * (16 * AROWB);
            uint32_t vf[2][4];
            ldm4t(vf[0][0], vf[0][1], vf[0][2], vf[0][3], vrow);
            #pragma unroll
            for (int dg = 0; dg < 8; dg++) {
                const int cur = dg & 1, nxt = cur ^ 1;
                if (dg < 7)
                    ldm4t(vf[nxt][0], vf[nxt][1], vf[nxt][2], vf[nxt][3],
                          vrow + (dg + 1) * 32);
                mma16h(o[2 * dg],     ph, &vf[cur][0]);
                mma16h(o[2 * dg + 1], ph, &vf[cur][2]);
            }
        }

        __syncthreads();
        if (kt + 2 < S_ / 64) { loadKV(kt + 2, kt & 1); cp_commit(); }
        else cp_commit();
    }

    float inv0 = 1.0f / l0r, inv1 = 1.0f / l1r;
    size_t row0 = tokbase + q0 + wid * 16 + g;
    size_t row1 = row0 + 8;
    #pragma unroll
    for (int nt = 0; nt < 16; nt++) {
        int col = h * 128 + nt * 8 + 2 * q;
        *(uint32_t*)&outh[row0 * D_ + col] =
            packh_rn(o[nt][0] * inv0, o[nt][1] * inv0);
        *(uint32_t*)&outh[row1 * D_ + col] =
            packh_rn(o[nt][2] * inv1, o[nt][3] * inv1);
    }
}

// ---------------------------------------------------------------------------
// kernel_launch
// ---------------------------------------------------------------------------
extern "C" void kernel_launch(void* const* d_in, const int* in_sizes, int n_in,
                              void* d_out, int out_size)
{
    const float* x     = (const float*)d_in[0];
    const float* alibi = (const float*)d_in[1];
    const float* pad   = (const float*)d_in[2];
    const float* Wqkv  = (const float*)d_in[3];
    const float* Aqkv  = (const float*)d_in[4];
    const float* Bqkv  = (const float*)d_in[5];
    const float* Wout  = (const float*)d_in[6];
    const float* Aout  = (const float*)d_in[7];
    const float* Bout  = (const float*)d_in[8];
    float* out = (float*)d_out;

    __half *qkvh, *xh, *wqh, *woh, *ah;
    cudaGetSymbolAddress((void**)&qkvh, g_qkvh);
    cudaGetSymbolAddress((void**)&xh,  g_xh);
    cudaGetSymbolAddress((void**)&wqh, g_wqh);
    cudaGetSymbolAddress((void**)&woh, g_woh);
    cudaGetSymbolAddress((void**)&ah,  g_ah);

    cudaFuncSetAttribute(tc_gemm_fp16,
                         cudaFuncAttributeMaxDynamicSharedMemorySize, TCG_SMEM);
    cudaFuncSetAttribute(attn_mma,
                         cudaFuncAttributeMaxDynamicSharedMemorySize, ATTN_SMEM);

    // pre-pass: x -> fp16; weights -> fp16 with LoRA folded in fp32
    convh_kernel<<<(M_TOK * D_ / 4 + 255) / 256, 256>>>(
        (const float4*)x, (uint2*)xh, M_TOK * D_ / 4);
    {
        dim3 gq(D_ / 64, (3 * D_) / 64);
        weff_kernel<<<gq, 256>>>(Wqkv, Aqkv, Bqkv, wqh, 3 * D_, D_, LORA_SCALE);
        dim3 go(D_ / 64, D_ / 64);
        weff_kernel<<<go, 256>>>(Wout, Aout, Bout, woh, D_, D_, LORA_SCALE);
    }

    // qkv = x @ Weff_qkv^T  -> fp16 (1-pass)
    {
        dim3 grid((3 * D_) / 128, M_TOK / 128);
        tc_gemm_fp16<<<grid, 256, TCG_SMEM>>>(xh, wqh,
                                              nullptr, (uint16_t*)qkvh,
                                              M_TOK, 3 * D_, D_, 1);
    }

    // attention -> fp16 ah
    {
        dim3 grid(S_ / 64, H_, B_);
        attn_mma<<<grid, 128, ATTN_SMEM>>>(qkvh, alibi, pad, (uint16_t*)ah);
    }

    // out = attn @ Weff_out^T  -> fp32 (1-pass)
    {
        dim3 grid(D_ / 128, M_TOK / 128);
        tc_gemm_fp16<<<grid, 256, TCG_SMEM>>>(ah, woh,
                                              out, nullptr,
                                              M_TOK, D_, D_, 0);
    }
}